// round 9
// baseline (speedup 1.0000x reference)
#include <cuda_runtime.h>

#define BATCH   2097152
#define DIMC    32
#define INDIM   10
#define LAYERS  4
#define MB      17
#define EPSV    1e-5f

#define GRID_MAIN 2048
#define TPB       256
#define RPT       4                       // stem/head: 1 row/thread, 4 iters
#define STRIDE    (GRID_MAIN*TPB)
#define SWEEPS    2                       // passA/B: 2 rows/thread, 2 sweeps
#define DYN_BYTES ((16384 + 8960) * 4)    // 64KB data tile + 35KB stats tile

typedef unsigned long long u64;

// ---------------- scratch (__device__ globals: allocation-free) ----------------
__device__ __align__(16) float g_h[(size_t)DIMC * BATCH];   // planar [c][row]
__device__ __align__(16) float g_r[(size_t)DIMC * BATCH];   // planar [c][row]
__device__ __align__(16) float g_A[LAYERS * DIMC * DIMC];   // fused Fourier A+I, [l][in][out]
__device__ float g_partials[GRID_MAIN * 64];                // per-CTA [sum[32], sumsq[32]]
__device__ float g_scale[DIMC];                             // BN affine: y = x*scale + shift
__device__ float g_shift[DIMC];

// ---------------- packed f32x2 helpers ----------------
__device__ __forceinline__ u64 pk2(float a, float b){
    u64 r; asm("mov.b64 %0,{%1,%2};" : "=l"(r) : "f"(a), "f"(b)); return r;
}
__device__ __forceinline__ void up2(u64 v, float &a, float &b){
    asm("mov.b64 {%0,%1},%2;" : "=f"(a), "=f"(b) : "l"(v));
}
__device__ __forceinline__ u64 fma2(u64 a, u64 b, u64 c){
    u64 d; asm("fma.rn.f32x2 %0,%1,%2,%3;" : "=l"(d) : "l"(a), "l"(b), "l"(c)); return d;
}
__device__ __forceinline__ float siluf(float x){
    return x * __fdividef(1.0f, 1.0f + __expf(-x));
}

// ------- Fourier operator precompute: A' = A + I. One thread per element. -------
__global__ void k_precompute_A(const float* __restrict__ wr, const float* __restrict__ wi){
    __shared__ double ct[32], st[32];
    int t = threadIdx.x;
    if(t < 32){
        double ang = 6.283185307179586476925286766559 * (double)t / 32.0;
        ct[t] = cos(ang); st[t] = sin(ang);
    }
    __syncthreads();
    int g = blockIdx.x * blockDim.x + t;               // 0..4095
    if(g >= LAYERS*DIMC*DIMC) return;
    int l = g >> 10, j = (g >> 5) & 31, d = g & 31;
    const float* WR = wr + l*MB*MB;
    const float* WI = wi + l*MB*MB;
    double v = 0.0;
    for(int k = 0; k < MB; k++){
        double re = 0.0, im = 0.0;
        for(int m = 0; m < MB; m++){
            double c = ct[(m*j)&31], s = st[(m*j)&31];   // rfft of e_j: c - i*s
            double a = (double)WR[m*MB + k], b = (double)WI[m*MB + k];
            re += c*a + s*b;
            im += c*b - s*a;
        }
        double al, be;
        if(k == 0)      { al = 1.0; be = 0.0; }
        else if(k == 16){ al = (d & 1) ? -1.0 : 1.0; be = 0.0; }
        else            { al = 2.0*ct[(k*d)&31]; be = 2.0*st[(k*d)&31]; }
        v += al*re - be*im;
    }
    v *= (1.0/32.0);
    if(j == d) v += 1.0;                                  // fold identity skip
    g_A[(l*DIMC + j)*DIMC + d] = (float)v;
}

// ---- stats via shared tile: [256 rows][35] floats, conflict-free both directions ----
#define STATS_PHASE(ACC) do{                                                   \
    __syncthreads();                                                           \
    { float* trow = tile + threadIdx.x*35;                                     \
      _Pragma("unroll")                                                        \
      for(int q = 0; q < 16; q++){                                             \
          float _a,_b; up2((ACC)[q],_a,_b);                                    \
          trow[2*q] = _a; trow[2*q+1] = _b;                                    \
      } }                                                                      \
    __syncthreads();                                                           \
    _Pragma("unroll")                                                          \
    for(int j = 0; j < 32; j++){                                               \
        float v = tile[(mrow*32 + j)*35 + ch];                                 \
        ssum += v; ssq += v*v;                                                 \
    }                                                                          \
}while(0)

#define STATS_TAIL() do{                                                       \
    __syncthreads();                                                           \
    tile[mrow*64 + ch]      = ssum;                                            \
    tile[mrow*64 + 32 + ch] = ssq;                                             \
    __syncthreads();                                                           \
    if(threadIdx.x < 64){                                                      \
        float v = 0.f;                                                         \
        _Pragma("unroll")                                                      \
        for(int m = 0; m < 8; m++) v += tile[m*64 + threadIdx.x];              \
        g_partials[blockIdx.x*64 + threadIdx.x] = v;                           \
    }                                                                          \
}while(0)

// bulk stage: 512 rows x 32 ch of a planar [c][row] array into smem (planar [c][512])
#define STAGE_TILE(DST, SRC, ROWBASE) do{                                      \
    float4* _d4 = (float4*)(DST);                                              \
    _Pragma("unroll")                                                          \
    for(int _i = 0; _i < 16; _i++){                                            \
        int _idx = threadIdx.x + _i*256;                                       \
        int _c = _idx >> 7, _j = _idx & 127;                                   \
        _d4[_idx] = ((const float4*)((SRC) + (size_t)_c*BATCH + (ROWBASE)))[_j];\
    }                                                                          \
}while(0)

// one k-step of the 2-row GEMV: acc{A,B}[16] += sp{A,B} * w[k][:]
#define GEMV_STEP(WSH, K, SPA, SPB) do{                                        \
    const ulonglong2* _w2 = (const ulonglong2*)((WSH) + (K)*16);               \
    _Pragma("unroll")                                                          \
    for(int i = 0; i < 8; i++){                                                \
        ulonglong2 ww = _w2[i];                                                \
        accA[2*i]   = fma2((SPA), ww.x, accA[2*i]);                            \
        accB[2*i]   = fma2((SPB), ww.x, accB[2*i]);                            \
        accA[2*i+1] = fma2((SPA), ww.y, accA[2*i+1]);                          \
        accB[2*i+1] = fma2((SPB), ww.y, accB[2*i+1]);                          \
    }                                                                          \
}while(0)

// ---------------- stem: h = x@stem_w + b; stats(h)  (round-8 verbatim) ----------------
__global__ __launch_bounds__(TPB) void k_stem(const float* __restrict__ x,
                                              const float* __restrict__ sw,
                                              const float* __restrict__ sb){
    __shared__ __align__(16) u64 wsh[INDIM*16];
    __shared__ u64 bsh[16];
    __shared__ float tile[8960];
    if(threadIdx.x < INDIM*16){
        int r = threadIdx.x >> 4, q = threadIdx.x & 15;
        wsh[threadIdx.x] = pk2(sw[r*DIMC + 2*q], sw[r*DIMC + 2*q + 1]);
    }
    if(threadIdx.x < 16) bsh[threadIdx.x] = pk2(sb[2*threadIdx.x], sb[2*threadIdx.x+1]);
    int ch = threadIdx.x & 31, mrow = threadIdx.x >> 5;
    float ssum = 0.f, ssq = 0.f;
    __syncthreads();
#pragma unroll 1
    for(int it = 0; it < RPT; ++it){
        int rowbase = blockIdx.x*TPB + it*STRIDE;
        int row = rowbase + threadIdx.x;
        __syncthreads();
        for(int k = threadIdx.x; k < TPB*INDIM; k += TPB)
            tile[k] = x[(size_t)rowbase*INDIM + k];
        __syncthreads();
        float xv[INDIM];
#pragma unroll
        for(int i = 0; i < INDIM; i++) xv[i] = tile[threadIdx.x*INDIM + i];
        __syncthreads();
        u64 acc[16];
#pragma unroll
        for(int q = 0; q < 16; q++) acc[q] = bsh[q];
#pragma unroll
        for(int i = 0; i < INDIM; i++){
            u64 xp = pk2(xv[i], xv[i]);
            const ulonglong2* w2 = (const ulonglong2*)(wsh + i*16);
#pragma unroll
            for(int q = 0; q < 8; q++){
                ulonglong2 ww = w2[q];
                acc[2*q]   = fma2(xp, ww.x, acc[2*q]);
                acc[2*q+1] = fma2(xp, ww.y, acc[2*q+1]);
            }
        }
        float* trow = tile + threadIdx.x*35;
#pragma unroll
        for(int q = 0; q < 16; q++){
            float a, b; up2(acc[q], a, b);
            g_h[(size_t)(2*q)*BATCH + row]   = a;
            g_h[(size_t)(2*q+1)*BATCH + row] = b;
            trow[2*q] = a; trow[2*q+1] = b;
        }
        __syncthreads();
#pragma unroll
        for(int j = 0; j < 32; j++){
            float v = tile[(mrow*32 + j)*35 + ch];
            ssum += v; ssq += v*v;
        }
    }
    STATS_TAIL();
}

// ---------------- finalize: partials -> BN scale/shift (round-8 verbatim) ----------------
__global__ void k_fin(const float* __restrict__ gamma, const float* __restrict__ beta, int layer){
    __shared__ float red[1024];
    __shared__ float tot[64];
    int t = threadIdx.x;
    int col = t & 63, part = t >> 6;
    const float* p = g_partials + (size_t)part*128*64 + col;
    float v = 0.f;
#pragma unroll 8
    for(int i = 0; i < 128; i++) v += p[(size_t)i*64];
    red[part*64 + col] = v;
    __syncthreads();
    if(t < 64){
        float s = 0.f;
#pragma unroll
        for(int q = 0; q < 16; q++) s += red[q*64 + t];
        tot[t] = s;
    }
    __syncthreads();
    if(t < DIMC){
        float mean = tot[t]      * (1.0f/(float)BATCH);
        float ex2  = tot[32 + t] * (1.0f/(float)BATCH);
        float var  = fmaxf(ex2 - mean*mean, 0.0f);
        float sc   = gamma[layer*DIMC + t] * rsqrtf(var + EPSV);
        g_scale[t] = sc;
        g_shift[t] = beta[layer*DIMC + t] - mean*sc;
    }
}

// ------- pass A: r = silu(bn1(h))@lin1 + b1; stats(r). smem-staged input tile -------
__global__ __launch_bounds__(TPB, 2) void k_passA(const float* __restrict__ w1,
                                                  const float* __restrict__ b1, int layer){
    extern __shared__ __align__(16) float dyn[];
    float* hs   = dyn;            // 16384 floats: staged h tile, planar [c][512]
    float* tile = dyn + 16384;    // 8960 floats: stats tile
    __shared__ __align__(16) u64 wsh[512];
    __shared__ u64 bsh[16];
    __shared__ float2 bn[DIMC];
    {
        const u64* src = (const u64*)(w1 + layer*DIMC*DIMC);
        for(int i = threadIdx.x; i < 512; i += TPB) wsh[i] = src[i];
    }
    if(threadIdx.x < DIMC) bn[threadIdx.x] = make_float2(g_scale[threadIdx.x], g_shift[threadIdx.x]);
    if(threadIdx.x < 16){
        const float* bb = b1 + layer*DIMC;
        bsh[threadIdx.x] = pk2(bb[2*threadIdx.x], bb[2*threadIdx.x+1]);
    }
    int ch = threadIdx.x & 31, mrow = threadIdx.x >> 5;
    float ssum = 0.f, ssq = 0.f;
    __syncthreads();
#pragma unroll 1
    for(int s = 0; s < SWEEPS; ++s){
        int rowbase = blockIdx.x*1024 + s*512;
        int row0 = rowbase + 2*threadIdx.x;
        STAGE_TILE(hs, g_h, rowbase);          // bulk, high-MLP load phase
        __syncthreads();
        u64 accA[16], accB[16];
#pragma unroll
        for(int q = 0; q < 16; q++){ accA[q] = bsh[q]; accB[q] = bsh[q]; }
#pragma unroll
        for(int k = 0; k < DIMC; k++){
            float2 hh = *(const float2*)(hs + (k << 9) + 2*threadIdx.x);
            float2 p = bn[k];
            float sA = siluf(fmaf(hh.x, p.x, p.y));
            float sB = siluf(fmaf(hh.y, p.x, p.y));
            u64 spA = pk2(sA, sA), spB = pk2(sB, sB);
            GEMV_STEP(wsh, k, spA, spB);
        }
        __syncthreads();                       // done reading hs before next sweep reuse
        STATS_PHASE(accA);
        STATS_PHASE(accB);
#pragma unroll
        for(int q = 0; q < 16; q++){
            float a0,a1,b0,b1; up2(accA[q],a0,a1); up2(accB[q],b0,b1);
            *(float2*)(g_r + (size_t)(2*q)*BATCH + row0)   = make_float2(a0, b0);
            *(float2*)(g_r + (size_t)(2*q+1)*BATCH + row0) = make_float2(a1, b1);
        }
    }
    STATS_TAIL();
}

// ------- pass B: h' = silu( h@(A+I) + silu(bn2(r))@lin2 + b2 ); stats(h') -------
// single staged buffer reused: stage r -> GEMV1 -> stage h -> GEMV2
__global__ __launch_bounds__(TPB, 2) void k_passB(const float* __restrict__ w2,
                                                  const float* __restrict__ b2, int layer){
    extern __shared__ __align__(16) float dyn[];
    float* buf  = dyn;            // 16384 floats: staged tile (r, then h)
    float* tile = dyn + 16384;    // 8960 floats: stats tile
    __shared__ __align__(16) u64 wa[512];   // A+I
    __shared__ __align__(16) u64 wl[512];   // lin2
    __shared__ u64 bsh[16];
    __shared__ float2 bn[DIMC];
    {
        const u64* srcA = (const u64*)(g_A + layer*DIMC*DIMC);
        const u64* srcL = (const u64*)(w2  + layer*DIMC*DIMC);
        for(int i = threadIdx.x; i < 512; i += TPB){ wa[i] = srcA[i]; wl[i] = srcL[i]; }
    }
    if(threadIdx.x < DIMC) bn[threadIdx.x] = make_float2(g_scale[threadIdx.x], g_shift[threadIdx.x]);
    if(threadIdx.x < 16){
        const float* bb = b2 + layer*DIMC;
        bsh[threadIdx.x] = pk2(bb[2*threadIdx.x], bb[2*threadIdx.x+1]);
    }
    int ch = threadIdx.x & 31, mrow = threadIdx.x >> 5;
    float ssum = 0.f, ssq = 0.f;
    __syncthreads();
#pragma unroll 1
    for(int s = 0; s < SWEEPS; ++s){
        int rowbase = blockIdx.x*1024 + s*512;
        int row0 = rowbase + 2*threadIdx.x;
        u64 accA[16], accB[16];
#pragma unroll
        for(int q = 0; q < 16; q++){ accA[q] = bsh[q]; accB[q] = bsh[q]; }
        // phase 1: stage r, then silu(bn2(r)) @ lin2 + b2
        STAGE_TILE(buf, g_r, rowbase);
        __syncthreads();
#pragma unroll
        for(int k = 0; k < DIMC; k++){
            float2 rr = *(const float2*)(buf + (k << 9) + 2*threadIdx.x);
            float2 p = bn[k];
            float sA = siluf(fmaf(rr.x, p.x, p.y));
            float sB = siluf(fmaf(rr.y, p.x, p.y));
            u64 spA = pk2(sA, sA), spB = pk2(sB, sB);
            GEMV_STEP(wl, k, spA, spB);
        }
        __syncthreads();                       // all threads done reading r tile
        // phase 2: stage h into same buffer, then + h @ (A + I)
        STAGE_TILE(buf, g_h, rowbase);
        __syncthreads();
#pragma unroll
        for(int k = 0; k < DIMC; k++){
            float2 hh = *(const float2*)(buf + (k << 9) + 2*threadIdx.x);
            u64 spA = pk2(hh.x, hh.x), spB = pk2(hh.y, hh.y);
            GEMV_STEP(wa, k, spA, spB);
        }
        __syncthreads();                       // done reading h tile
        // silu on outputs (in place)
#pragma unroll
        for(int q = 0; q < 16; q++){
            float a0,a1,b0,b1; up2(accA[q],a0,a1); up2(accB[q],b0,b1);
            accA[q] = pk2(siluf(a0), siluf(a1));
            accB[q] = pk2(siluf(b0), siluf(b1));
        }
        STATS_PHASE(accA);
        STATS_PHASE(accB);
#pragma unroll
        for(int q = 0; q < 16; q++){
            float a0,a1,b0,b1; up2(accA[q],a0,a1); up2(accB[q],b0,b1);
            *(float2*)(g_h + (size_t)(2*q)*BATCH + row0)   = make_float2(a0, b0);
            *(float2*)(g_h + (size_t)(2*q+1)*BATCH + row0) = make_float2(a1, b1);
        }
    }
    STATS_TAIL();
}

// ---------------- head: out = h @ head_w + head_b (round-8 verbatim) ----------------
__global__ __launch_bounds__(TPB) void k_head(const float* __restrict__ hw,
                                              const float* __restrict__ hb,
                                              float* __restrict__ out){
    __shared__ float wsh[DIMC*INDIM];
    __shared__ float bshf[INDIM];
    __shared__ float tile[TPB*INDIM];
    for(int i = threadIdx.x; i < DIMC*INDIM; i += TPB) wsh[i] = hw[i];
    if(threadIdx.x < INDIM) bshf[threadIdx.x] = hb[threadIdx.x];
    __syncthreads();
#pragma unroll 1
    for(int it = 0; it < RPT; ++it){
        int rowbase = blockIdx.x*TPB + it*STRIDE;
        int row = rowbase + threadIdx.x;
        float acc[INDIM];
#pragma unroll
        for(int i = 0; i < INDIM; i++) acc[i] = bshf[i];
#pragma unroll 4
        for(int c = 0; c < DIMC; c++){
            float h = g_h[(size_t)c*BATCH + row];
#pragma unroll
            for(int i = 0; i < INDIM; i++) acc[i] = fmaf(h, wsh[c*INDIM + i], acc[i]);
        }
        __syncthreads();
#pragma unroll
        for(int i = 0; i < INDIM; i++) tile[threadIdx.x*INDIM + i] = acc[i];
        __syncthreads();
        for(int k = threadIdx.x; k < TPB*INDIM; k += TPB)
            out[(size_t)rowbase*INDIM + k] = tile[k];
    }
}

// ---------------- launch ----------------
extern "C" void kernel_launch(void* const* d_in, const int* in_sizes, int n_in,
                              void* d_out, int out_size) {
    (void)in_sizes; (void)n_in; (void)out_size;
    const float* x      = (const float*)d_in[0];
    const float* stem_w = (const float*)d_in[1];
    const float* stem_b = (const float*)d_in[2];
    const float* fno_wr = (const float*)d_in[3];
    const float* fno_wi = (const float*)d_in[4];
    const float* bn1_g  = (const float*)d_in[5];
    const float* bn1_b  = (const float*)d_in[6];
    const float* lin1_w = (const float*)d_in[7];
    const float* lin1_b = (const float*)d_in[8];
    const float* bn2_g  = (const float*)d_in[9];
    const float* bn2_b  = (const float*)d_in[10];
    const float* lin2_w = (const float*)d_in[11];
    const float* lin2_b = (const float*)d_in[12];
    const float* head_w = (const float*)d_in[13];
    const float* head_b = (const float*)d_in[14];
    float* out = (float*)d_out;

    cudaFuncSetAttribute(k_passA, cudaFuncAttributeMaxDynamicSharedMemorySize, DYN_BYTES);
    cudaFuncSetAttribute(k_passB, cudaFuncAttributeMaxDynamicSharedMemorySize, DYN_BYTES);

    k_precompute_A<<<16, 256>>>(fno_wr, fno_wi);
    k_stem<<<GRID_MAIN, TPB>>>(x, stem_w, stem_b);
    for(int l = 0; l < LAYERS; l++){
        k_fin<<<1, 1024>>>(bn1_g, bn1_b, l);          // stats of h -> bn1 affine
        k_passA<<<GRID_MAIN, TPB, DYN_BYTES>>>(lin1_w, lin1_b, l);
        k_fin<<<1, 1024>>>(bn2_g, bn2_b, l);          // stats of r -> bn2 affine
        k_passB<<<GRID_MAIN, TPB, DYN_BYTES>>>(lin2_w, lin2_b, l);
    }
    k_head<<<GRID_MAIN, TPB>>>(head_w, head_b, out);
}

// round 10
// speedup vs baseline: 1.0060x; 1.0060x over previous
#include <cuda_runtime.h>

#define BATCH   2097152
#define DIMC    32
#define INDIM   10
#define LAYERS  4
#define MB      17
#define EPSV    1e-5f

#define GRID_MAIN 2048
#define TPB       256
#define RPT       4                       // stem/head: 1 row/thread, 4 iters
#define STRIDE    (GRID_MAIN*TPB)
#define NTILES    4                       // passA/B: 4 tiles of 256 rows per CTA
#define TILE      256
#define DYN_FLOATS (16384 + 8960)         // two 8192-float buffers + stats tile
#define DYN_BYTES  (DYN_FLOATS * 4)

typedef unsigned long long u64;

// ---------------- scratch (__device__ globals: allocation-free) ----------------
__device__ __align__(16) float g_h[(size_t)DIMC * BATCH];   // planar [c][row]
__device__ __align__(16) float g_r[(size_t)DIMC * BATCH];   // planar [c][row]
__device__ __align__(16) float g_A[LAYERS * DIMC * DIMC];   // fused Fourier A+I, [l][in][out]
__device__ float g_partials[GRID_MAIN * 64];                // per-CTA [sum[32], sumsq[32]]
__device__ float g_scale[DIMC];                             // BN affine: y = x*scale + shift
__device__ float g_shift[DIMC];

// ---------------- packed f32x2 helpers ----------------
__device__ __forceinline__ u64 pk2(float a, float b){
    u64 r; asm("mov.b64 %0,{%1,%2};" : "=l"(r) : "f"(a), "f"(b)); return r;
}
__device__ __forceinline__ void up2(u64 v, float &a, float &b){
    asm("mov.b64 {%0,%1},%2;" : "=f"(a), "=f"(b) : "l"(v));
}
__device__ __forceinline__ u64 fma2(u64 a, u64 b, u64 c){
    u64 d; asm("fma.rn.f32x2 %0,%1,%2,%3;" : "=l"(d) : "l"(a), "l"(b), "l"(c)); return d;
}
__device__ __forceinline__ float siluf(float x){
    return x * __fdividef(1.0f, 1.0f + __expf(-x));
}

// ------- Fourier operator precompute: A' = A + I. One thread per element. -------
__global__ void k_precompute_A(const float* __restrict__ wr, const float* __restrict__ wi){
    __shared__ double ct[32], st[32];
    int t = threadIdx.x;
    if(t < 32){
        double ang = 6.283185307179586476925286766559 * (double)t / 32.0;
        ct[t] = cos(ang); st[t] = sin(ang);
    }
    __syncthreads();
    int g = blockIdx.x * blockDim.x + t;               // 0..4095
    if(g >= LAYERS*DIMC*DIMC) return;
    int l = g >> 10, j = (g >> 5) & 31, d = g & 31;
    const float* WR = wr + l*MB*MB;
    const float* WI = wi + l*MB*MB;
    double v = 0.0;
    for(int k = 0; k < MB; k++){
        double re = 0.0, im = 0.0;
        for(int m = 0; m < MB; m++){
            double c = ct[(m*j)&31], s = st[(m*j)&31];   // rfft of e_j: c - i*s
            double a = (double)WR[m*MB + k], b = (double)WI[m*MB + k];
            re += c*a + s*b;
            im += c*b - s*a;
        }
        double al, be;
        if(k == 0)      { al = 1.0; be = 0.0; }
        else if(k == 16){ al = (d & 1) ? -1.0 : 1.0; be = 0.0; }
        else            { al = 2.0*ct[(k*d)&31]; be = 2.0*st[(k*d)&31]; }
        v += al*re - be*im;
    }
    v *= (1.0/32.0);
    if(j == d) v += 1.0;                                  // fold identity skip
    g_A[(l*DIMC + j)*DIMC + d] = (float)v;
}

// ---- stats via shared tile: [256 rows][35] floats, conflict-free both directions ----
#define STATS_PHASE(ACC) do{                                                   \
    __syncthreads();                                                           \
    { float* trow = tile + threadIdx.x*35;                                     \
      _Pragma("unroll")                                                        \
      for(int q = 0; q < 16; q++){                                             \
          float _a,_b; up2((ACC)[q],_a,_b);                                    \
          trow[2*q] = _a; trow[2*q+1] = _b;                                    \
      } }                                                                      \
    __syncthreads();                                                           \
    _Pragma("unroll")                                                          \
    for(int j = 0; j < 32; j++){                                               \
        float v = tile[(mrow*32 + j)*35 + ch];                                 \
        ssum += v; ssq += v*v;                                                 \
    }                                                                          \
}while(0)

#define STATS_TAIL() do{                                                       \
    __syncthreads();                                                           \
    tile[mrow*64 + ch]      = ssum;                                            \
    tile[mrow*64 + 32 + ch] = ssq;                                             \
    __syncthreads();                                                           \
    if(threadIdx.x < 64){                                                      \
        float v = 0.f;                                                         \
        _Pragma("unroll")                                                      \
        for(int m = 0; m < 8; m++) v += tile[m*64 + threadIdx.x];              \
        g_partials[blockIdx.x*64 + threadIdx.x] = v;                           \
    }                                                                          \
}while(0)

// async copy of one 256-row x 32-ch planar tile into smem (layout [c][256])
// 2048 16B-chunks; 8 per thread; one commit_group.
#define COPY_TILE_ASYNC(DSTF, SRC, ROWBASE) do{                                \
    unsigned _sa = (unsigned)__cvta_generic_to_shared(DSTF);                   \
    _Pragma("unroll")                                                          \
    for(int _i = 0; _i < 8; _i++){                                             \
        int _idx = threadIdx.x + _i*256;                                       \
        int _c = _idx >> 6, _j = _idx & 63;                                    \
        const void* _src = (const void*)((SRC) + (size_t)_c*BATCH + (ROWBASE) + _j*4); \
        asm volatile("cp.async.cg.shared.global [%0], [%1], 16;"               \
                     :: "r"(_sa + _idx*16), "l"(_src) : "memory");             \
    }                                                                          \
    asm volatile("cp.async.commit_group;" ::: "memory");                       \
}while(0)

#define CP_WAIT_1() asm volatile("cp.async.wait_group 1;" ::: "memory")
#define CP_WAIT_0() asm volatile("cp.async.wait_group 0;" ::: "memory")

// 1-row GEMV k-step: acc[16] += sp * w[k][:]
#define GEMV1R_STEP(WSH, K, SP) do{                                            \
    const ulonglong2* _w2 = (const ulonglong2*)((WSH) + (K)*16);               \
    _Pragma("unroll")                                                          \
    for(int i = 0; i < 8; i++){                                                \
        ulonglong2 ww = _w2[i];                                                \
        acc[2*i]   = fma2((SP), ww.x, acc[2*i]);                               \
        acc[2*i+1] = fma2((SP), ww.y, acc[2*i+1]);                             \
    }                                                                          \
}while(0)

// ---------------- stem: h = x@stem_w + b; stats(h)  (round-8 verbatim) ----------------
__global__ __launch_bounds__(TPB) void k_stem(const float* __restrict__ x,
                                              const float* __restrict__ sw,
                                              const float* __restrict__ sb){
    __shared__ __align__(16) u64 wsh[INDIM*16];
    __shared__ u64 bsh[16];
    __shared__ float tile[8960];
    if(threadIdx.x < INDIM*16){
        int r = threadIdx.x >> 4, q = threadIdx.x & 15;
        wsh[threadIdx.x] = pk2(sw[r*DIMC + 2*q], sw[r*DIMC + 2*q + 1]);
    }
    if(threadIdx.x < 16) bsh[threadIdx.x] = pk2(sb[2*threadIdx.x], sb[2*threadIdx.x+1]);
    int ch = threadIdx.x & 31, mrow = threadIdx.x >> 5;
    float ssum = 0.f, ssq = 0.f;
    __syncthreads();
#pragma unroll 1
    for(int it = 0; it < RPT; ++it){
        int rowbase = blockIdx.x*TPB + it*STRIDE;
        int row = rowbase + threadIdx.x;
        __syncthreads();
        for(int k = threadIdx.x; k < TPB*INDIM; k += TPB)
            tile[k] = x[(size_t)rowbase*INDIM + k];
        __syncthreads();
        float xv[INDIM];
#pragma unroll
        for(int i = 0; i < INDIM; i++) xv[i] = tile[threadIdx.x*INDIM + i];
        __syncthreads();
        u64 acc[16];
#pragma unroll
        for(int q = 0; q < 16; q++) acc[q] = bsh[q];
#pragma unroll
        for(int i = 0; i < INDIM; i++){
            u64 xp = pk2(xv[i], xv[i]);
            GEMV1R_STEP(wsh, i, xp);
        }
        float* trow = tile + threadIdx.x*35;
#pragma unroll
        for(int q = 0; q < 16; q++){
            float a, b; up2(acc[q], a, b);
            g_h[(size_t)(2*q)*BATCH + row]   = a;
            g_h[(size_t)(2*q+1)*BATCH + row] = b;
            trow[2*q] = a; trow[2*q+1] = b;
        }
        __syncthreads();
#pragma unroll
        for(int j = 0; j < 32; j++){
            float v = tile[(mrow*32 + j)*35 + ch];
            ssum += v; ssq += v*v;
        }
    }
    STATS_TAIL();
}

// ---------------- finalize: partials -> BN scale/shift (round-8 verbatim) ----------------
__global__ void k_fin(const float* __restrict__ gamma, const float* __restrict__ beta, int layer){
    __shared__ float red[1024];
    __shared__ float tot[64];
    int t = threadIdx.x;
    int col = t & 63, part = t >> 6;
    const float* p = g_partials + (size_t)part*128*64 + col;
    float v = 0.f;
#pragma unroll 8
    for(int i = 0; i < 128; i++) v += p[(size_t)i*64];
    red[part*64 + col] = v;
    __syncthreads();
    if(t < 64){
        float s = 0.f;
#pragma unroll
        for(int q = 0; q < 16; q++) s += red[q*64 + t];
        tot[t] = s;
    }
    __syncthreads();
    if(t < DIMC){
        float mean = tot[t]      * (1.0f/(float)BATCH);
        float ex2  = tot[32 + t] * (1.0f/(float)BATCH);
        float var  = fmaxf(ex2 - mean*mean, 0.0f);
        float sc   = gamma[layer*DIMC + t] * rsqrtf(var + EPSV);
        g_scale[t] = sc;
        g_shift[t] = beta[layer*DIMC + t] - mean*sc;
    }
}

// ------- pass A: r = silu(bn1(h))@lin1 + b1; stats(r). cp.async double-buffered -------
__global__ __launch_bounds__(TPB, 2) void k_passA(const float* __restrict__ w1,
                                                  const float* __restrict__ b1, int layer){
    extern __shared__ __align__(16) float dyn[];
    float* buf  = dyn;            // 2 x 8192 floats: double-buffered h tiles [c][256]
    float* tile = dyn + 16384;    // 8960 floats: stats tile
    __shared__ __align__(16) u64 wsh[512];
    __shared__ u64 bsh[16];
    __shared__ float2 bn[DIMC];
    {
        const u64* src = (const u64*)(w1 + layer*DIMC*DIMC);
        for(int i = threadIdx.x; i < 512; i += TPB) wsh[i] = src[i];
    }
    if(threadIdx.x < DIMC) bn[threadIdx.x] = make_float2(g_scale[threadIdx.x], g_shift[threadIdx.x]);
    if(threadIdx.x < 16){
        const float* bb = b1 + layer*DIMC;
        bsh[threadIdx.x] = pk2(bb[2*threadIdx.x], bb[2*threadIdx.x+1]);
    }
    int ch = threadIdx.x & 31, mrow = threadIdx.x >> 5;
    float ssum = 0.f, ssq = 0.f;
    int base0 = blockIdx.x * (NTILES*TILE);
    COPY_TILE_ASYNC(buf, g_h, base0);            // tile 0 in flight
    __syncthreads();
#pragma unroll 1
    for(int t = 0; t < NTILES; ++t){
        if(t < NTILES-1){
            COPY_TILE_ASYNC(buf + ((t+1)&1)*8192, g_h, base0 + (t+1)*TILE);
            CP_WAIT_1();                         // tile t complete, t+1 in flight
        }else{
            CP_WAIT_0();
        }
        __syncthreads();
        const float* cur = buf + (t&1)*8192;
        int row = base0 + t*TILE + threadIdx.x;
        u64 acc[16];
#pragma unroll
        for(int q = 0; q < 16; q++) acc[q] = bsh[q];
#pragma unroll
        for(int k = 0; k < DIMC; k++){
            float h = cur[(k<<8) + threadIdx.x];
            float2 p = bn[k];
            float s = siluf(fmaf(h, p.x, p.y));
            u64 sp = pk2(s, s);
            GEMV1R_STEP(wsh, k, sp);
        }
        STATS_PHASE(acc);                        // first sync also fences cur reads
#pragma unroll
        for(int q = 0; q < 16; q++){
            float a, b; up2(acc[q], a, b);
            g_r[(size_t)(2*q)*BATCH + row]   = a;
            g_r[(size_t)(2*q+1)*BATCH + row] = b;
        }
    }
    STATS_TAIL();
}

// ------- pass B: h' = silu( h@(A+I) + silu(bn2(r))@lin2 + b2 ); stats(h') -------
// two buffers (R, H) pipelined at phase granularity: copies overlap GEMV phases.
__global__ __launch_bounds__(TPB, 2) void k_passB(const float* __restrict__ w2,
                                                  const float* __restrict__ b2, int layer){
    extern __shared__ __align__(16) float dyn[];
    float* bufR = dyn;            // 8192 floats: r tile [c][256]
    float* bufH = dyn + 8192;     // 8192 floats: h tile [c][256]
    float* tile = dyn + 16384;    // 8960 floats: stats tile
    __shared__ __align__(16) u64 wa[512];   // A+I
    __shared__ __align__(16) u64 wl[512];   // lin2
    __shared__ u64 bsh[16];
    __shared__ float2 bn[DIMC];
    {
        const u64* srcA = (const u64*)(g_A + layer*DIMC*DIMC);
        const u64* srcL = (const u64*)(w2  + layer*DIMC*DIMC);
        for(int i = threadIdx.x; i < 512; i += TPB){ wa[i] = srcA[i]; wl[i] = srcL[i]; }
    }
    if(threadIdx.x < DIMC) bn[threadIdx.x] = make_float2(g_scale[threadIdx.x], g_shift[threadIdx.x]);
    if(threadIdx.x < 16){
        const float* bb = b2 + layer*DIMC;
        bsh[threadIdx.x] = pk2(bb[2*threadIdx.x], bb[2*threadIdx.x+1]);
    }
    int ch = threadIdx.x & 31, mrow = threadIdx.x >> 5;
    float ssum = 0.f, ssq = 0.f;
    int base0 = blockIdx.x * (NTILES*TILE);
    COPY_TILE_ASYNC(bufR, g_r, base0);           // r(0)
    COPY_TILE_ASYNC(bufH, g_h, base0);           // h(0)
    __syncthreads();
#pragma unroll 1
    for(int t = 0; t < NTILES; ++t){
        int row = base0 + t*TILE + threadIdx.x;
        CP_WAIT_1();                             // r(t) done (h(t) may pend)
        __syncthreads();
        u64 acc[16];
#pragma unroll
        for(int q = 0; q < 16; q++) acc[q] = bsh[q];
        // phase 1: silu(bn2(r)) @ lin2 + b2   (reads bufR)
#pragma unroll
        for(int k = 0; k < DIMC; k++){
            float r = bufR[(k<<8) + threadIdx.x];
            float2 p = bn[k];
            float s = siluf(fmaf(r, p.x, p.y));
            u64 sp = pk2(s, s);
            GEMV1R_STEP(wl, k, sp);
        }
        __syncthreads();                         // all reads of bufR done
        if(t < NTILES-1){
            COPY_TILE_ASYNC(bufR, g_r, base0 + (t+1)*TILE);  // overlaps phase 2
            CP_WAIT_1();                         // h(t) done (r(t+1) pends)
        }else{
            CP_WAIT_0();                         // h(t) done
        }
        __syncthreads();
        // phase 2: + h @ (A + I)   (reads bufH)
#pragma unroll
        for(int k = 0; k < DIMC; k++){
            float h = bufH[(k<<8) + threadIdx.x];
            u64 sp = pk2(h, h);
            GEMV1R_STEP(wa, k, sp);
        }
        __syncthreads();                         // all reads of bufH done
        if(t < NTILES-1)
            COPY_TILE_ASYNC(bufH, g_h, base0 + (t+1)*TILE);  // overlaps stats/stores
        // silu on outputs (in place)
#pragma unroll
        for(int q = 0; q < 16; q++){
            float a, b; up2(acc[q], a, b);
            acc[q] = pk2(siluf(a), siluf(b));
        }
        STATS_PHASE(acc);
#pragma unroll
        for(int q = 0; q < 16; q++){
            float a, b; up2(acc[q], a, b);
            g_h[(size_t)(2*q)*BATCH + row]   = a;
            g_h[(size_t)(2*q+1)*BATCH + row] = b;
        }
    }
    STATS_TAIL();
}

// ---------------- head: out = h @ head_w + head_b (round-8 verbatim) ----------------
__global__ __launch_bounds__(TPB) void k_head(const float* __restrict__ hw,
                                              const float* __restrict__ hb,
                                              float* __restrict__ out){
    __shared__ float wsh[DIMC*INDIM];
    __shared__ float bshf[INDIM];
    __shared__ float tile[TPB*INDIM];
    for(int i = threadIdx.x; i < DIMC*INDIM; i += TPB) wsh[i] = hw[i];
    if(threadIdx.x < INDIM) bshf[threadIdx.x] = hb[threadIdx.x];
    __syncthreads();
#pragma unroll 1
    for(int it = 0; it < RPT; ++it){
        int rowbase = blockIdx.x*TPB + it*STRIDE;
        int row = rowbase + threadIdx.x;
        float acc[INDIM];
#pragma unroll
        for(int i = 0; i < INDIM; i++) acc[i] = bshf[i];
#pragma unroll 4
        for(int c = 0; c < DIMC; c++){
            float h = g_h[(size_t)c*BATCH + row];
#pragma unroll
            for(int i = 0; i < INDIM; i++) acc[i] = fmaf(h, wsh[c*INDIM + i], acc[i]);
        }
        __syncthreads();
#pragma unroll
        for(int i = 0; i < INDIM; i++) tile[threadIdx.x*INDIM + i] = acc[i];
        __syncthreads();
        for(int k = threadIdx.x; k < TPB*INDIM; k += TPB)
            out[(size_t)rowbase*INDIM + k] = tile[k];
    }
}

// ---------------- launch ----------------
extern "C" void kernel_launch(void* const* d_in, const int* in_sizes, int n_in,
                              void* d_out, int out_size) {
    (void)in_sizes; (void)n_in; (void)out_size;
    const float* x      = (const float*)d_in[0];
    const float* stem_w = (const float*)d_in[1];
    const float* stem_b = (const float*)d_in[2];
    const float* fno_wr = (const float*)d_in[3];
    const float* fno_wi = (const float*)d_in[4];
    const float* bn1_g  = (const float*)d_in[5];
    const float* bn1_b  = (const float*)d_in[6];
    const float* lin1_w = (const float*)d_in[7];
    const float* lin1_b = (const float*)d_in[8];
    const float* bn2_g  = (const float*)d_in[9];
    const float* bn2_b  = (const float*)d_in[10];
    const float* lin2_w = (const float*)d_in[11];
    const float* lin2_b = (const float*)d_in[12];
    const float* head_w = (const float*)d_in[13];
    const float* head_b = (const float*)d_in[14];
    float* out = (float*)d_out;

    cudaFuncSetAttribute(k_passA, cudaFuncAttributeMaxDynamicSharedMemorySize, DYN_BYTES);
    cudaFuncSetAttribute(k_passB, cudaFuncAttributeMaxDynamicSharedMemorySize, DYN_BYTES);

    k_precompute_A<<<16, 256>>>(fno_wr, fno_wi);
    k_stem<<<GRID_MAIN, TPB>>>(x, stem_w, stem_b);
    for(int l = 0; l < LAYERS; l++){
        k_fin<<<1, 1024>>>(bn1_g, bn1_b, l);          // stats of h -> bn1 affine
        k_passA<<<GRID_MAIN, TPB, DYN_BYTES>>>(lin1_w, lin1_b, l);
        k_fin<<<1, 1024>>>(bn2_g, bn2_b, l);          // stats of r -> bn2 affine
        k_passB<<<GRID_MAIN, TPB, DYN_BYTES>>>(lin2_w, lin2_b, l);
    }
    k_head<<<GRID_MAIN, TPB>>>(head_w, head_b, out);
}

// round 11
// speedup vs baseline: 1.0378x; 1.0316x over previous
#include <cuda_runtime.h>
#include <stdint.h>

#define BATCH   2097152
#define DIMC    32
#define INDIM   10
#define LAYERS  4
#define MB      17
#define EPSV    1e-5f

#define GRID_MAIN 2048
#define TPB       256
#define RPT       4                       // stem/head: 1 row/thread, 4 iters
#define STRIDE    (GRID_MAIN*TPB)

#define TILE_ROWS 256
#define NT        4                       // 2048 CTAs * 256 rows * 4 tiles = BATCH
#define PL        264                     // plane stride (floats): 264%32=8 -> conflict-free frags
#define PLANE     (DIMC*PL)               // 8448 floats

#define DYNA_FL   (PLANE + 512*4)                 // passA: 1 plane + 512 uint4 wf
#define DYNB_FL   (2*PLANE + 1536*4)              // passB: 2 planes + 1536 uint4 wf
#define DYNA_B    (DYNA_FL*4)
#define DYNB_B    (DYNB_FL*4)

typedef unsigned long long u64;

// ---------------- scratch ----------------
__device__ __align__(16) float g_h[(size_t)DIMC * BATCH];   // planar [c][row]
__device__ __align__(16) float g_A[LAYERS * DIMC * DIMC];   // fused Fourier A+I, [l][in][out]
__device__ float g_partials[GRID_MAIN * 64];
__device__ float g_scale[64];                               // slot0: bn1, slot1: bn2
__device__ float g_shift[64];

// ---------------- helpers ----------------
__device__ __forceinline__ u64 pk2(float a, float b){
    u64 r; asm("mov.b64 %0,{%1,%2};" : "=l"(r) : "f"(a), "f"(b)); return r;
}
__device__ __forceinline__ void up2(u64 v, float &a, float &b){
    asm("mov.b64 {%0,%1},%2;" : "=f"(a), "=f"(b) : "l"(v));
}
__device__ __forceinline__ u64 fma2(u64 a, u64 b, u64 c){
    u64 d; asm("fma.rn.f32x2 %0,%1,%2,%3;" : "=l"(d) : "l"(a), "l"(b), "l"(c)); return d;
}
__device__ __forceinline__ float siluf(float x){
    return x * __fdividef(1.0f, 1.0f + __expf(-x));
}
__device__ __forceinline__ unsigned tf32u(float x){
    unsigned u; asm("cvt.rna.tf32.f32 %0, %1;" : "=r"(u) : "f"(x)); return u;
}

// m16n8k8 tf32 MMA: d[4] += A(a[4]) * B(b0,b1)
#define MMA8(d, a, b0, b1) \
    asm("mma.sync.aligned.m16n8k8.row.col.f32.tf32.tf32.f32 " \
        "{%0,%1,%2,%3},{%4,%5,%6,%7},{%8,%9},{%0,%1,%2,%3};" \
        : "+f"((d)[0]), "+f"((d)[1]), "+f"((d)[2]), "+f"((d)[3]) \
        : "r"((a)[0]), "r"((a)[1]), "r"((a)[2]), "r"((a)[3]), "r"(b0), "r"(b1))

// ------- Fourier operator precompute: A' = A + I (round-8 verbatim) -------
__global__ void k_precompute_A(const float* __restrict__ wr, const float* __restrict__ wi){
    __shared__ double ct[32], st[32];
    int t = threadIdx.x;
    if(t < 32){
        double ang = 6.283185307179586476925286766559 * (double)t / 32.0;
        ct[t] = cos(ang); st[t] = sin(ang);
    }
    __syncthreads();
    int g = blockIdx.x * blockDim.x + t;
    if(g >= LAYERS*DIMC*DIMC) return;
    int l = g >> 10, j = (g >> 5) & 31, d = g & 31;
    const float* WR = wr + l*MB*MB;
    const float* WI = wi + l*MB*MB;
    double v = 0.0;
    for(int k = 0; k < MB; k++){
        double re = 0.0, im = 0.0;
        for(int m = 0; m < MB; m++){
            double c = ct[(m*j)&31], s = st[(m*j)&31];
            double a = (double)WR[m*MB + k], b = (double)WI[m*MB + k];
            re += c*a + s*b;
            im += c*b - s*a;
        }
        double al, be;
        if(k == 0)      { al = 1.0; be = 0.0; }
        else if(k == 16){ al = (d & 1) ? -1.0 : 1.0; be = 0.0; }
        else            { al = 2.0*ct[(k*d)&31]; be = 2.0*st[(k*d)&31]; }
        v += al*re - be*im;
    }
    v *= (1.0/32.0);
    if(j == d) v += 1.0;
    g_A[(l*DIMC + j)*DIMC + d] = (float)v;
}

// ---------------- stem (round-8 verbatim) ----------------
__global__ __launch_bounds__(TPB) void k_stem(const float* __restrict__ x,
                                              const float* __restrict__ sw,
                                              const float* __restrict__ sb){
    __shared__ __align__(16) u64 wsh[INDIM*16];
    __shared__ u64 bsh[16];
    __shared__ float tile[8960];
    if(threadIdx.x < INDIM*16){
        int r = threadIdx.x >> 4, q = threadIdx.x & 15;
        wsh[threadIdx.x] = pk2(sw[r*DIMC + 2*q], sw[r*DIMC + 2*q + 1]);
    }
    if(threadIdx.x < 16) bsh[threadIdx.x] = pk2(sb[2*threadIdx.x], sb[2*threadIdx.x+1]);
    int ch = threadIdx.x & 31, mrow = threadIdx.x >> 5;
    float ssum = 0.f, ssq = 0.f;
    __syncthreads();
#pragma unroll 1
    for(int it = 0; it < RPT; ++it){
        int rowbase = blockIdx.x*TPB + it*STRIDE;
        int row = rowbase + threadIdx.x;
        __syncthreads();
        for(int k = threadIdx.x; k < TPB*INDIM; k += TPB)
            tile[k] = x[(size_t)rowbase*INDIM + k];
        __syncthreads();
        float xv[INDIM];
#pragma unroll
        for(int i = 0; i < INDIM; i++) xv[i] = tile[threadIdx.x*INDIM + i];
        __syncthreads();
        u64 acc[16];
#pragma unroll
        for(int q = 0; q < 16; q++) acc[q] = bsh[q];
#pragma unroll
        for(int i = 0; i < INDIM; i++){
            u64 xp = pk2(xv[i], xv[i]);
            const ulonglong2* w2 = (const ulonglong2*)(wsh + i*16);
#pragma unroll
            for(int q = 0; q < 8; q++){
                ulonglong2 ww = w2[q];
                acc[2*q]   = fma2(xp, ww.x, acc[2*q]);
                acc[2*q+1] = fma2(xp, ww.y, acc[2*q+1]);
            }
        }
        float* trow = tile + threadIdx.x*35;
#pragma unroll
        for(int q = 0; q < 16; q++){
            float a, b; up2(acc[q], a, b);
            g_h[(size_t)(2*q)*BATCH + row]   = a;
            g_h[(size_t)(2*q+1)*BATCH + row] = b;
            trow[2*q] = a; trow[2*q+1] = b;
        }
        __syncthreads();
#pragma unroll
        for(int j = 0; j < 32; j++){
            float v = tile[(mrow*32 + j)*35 + ch];
            ssum += v; ssq += v*v;
        }
    }
    __syncthreads();
    tile[mrow*64 + ch]      = ssum;
    tile[mrow*64 + 32 + ch] = ssq;
    __syncthreads();
    if(threadIdx.x < 64){
        float v = 0.f;
#pragma unroll
        for(int m = 0; m < 8; m++) v += tile[m*64 + threadIdx.x];
        g_partials[blockIdx.x*64 + threadIdx.x] = v;
    }
}

// ---------------- finalize: partials -> BN affine into slot ----------------
__global__ void k_fin(const float* __restrict__ gamma, const float* __restrict__ beta,
                      int layer, int slot){
    __shared__ float red[1024];
    __shared__ float tot[64];
    int t = threadIdx.x;
    int col = t & 63, part = t >> 6;
    const float* p = g_partials + (size_t)part*128*64 + col;
    float v = 0.f;
#pragma unroll 8
    for(int i = 0; i < 128; i++) v += p[(size_t)i*64];
    red[part*64 + col] = v;
    __syncthreads();
    if(t < 64){
        float s = 0.f;
#pragma unroll
        for(int q = 0; q < 16; q++) s += red[q*64 + t];
        tot[t] = s;
    }
    __syncthreads();
    if(t < DIMC){
        float mean = tot[t]      * (1.0f/(float)BATCH);
        float ex2  = tot[32 + t] * (1.0f/(float)BATCH);
        float var  = fmaxf(ex2 - mean*mean, 0.0f);
        float sc   = gamma[layer*DIMC + t] * rsqrtf(var + EPSV);
        g_scale[slot*32 + t] = sc;
        g_shift[slot*32 + t] = beta[layer*DIMC + t] - mean*sc;
    }
}

// ---- shared device pieces for the MMA passes ----

// build split-tf32 B-fragment array for one 32x32 [in][out] matrix into WF[512]
// entry e: lane=e&31, ns=(e>>5)&3, ks=e>>7 ; uint4 = {hi_b0, hi_b1, lo_b0, lo_b1}
__device__ __forceinline__ void prep_wf(uint4* WF, const float* __restrict__ W){
    for(int e = threadIdx.x; e < 512; e += TPB){
        int lane = e & 31, ns = (e >> 5) & 3, ks = e >> 7;
        int tig = lane & 3, gg = lane >> 2;
        int k0 = ks*8 + tig, n = ns*8 + gg;
        float v0 = W[k0*32 + n], v1 = W[(k0+4)*32 + n];
        unsigned h0 = tf32u(v0);
        unsigned l0 = tf32u(v0 - __uint_as_float(h0));
        unsigned h1 = tf32u(v1);
        unsigned l1 = tf32u(v1 - __uint_as_float(h1));
        WF[(ks*4 + ns)*32 + lane] = make_uint4(h0, h1, l0, l1);
    }
}

// cooperative global<->plane copy (256 rows x 32 ch), float4 granularity
__device__ __forceinline__ void coop_load(float* P, const float* __restrict__ src, int rowbase){
#pragma unroll
    for(int i = 0; i < 8; i++){
        int f = threadIdx.x + i*256;           // 0..2047
        int c = f >> 6, r4 = f & 63;
        float4 v = *(const float4*)(src + (size_t)c*BATCH + rowbase + 4*r4);
        *(float4*)(P + c*PL + 4*r4) = v;
    }
}
__device__ __forceinline__ void coop_store(const float* P, float* __restrict__ dst, int rowbase){
#pragma unroll
    for(int i = 0; i < 8; i++){
        int f = threadIdx.x + i*256;
        int c = f >> 6, r4 = f & 63;
        float4 v = *(const float4*)(P + c*PL + 4*r4);
        *(float4*)(dst + (size_t)c*BATCH + rowbase + 4*r4) = v;
    }
}

// one 3-split MMA chain: acc[2][4][4] += P(rows wbase..wbase+31) @ W(frags)
__device__ __forceinline__ void chain(float acc[2][4][4], const float* P, const uint4* WF,
                                      int wbase, int tig, int gg){
#pragma unroll
    for(int ks = 0; ks < 4; ks++){
        unsigned ah[2][4], al[2][4];
#pragma unroll
        for(int s = 0; s < 2; s++){
            int rb = wbase + 16*s + gg;
            int c0 = (ks*8 + tig)*PL, c1 = c0 + 4*PL;
            float r0 = P[c0 + rb],     r1 = P[c0 + rb + 8];
            float r2 = P[c1 + rb],     r3 = P[c1 + rb + 8];
            ah[s][0] = tf32u(r0); al[s][0] = tf32u(r0 - __uint_as_float(ah[s][0]));
            ah[s][1] = tf32u(r1); al[s][1] = tf32u(r1 - __uint_as_float(ah[s][1]));
            ah[s][2] = tf32u(r2); al[s][2] = tf32u(r2 - __uint_as_float(ah[s][2]));
            ah[s][3] = tf32u(r3); al[s][3] = tf32u(r3 - __uint_as_float(ah[s][3]));
        }
#pragma unroll
        for(int ns = 0; ns < 4; ns++){
            uint4 w = WF[(ks*4 + ns)*32 + (threadIdx.x & 31)];
#pragma unroll
            for(int s = 0; s < 2; s++){
                MMA8(acc[s][ns], ah[s], w.x, w.y);   // hi*hi
                MMA8(acc[s][ns], ah[s], w.z, w.w);   // hi*lo
                MMA8(acc[s][ns], al[s], w.x, w.y);   // lo*hi
            }
        }
    }
}

// store acc frags (optionally silu) into plane at warp rows
__device__ __forceinline__ void frags_to_plane(float* P, float acc[2][4][4],
                                               int wbase, int tig, int gg, int do_silu){
#pragma unroll
    for(int s = 0; s < 2; s++){
        int rb = wbase + 16*s + gg;
#pragma unroll
        for(int ns = 0; ns < 4; ns++){
            int col = ns*8 + 2*tig;
            float v0 = acc[s][ns][0], v1 = acc[s][ns][1];
            float v2 = acc[s][ns][2], v3 = acc[s][ns][3];
            if(do_silu){ v0 = siluf(v0); v1 = siluf(v1); v2 = siluf(v2); v3 = siluf(v3); }
            P[col*PL + rb]       = v0;
            P[(col+1)*PL + rb]   = v1;
            P[col*PL + rb + 8]   = v2;
            P[(col+1)*PL + rb+8] = v3;
        }
    }
}

// add bias[col] to acc frags
__device__ __forceinline__ void add_bias(float acc[2][4][4], const float* bb, int tig){
#pragma unroll
    for(int ns = 0; ns < 4; ns++){
        float b0 = bb[ns*8 + 2*tig], b1 = bb[ns*8 + 2*tig + 1];
#pragma unroll
        for(int s = 0; s < 2; s++){
            acc[s][ns][0] += b0; acc[s][ns][1] += b1;
            acc[s][ns][2] += b0; acc[s][ns][3] += b1;
        }
    }
}

// per-thread channel stats over one plane tile (thread: ch=t&31, seg=t>>5 -> 32 rows)
__device__ __forceinline__ void plane_stats(const float* P, int ch, int seg,
                                            float &ssum, float &ssq){
    const float4* p4 = (const float4*)(P + ch*PL + seg*32);
#pragma unroll
    for(int k = 0; k < 8; k++){
        float4 v = p4[k];
        ssum += v.x + v.y + v.z + v.w;
        ssq  += v.x*v.x + v.y*v.y + v.z*v.z + v.w*v.w;
    }
}

#define MMA_STATS_TAIL() do{                                                   \
    __syncthreads();                                                           \
    sred[wid*64 + ch]      = ssum;                                             \
    sred[wid*64 + 32 + ch] = ssq;                                              \
    __syncthreads();                                                           \
    if(threadIdx.x < 64){                                                      \
        float v = 0.f;                                                         \
        _Pragma("unroll")                                                      \
        for(int m = 0; m < 8; m++) v += sred[m*64 + threadIdx.x];              \
        g_partials[blockIdx.x*64 + threadIdx.x] = v;                           \
    }                                                                          \
}while(0)

// ------- pass A: r = silu(bn1(h))@W1 + b1 ; emit stats(r) only (no r store) -------
__global__ __launch_bounds__(TPB, 3) void k_passA(const float* __restrict__ w1,
                                                  const float* __restrict__ b1, int layer){
    extern __shared__ __align__(16) float dyn[];
    float* P = dyn;                          // one plane (h -> s1 in place -> r frags)
    uint4* WF = (uint4*)(dyn + PLANE);
    __shared__ float sc1[32], sh1[32], bb1[32];
    __shared__ float sred[512];
    prep_wf(WF, w1 + layer*1024);
    if(threadIdx.x < 32){
        sc1[threadIdx.x] = g_scale[threadIdx.x];
        sh1[threadIdx.x] = g_shift[threadIdx.x];
        bb1[threadIdx.x] = b1[layer*32 + threadIdx.x];
    }
    int wid = threadIdx.x >> 5, lane = threadIdx.x & 31;
    int tig = lane & 3, gg = lane >> 2;
    int ch = lane, wbase = wid*32;
    float ssum = 0.f, ssq = 0.f;
    __syncthreads();
#pragma unroll 1
    for(int t = 0; t < NT; ++t){
        int rowbase = blockIdx.x*(NT*TILE_ROWS) + t*TILE_ROWS;
        coop_load(P, g_h, rowbase);
        __syncthreads();
        // s1 = silu(bn1(h)) in place (warp-private rows)
#pragma unroll
        for(int c = 0; c < DIMC; c++){
            float v = P[c*PL + wbase + lane];
            P[c*PL + wbase + lane] = siluf(fmaf(v, sc1[c], sh1[c]));
        }
        float acc[2][4][4];
#pragma unroll
        for(int s = 0; s < 2; s++)
#pragma unroll
            for(int n = 0; n < 4; n++)
#pragma unroll
                for(int q = 0; q < 4; q++) acc[s][n][q] = 0.f;
        chain(acc, P, WF, wbase, tig, gg);
        add_bias(acc, bb1, tig);
        frags_to_plane(P, acc, wbase, tig, gg, 0);   // raw r for stats
        __syncthreads();
        plane_stats(P, ch, wid, ssum, ssq);
        __syncthreads();                              // stats read done before next load
    }
    MMA_STATS_TAIL();
}

// ------- pass B: h' = silu( h@(A+I) + silu(bn2(r))@W2 + b2 ), r recomputed -------
__global__ __launch_bounds__(TPB, 2) void k_passB(const float* __restrict__ w1,
                                                  const float* __restrict__ b1,
                                                  const float* __restrict__ w2,
                                                  const float* __restrict__ b2, int layer){
    extern __shared__ __align__(16) float dyn[];
    float* H = dyn;                          // raw h plane
    float* S = dyn + PLANE;                  // s1 -> s2 -> out plane
    uint4* WF = (uint4*)(dyn + 2*PLANE);     // [0]=W1 [1]=W2 [2]=A'
    __shared__ float sc1[32], sh1[32], sc2[32], sh2[32], bb1[32], bb2[32];
    __shared__ float sred[512];
    prep_wf(WF,        w1 + layer*1024);
    prep_wf(WF + 512,  w2 + layer*1024);
    prep_wf(WF + 1024, g_A + layer*1024);
    if(threadIdx.x < 32){
        sc1[threadIdx.x] = g_scale[threadIdx.x];
        sh1[threadIdx.x] = g_shift[threadIdx.x];
        sc2[threadIdx.x] = g_scale[32 + threadIdx.x];
        sh2[threadIdx.x] = g_shift[32 + threadIdx.x];
        bb1[threadIdx.x] = b1[layer*32 + threadIdx.x];
        bb2[threadIdx.x] = b2[layer*32 + threadIdx.x];
    }
    int wid = threadIdx.x >> 5, lane = threadIdx.x & 31;
    int tig = lane & 3, gg = lane >> 2;
    int ch = lane, wbase = wid*32;
    float ssum = 0.f, ssq = 0.f;
    __syncthreads();
#pragma unroll 1
    for(int t = 0; t < NT; ++t){
        int rowbase = blockIdx.x*(NT*TILE_ROWS) + t*TILE_ROWS;
        coop_load(H, g_h, rowbase);
        __syncthreads();
        // s1 = silu(bn1(h)) -> S (warp-private rows)
#pragma unroll
        for(int c = 0; c < DIMC; c++){
            float v = H[c*PL + wbase + lane];
            S[c*PL + wbase + lane] = siluf(fmaf(v, sc1[c], sh1[c]));
        }
        float acc[2][4][4];
        // chain 1: r = s1 @ W1 + b1
#pragma unroll
        for(int s = 0; s < 2; s++)
#pragma unroll
            for(int n = 0; n < 4; n++)
#pragma unroll
                for(int q = 0; q < 4; q++) acc[s][n][q] = 0.f;
        chain(acc, S, WF, wbase, tig, gg);
        add_bias(acc, bb1, tig);
        // s2 = silu(bn2(r)) -> S (overwrite own rows; chain1 reads done)
#pragma unroll
        for(int s = 0; s < 2; s++){
            int rb = wbase + 16*s + gg;
#pragma unroll
            for(int ns = 0; ns < 4; ns++){
                int col = ns*8 + 2*tig;
                float a = sc2[col],   b = sh2[col];
                float a1 = sc2[col+1], b1v = sh2[col+1];
                S[col*PL + rb]        = siluf(fmaf(acc[s][ns][0], a,  b));
                S[(col+1)*PL + rb]    = siluf(fmaf(acc[s][ns][1], a1, b1v));
                S[col*PL + rb + 8]    = siluf(fmaf(acc[s][ns][2], a,  b));
                S[(col+1)*PL + rb+8]  = siluf(fmaf(acc[s][ns][3], a1, b1v));
            }
        }
        // chain 2: acc = s2 @ W2 + b2 ; chain 3: acc += h @ (A+I)
#pragma unroll
        for(int s = 0; s < 2; s++)
#pragma unroll
            for(int n = 0; n < 4; n++)
#pragma unroll
                for(int q = 0; q < 4; q++) acc[s][n][q] = 0.f;
        chain(acc, S, WF + 512,  wbase, tig, gg);
        add_bias(acc, bb2, tig);
        chain(acc, H, WF + 1024, wbase, tig, gg);
        // out = silu(acc) -> S (own rows; chain2 reads done)
        frags_to_plane(S, acc, wbase, tig, gg, 1);
        __syncthreads();
        coop_store(S, g_h, rowbase);
        plane_stats(S, ch, wid, ssum, ssq);
        __syncthreads();                              // before next tile overwrites H/S
    }
    MMA_STATS_TAIL();
}

// ---------------- head (round-8 verbatim) ----------------
__global__ __launch_bounds__(TPB) void k_head(const float* __restrict__ hw,
                                              const float* __restrict__ hb,
                                              float* __restrict__ out){
    __shared__ float wsh[DIMC*INDIM];
    __shared__ float bshf[INDIM];
    __shared__ float tile[TPB*INDIM];
    for(int i = threadIdx.x; i < DIMC*INDIM; i += TPB) wsh[i] = hw[i];
    if(threadIdx.x < INDIM) bshf[threadIdx.x] = hb[threadIdx.x];
    __syncthreads();
#pragma unroll 1
    for(int it = 0; it < RPT; ++it){
        int rowbase = blockIdx.x*TPB + it*STRIDE;
        int row = rowbase + threadIdx.x;
        float acc[INDIM];
#pragma unroll
        for(int i = 0; i < INDIM; i++) acc[i] = bshf[i];
#pragma unroll 4
        for(int c = 0; c < DIMC; c++){
            float h = g_h[(size_t)c*BATCH + row];
#pragma unroll
            for(int i = 0; i < INDIM; i++) acc[i] = fmaf(h, wsh[c*INDIM + i], acc[i]);
        }
        __syncthreads();
#pragma unroll
        for(int i = 0; i < INDIM; i++) tile[threadIdx.x*INDIM + i] = acc[i];
        __syncthreads();
        for(int k = threadIdx.x; k < TPB*INDIM; k += TPB)
            out[(size_t)rowbase*INDIM + k] = tile[k];
    }
}

// ---------------- launch ----------------
extern "C" void kernel_launch(void* const* d_in, const int* in_sizes, int n_in,
                              void* d_out, int out_size) {
    (void)in_sizes; (void)n_in; (void)out_size;
    const float* x      = (const float*)d_in[0];
    const float* stem_w = (const float*)d_in[1];
    const float* stem_b = (const float*)d_in[2];
    const float* fno_wr = (const float*)d_in[3];
    const float* fno_wi = (const float*)d_in[4];
    const float* bn1_g  = (const float*)d_in[5];
    const float* bn1_b  = (const float*)d_in[6];
    const float* lin1_w = (const float*)d_in[7];
    const float* lin1_b = (const float*)d_in[8];
    const float* bn2_g  = (const float*)d_in[9];
    const float* bn2_b  = (const float*)d_in[10];
    const float* lin2_w = (const float*)d_in[11];
    const float* lin2_b = (const float*)d_in[12];
    const float* head_w = (const float*)d_in[13];
    const float* head_b = (const float*)d_in[14];
    float* out = (float*)d_out;

    cudaFuncSetAttribute(k_passA, cudaFuncAttributeMaxDynamicSharedMemorySize, DYNA_B);
    cudaFuncSetAttribute(k_passB, cudaFuncAttributeMaxDynamicSharedMemorySize, DYNB_B);

    k_precompute_A<<<16, 256>>>(fno_wr, fno_wi);
    k_stem<<<GRID_MAIN, TPB>>>(x, stem_w, stem_b);
    for(int l = 0; l < LAYERS; l++){
        k_fin<<<1, 1024>>>(bn1_g, bn1_b, l, 0);      // h stats -> bn1 affine
        k_passA<<<GRID_MAIN, TPB, DYNA_B>>>(lin1_w, lin1_b, l);
        k_fin<<<1, 1024>>>(bn2_g, bn2_b, l, 1);      // r stats -> bn2 affine
        k_passB<<<GRID_MAIN, TPB, DYNB_B>>>(lin1_w, lin1_b, lin2_w, lin2_b, l);
    }
    k_head<<<GRID_MAIN, TPB>>>(head_w, head_b, out);
}

// round 12
// speedup vs baseline: 1.1207x; 1.0798x over previous
#include <cuda_runtime.h>
#include <stdint.h>

#define BATCH   2097152
#define DIMC    32
#define INDIM   10
#define LAYERS  4
#define MB      17
#define EPSV    1e-5f

#define GRID_MAIN 2048
#define TPB       256
#define RPT       4                       // stem/head: 1 row/thread, 4 iters
#define STRIDE    (GRID_MAIN*TPB)

#define TILE_ROWS 256
#define NT        4                       // 2048 CTAs * 256 rows * 4 tiles = BATCH
#define PL        264                     // plane stride (floats): conflict-free frags
#define PLANE     (DIMC*PL)               // 8448 floats

#define DYNA_FL   (PLANE + 512*4)                 // passA: 1 plane + 512 uint4 wf
#define DYNB_FL   (2*PLANE + 1536*4)              // passB: 2 planes + 1536 uint4 wf
#define DYNA_B    (DYNA_FL*4)
#define DYNB_B    (DYNB_FL*4)

typedef unsigned long long u64;

// ---------------- scratch ----------------
__device__ __align__(16) float g_h[(size_t)DIMC * BATCH];   // planar [c][row]
__device__ __align__(16) float g_A[LAYERS * DIMC * DIMC];   // fused Fourier A+I, [l][in][out]
__device__ float g_partials[GRID_MAIN * 64];
__device__ float g_scale[64];                               // slot0: bn1, slot1: bn2
__device__ float g_shift[64];

// ---------------- helpers ----------------
__device__ __forceinline__ u64 pk2(float a, float b){
    u64 r; asm("mov.b64 %0,{%1,%2};" : "=l"(r) : "f"(a), "f"(b)); return r;
}
__device__ __forceinline__ void up2(u64 v, float &a, float &b){
    asm("mov.b64 {%0,%1},%2;" : "=f"(a), "=f"(b) : "l"(v));
}
__device__ __forceinline__ u64 fma2(u64 a, u64 b, u64 c){
    u64 d; asm("fma.rn.f32x2 %0,%1,%2,%3;" : "=l"(d) : "l"(a), "l"(b), "l"(c)); return d;
}
__device__ __forceinline__ float siluf(float x){
    return x * __fdividef(1.0f, 1.0f + __expf(-x));
}
__device__ __forceinline__ unsigned tf32u(float x){
    unsigned u; asm("cvt.rna.tf32.f32 %0, %1;" : "=r"(u) : "f"(x)); return u;
}

// m16n8k8 tf32 MMA: d[4] += A(a[4]) * B(b0,b1)
#define MMA8(d, a, b0, b1) \
    asm("mma.sync.aligned.m16n8k8.row.col.f32.tf32.tf32.f32 " \
        "{%0,%1,%2,%3},{%4,%5,%6,%7},{%8,%9},{%0,%1,%2,%3};" \
        : "+f"((d)[0]), "+f"((d)[1]), "+f"((d)[2]), "+f"((d)[3]) \
        : "r"((a)[0]), "r"((a)[1]), "r"((a)[2]), "r"((a)[3]), "r"(b0), "r"(b1))

// ------- Fourier operator precompute: A' = A + I (verbatim) -------
__global__ void k_precompute_A(const float* __restrict__ wr, const float* __restrict__ wi){
    __shared__ double ct[32], st[32];
    int t = threadIdx.x;
    if(t < 32){
        double ang = 6.283185307179586476925286766559 * (double)t / 32.0;
        ct[t] = cos(ang); st[t] = sin(ang);
    }
    __syncthreads();
    int g = blockIdx.x * blockDim.x + t;
    if(g >= LAYERS*DIMC*DIMC) return;
    int l = g >> 10, j = (g >> 5) & 31, d = g & 31;
    const float* WR = wr + l*MB*MB;
    const float* WI = wi + l*MB*MB;
    double v = 0.0;
    for(int k = 0; k < MB; k++){
        double re = 0.0, im = 0.0;
        for(int m = 0; m < MB; m++){
            double c = ct[(m*j)&31], s = st[(m*j)&31];
            double a = (double)WR[m*MB + k], b = (double)WI[m*MB + k];
            re += c*a + s*b;
            im += c*b - s*a;
        }
        double al, be;
        if(k == 0)      { al = 1.0; be = 0.0; }
        else if(k == 16){ al = (d & 1) ? -1.0 : 1.0; be = 0.0; }
        else            { al = 2.0*ct[(k*d)&31]; be = 2.0*st[(k*d)&31]; }
        v += al*re - be*im;
    }
    v *= (1.0/32.0);
    if(j == d) v += 1.0;
    g_A[(l*DIMC + j)*DIMC + d] = (float)v;
}

// ---------------- stem (verbatim) ----------------
__global__ __launch_bounds__(TPB) void k_stem(const float* __restrict__ x,
                                              const float* __restrict__ sw,
                                              const float* __restrict__ sb){
    __shared__ __align__(16) u64 wsh[INDIM*16];
    __shared__ u64 bsh[16];
    __shared__ float tile[8960];
    if(threadIdx.x < INDIM*16){
        int r = threadIdx.x >> 4, q = threadIdx.x & 15;
        wsh[threadIdx.x] = pk2(sw[r*DIMC + 2*q], sw[r*DIMC + 2*q + 1]);
    }
    if(threadIdx.x < 16) bsh[threadIdx.x] = pk2(sb[2*threadIdx.x], sb[2*threadIdx.x+1]);
    int ch = threadIdx.x & 31, mrow = threadIdx.x >> 5;
    float ssum = 0.f, ssq = 0.f;
    __syncthreads();
#pragma unroll 1
    for(int it = 0; it < RPT; ++it){
        int rowbase = blockIdx.x*TPB + it*STRIDE;
        int row = rowbase + threadIdx.x;
        __syncthreads();
        for(int k = threadIdx.x; k < TPB*INDIM; k += TPB)
            tile[k] = x[(size_t)rowbase*INDIM + k];
        __syncthreads();
        float xv[INDIM];
#pragma unroll
        for(int i = 0; i < INDIM; i++) xv[i] = tile[threadIdx.x*INDIM + i];
        __syncthreads();
        u64 acc[16];
#pragma unroll
        for(int q = 0; q < 16; q++) acc[q] = bsh[q];
#pragma unroll
        for(int i = 0; i < INDIM; i++){
            u64 xp = pk2(xv[i], xv[i]);
            const ulonglong2* w2 = (const ulonglong2*)(wsh + i*16);
#pragma unroll
            for(int q = 0; q < 8; q++){
                ulonglong2 ww = w2[q];
                acc[2*q]   = fma2(xp, ww.x, acc[2*q]);
                acc[2*q+1] = fma2(xp, ww.y, acc[2*q+1]);
            }
        }
        float* trow = tile + threadIdx.x*35;
#pragma unroll
        for(int q = 0; q < 16; q++){
            float a, b; up2(acc[q], a, b);
            g_h[(size_t)(2*q)*BATCH + row]   = a;
            g_h[(size_t)(2*q+1)*BATCH + row] = b;
            trow[2*q] = a; trow[2*q+1] = b;
        }
        __syncthreads();
#pragma unroll
        for(int j = 0; j < 32; j++){
            float v = tile[(mrow*32 + j)*35 + ch];
            ssum += v; ssq += v*v;
        }
    }
    __syncthreads();
    tile[mrow*64 + ch]      = ssum;
    tile[mrow*64 + 32 + ch] = ssq;
    __syncthreads();
    if(threadIdx.x < 64){
        float v = 0.f;
#pragma unroll
        for(int m = 0; m < 8; m++) v += tile[m*64 + threadIdx.x];
        g_partials[blockIdx.x*64 + threadIdx.x] = v;
    }
}

// ---------------- finalize: partials -> BN affine into slot (verbatim) ----------------
__global__ void k_fin(const float* __restrict__ gamma, const float* __restrict__ beta,
                      int layer, int slot){
    __shared__ float red[1024];
    __shared__ float tot[64];
    int t = threadIdx.x;
    int col = t & 63, part = t >> 6;
    const float* p = g_partials + (size_t)part*128*64 + col;
    float v = 0.f;
#pragma unroll 8
    for(int i = 0; i < 128; i++) v += p[(size_t)i*64];
    red[part*64 + col] = v;
    __syncthreads();
    if(t < 64){
        float s = 0.f;
#pragma unroll
        for(int q = 0; q < 16; q++) s += red[q*64 + t];
        tot[t] = s;
    }
    __syncthreads();
    if(t < DIMC){
        float mean = tot[t]      * (1.0f/(float)BATCH);
        float ex2  = tot[32 + t] * (1.0f/(float)BATCH);
        float var  = fmaxf(ex2 - mean*mean, 0.0f);
        float sc   = gamma[layer*DIMC + t] * rsqrtf(var + EPSV);
        g_scale[slot*32 + t] = sc;
        g_shift[slot*32 + t] = beta[layer*DIMC + t] - mean*sc;
    }
}

// ---- shared device pieces for the MMA passes ----

__device__ __forceinline__ void prep_wf(uint4* WF, const float* __restrict__ W){
    for(int e = threadIdx.x; e < 512; e += TPB){
        int lane = e & 31, ns = (e >> 5) & 3, ks = e >> 7;
        int tig = lane & 3, gg = lane >> 2;
        int k0 = ks*8 + tig, n = ns*8 + gg;
        float v0 = W[k0*32 + n], v1 = W[(k0+4)*32 + n];
        unsigned h0 = tf32u(v0);
        unsigned l0 = tf32u(v0 - __uint_as_float(h0));
        unsigned h1 = tf32u(v1);
        unsigned l1 = tf32u(v1 - __uint_as_float(h1));
        WF[(ks*4 + ns)*32 + lane] = make_uint4(h0, h1, l0, l1);
    }
}

// staging: gmem -> plane with fused bn+silu (activation plane)
__device__ __forceinline__ void coop_load_act(float* S, const float* __restrict__ src,
                                              int rowbase, const float* sc, const float* sh){
#pragma unroll
    for(int i = 0; i < 8; i++){
        int f = threadIdx.x + i*256;
        int c = f >> 6, r4 = f & 63;
        float4 v = *(const float4*)(src + (size_t)c*BATCH + rowbase + 4*r4);
        float a = sc[c], b = sh[c];
        v.x = siluf(fmaf(v.x, a, b)); v.y = siluf(fmaf(v.y, a, b));
        v.z = siluf(fmaf(v.z, a, b)); v.w = siluf(fmaf(v.w, a, b));
        *(float4*)(S + c*PL + 4*r4) = v;
    }
}

// staging: gmem -> raw plane H AND activated plane S in one pass
__device__ __forceinline__ void coop_load_dual(float* H, float* S, const float* __restrict__ src,
                                               int rowbase, const float* sc, const float* sh){
#pragma unroll
    for(int i = 0; i < 8; i++){
        int f = threadIdx.x + i*256;
        int c = f >> 6, r4 = f & 63;
        float4 v = *(const float4*)(src + (size_t)c*BATCH + rowbase + 4*r4);
        *(float4*)(H + c*PL + 4*r4) = v;
        float a = sc[c], b = sh[c];
        v.x = siluf(fmaf(v.x, a, b)); v.y = siluf(fmaf(v.y, a, b));
        v.z = siluf(fmaf(v.z, a, b)); v.w = siluf(fmaf(v.w, a, b));
        *(float4*)(S + c*PL + 4*r4) = v;
    }
}

// one 3-split MMA chain: acc[2][4][4] += P(rows wbase..wbase+31) @ W(frags)
__device__ __forceinline__ void chain(float acc[2][4][4], const float* P, const uint4* WF,
                                      int wbase, int tig, int gg){
#pragma unroll
    for(int ks = 0; ks < 4; ks++){
        unsigned ah[2][4], al[2][4];
#pragma unroll
        for(int s = 0; s < 2; s++){
            int rb = wbase + 16*s + gg;
            int c0 = (ks*8 + tig)*PL, c1 = c0 + 4*PL;
            float r0 = P[c0 + rb],     r1 = P[c0 + rb + 8];
            float r2 = P[c1 + rb],     r3 = P[c1 + rb + 8];
            ah[s][0] = tf32u(r0); al[s][0] = tf32u(r0 - __uint_as_float(ah[s][0]));
            ah[s][1] = tf32u(r1); al[s][1] = tf32u(r1 - __uint_as_float(ah[s][1]));
            ah[s][2] = tf32u(r2); al[s][2] = tf32u(r2 - __uint_as_float(ah[s][2]));
            ah[s][3] = tf32u(r3); al[s][3] = tf32u(r3 - __uint_as_float(ah[s][3]));
        }
#pragma unroll
        for(int ns = 0; ns < 4; ns++){
            uint4 w = WF[(ks*4 + ns)*32 + (threadIdx.x & 31)];
#pragma unroll
            for(int s = 0; s < 2; s++){
                MMA8(acc[s][ns], ah[s], w.x, w.y);   // hi*hi
                MMA8(acc[s][ns], ah[s], w.z, w.w);   // hi*lo
                MMA8(acc[s][ns], al[s], w.x, w.y);   // lo*hi
            }
        }
    }
}

// store raw acc frags into plane at warp rows (for stats)
__device__ __forceinline__ void frags_to_plane(float* P, float acc[2][4][4],
                                               int wbase, int tig, int gg){
#pragma unroll
    for(int s = 0; s < 2; s++){
        int rb = wbase + 16*s + gg;
#pragma unroll
        for(int ns = 0; ns < 4; ns++){
            int col = ns*8 + 2*tig;
            P[col*PL + rb]       = acc[s][ns][0];
            P[(col+1)*PL + rb]   = acc[s][ns][1];
            P[col*PL + rb + 8]   = acc[s][ns][2];
            P[(col+1)*PL + rb+8] = acc[s][ns][3];
        }
    }
}

// silu + write frags to stats plane AND direct STG to gmem
__device__ __forceinline__ void frags_out(float* S, float* __restrict__ gdst, int rowbase,
                                          float acc[2][4][4], int wbase, int tig, int gg){
#pragma unroll
    for(int s = 0; s < 2; s++){
        int rb = wbase + 16*s + gg;
#pragma unroll
        for(int ns = 0; ns < 4; ns++){
            int col = ns*8 + 2*tig;
            float v0 = siluf(acc[s][ns][0]), v1 = siluf(acc[s][ns][1]);
            float v2 = siluf(acc[s][ns][2]), v3 = siluf(acc[s][ns][3]);
            S[col*PL + rb]       = v0;
            S[(col+1)*PL + rb]   = v1;
            S[col*PL + rb + 8]   = v2;
            S[(col+1)*PL + rb+8] = v3;
            gdst[(size_t)col*BATCH     + rowbase + rb]     = v0;
            gdst[(size_t)(col+1)*BATCH + rowbase + rb]     = v1;
            gdst[(size_t)col*BATCH     + rowbase + rb + 8] = v2;
            gdst[(size_t)(col+1)*BATCH + rowbase + rb + 8] = v3;
        }
    }
}

__device__ __forceinline__ void add_bias(float acc[2][4][4], const float* bb, int tig){
#pragma unroll
    for(int ns = 0; ns < 4; ns++){
        float b0 = bb[ns*8 + 2*tig], b1 = bb[ns*8 + 2*tig + 1];
#pragma unroll
        for(int s = 0; s < 2; s++){
            acc[s][ns][0] += b0; acc[s][ns][1] += b1;
            acc[s][ns][2] += b0; acc[s][ns][3] += b1;
        }
    }
}

__device__ __forceinline__ void plane_stats(const float* P, int ch, int seg,
                                            float &ssum, float &ssq){
    const float4* p4 = (const float4*)(P + ch*PL + seg*32);
#pragma unroll
    for(int k = 0; k < 8; k++){
        float4 v = p4[k];
        ssum += v.x + v.y + v.z + v.w;
        ssq  += v.x*v.x + v.y*v.y + v.z*v.z + v.w*v.w;
    }
}

#define MMA_STATS_TAIL() do{                                                   \
    __syncthreads();                                                           \
    sred[wid*64 + ch]      = ssum;                                             \
    sred[wid*64 + 32 + ch] = ssq;                                              \
    __syncthreads();                                                           \
    if(threadIdx.x < 64){                                                      \
        float v = 0.f;                                                         \
        _Pragma("unroll")                                                      \
        for(int m = 0; m < 8; m++) v += sred[m*64 + threadIdx.x];              \
        g_partials[blockIdx.x*64 + threadIdx.x] = v;                           \
    }                                                                          \
}while(0)

// ------- pass A: stats( silu(bn1(h))@W1 + b1 ), activation fused into staging -------
__global__ __launch_bounds__(TPB, 3) void k_passA(const float* __restrict__ w1,
                                                  const float* __restrict__ b1, int layer){
    extern __shared__ __align__(16) float dyn[];
    float* P = dyn;                          // activated plane -> r frags
    uint4* WF = (uint4*)(dyn + PLANE);
    __shared__ float sc1[32], sh1[32], bb1[32];
    __shared__ float sred[512];
    prep_wf(WF, w1 + layer*1024);
    if(threadIdx.x < 32){
        sc1[threadIdx.x] = g_scale[threadIdx.x];
        sh1[threadIdx.x] = g_shift[threadIdx.x];
        bb1[threadIdx.x] = b1[layer*32 + threadIdx.x];
    }
    int wid = threadIdx.x >> 5, lane = threadIdx.x & 31;
    int tig = lane & 3, gg = lane >> 2;
    int ch = lane, wbase = wid*32;
    float ssum = 0.f, ssq = 0.f;
    __syncthreads();
#pragma unroll 1
    for(int t = 0; t < NT; ++t){
        int rowbase = blockIdx.x*(NT*TILE_ROWS) + t*TILE_ROWS;
        coop_load_act(P, g_h, rowbase, sc1, sh1);    // s1 = silu(bn1(h)) fused
        __syncthreads();
        float acc[2][4][4];
#pragma unroll
        for(int s = 0; s < 2; s++)
#pragma unroll
            for(int n = 0; n < 4; n++)
#pragma unroll
                for(int q = 0; q < 4; q++) acc[s][n][q] = 0.f;
        chain(acc, P, WF, wbase, tig, gg);
        add_bias(acc, bb1, tig);
        frags_to_plane(P, acc, wbase, tig, gg);      // raw r for stats
        __syncthreads();
        plane_stats(P, ch, wid, ssum, ssq);
        __syncthreads();
    }
    MMA_STATS_TAIL();
}

// ------- pass B: h' = silu( h@(A+I) + silu(bn2(r))@W2 + b2 ), r recomputed -------
__global__ __launch_bounds__(TPB, 2) void k_passB(const float* __restrict__ w1,
                                                  const float* __restrict__ b1,
                                                  const float* __restrict__ w2,
                                                  const float* __restrict__ b2, int layer){
    extern __shared__ __align__(16) float dyn[];
    float* H = dyn;                          // raw h plane
    float* S = dyn + PLANE;                  // s1 -> s2 -> out plane
    uint4* WF = (uint4*)(dyn + 2*PLANE);     // [0]=W1 [1]=W2 [2]=A'
    __shared__ float sc1[32], sh1[32], sc2[32], sh2[32], bb1[32], bb2[32];
    __shared__ float sred[512];
    prep_wf(WF,        w1 + layer*1024);
    prep_wf(WF + 512,  w2 + layer*1024);
    prep_wf(WF + 1024, g_A + layer*1024);
    if(threadIdx.x < 32){
        sc1[threadIdx.x] = g_scale[threadIdx.x];
        sh1[threadIdx.x] = g_shift[threadIdx.x];
        sc2[threadIdx.x] = g_scale[32 + threadIdx.x];
        sh2[threadIdx.x] = g_shift[32 + threadIdx.x];
        bb1[threadIdx.x] = b1[layer*32 + threadIdx.x];
        bb2[threadIdx.x] = b2[layer*32 + threadIdx.x];
    }
    int wid = threadIdx.x >> 5, lane = threadIdx.x & 31;
    int tig = lane & 3, gg = lane >> 2;
    int ch = lane, wbase = wid*32;
    float ssum = 0.f, ssq = 0.f;
    __syncthreads();
#pragma unroll 1
    for(int t = 0; t < NT; ++t){
        int rowbase = blockIdx.x*(NT*TILE_ROWS) + t*TILE_ROWS;
        coop_load_dual(H, S, g_h, rowbase, sc1, sh1);   // H=raw, S=silu(bn1(h))
        __syncthreads();
        float acc[2][4][4];
        // chain 1: r = s1 @ W1 + b1
#pragma unroll
        for(int s = 0; s < 2; s++)
#pragma unroll
            for(int n = 0; n < 4; n++)
#pragma unroll
                for(int q = 0; q < 4; q++) acc[s][n][q] = 0.f;
        chain(acc, S, WF, wbase, tig, gg);
        add_bias(acc, bb1, tig);
        // s2 = silu(bn2(r)) -> S (own warp rows; chain1 reads were own rows too)
#pragma unroll
        for(int s = 0; s < 2; s++){
            int rb = wbase + 16*s + gg;
#pragma unroll
            for(int ns = 0; ns < 4; ns++){
                int col = ns*8 + 2*tig;
                float a = sc2[col],    b  = sh2[col];
                float a1 = sc2[col+1], b1v = sh2[col+1];
                S[col*PL + rb]        = siluf(fmaf(acc[s][ns][0], a,  b));
                S[(col+1)*PL + rb]    = siluf(fmaf(acc[s][ns][1], a1, b1v));
                S[col*PL + rb + 8]    = siluf(fmaf(acc[s][ns][2], a,  b));
                S[(col+1)*PL + rb+8]  = siluf(fmaf(acc[s][ns][3], a1, b1v));
            }
        }
        // chain 2: acc = s2 @ W2 + b2 ; chain 3: acc += h @ (A+I)
#pragma unroll
        for(int s = 0; s < 2; s++)
#pragma unroll
            for(int n = 0; n < 4; n++)
#pragma unroll
                for(int q = 0; q < 4; q++) acc[s][n][q] = 0.f;
        chain(acc, S, WF + 512,  wbase, tig, gg);
        add_bias(acc, bb2, tig);
        chain(acc, H, WF + 1024, wbase, tig, gg);
        // out = silu(acc): plane (stats) + direct STG to gmem
        frags_out(S, g_h, rowbase, acc, wbase, tig, gg);
        __syncthreads();
        plane_stats(S, ch, wid, ssum, ssq);
        __syncthreads();
    }
    MMA_STATS_TAIL();
}

// ---------------- head (verbatim) ----------------
__global__ __launch_bounds__(TPB) void k_head(const float* __restrict__ hw,
                                              const float* __restrict__ hb,
                                              float* __restrict__ out){
    __shared__ float wsh[DIMC*INDIM];
    __shared__ float bshf[INDIM];
    __shared__ float tile[TPB*INDIM];
    for(int i = threadIdx.x; i < DIMC*INDIM; i += TPB) wsh[i] = hw[i];
    if(threadIdx.x < INDIM) bshf[threadIdx.x] = hb[threadIdx.x];
    __syncthreads();
#pragma unroll 1
    for(int it = 0; it < RPT; ++it){
        int rowbase = blockIdx.x*TPB + it*STRIDE;
        int row = rowbase + threadIdx.x;
        float acc[INDIM];
#pragma unroll
        for(int i = 0; i < INDIM; i++) acc[i] = bshf[i];
#pragma unroll 4
        for(int c = 0; c < DIMC; c++){
            float h = g_h[(size_t)c*BATCH + row];
#pragma unroll
            for(int i = 0; i < INDIM; i++) acc[i] = fmaf(h, wsh[c*INDIM + i], acc[i]);
        }
        __syncthreads();
#pragma unroll
        for(int i = 0; i < INDIM; i++) tile[threadIdx.x*INDIM + i] = acc[i];
        __syncthreads();
        for(int k = threadIdx.x; k < TPB*INDIM; k += TPB)
            out[(size_t)rowbase*INDIM + k] = tile[k];
    }
}

// ---------------- launch ----------------
extern "C" void kernel_launch(void* const* d_in, const int* in_sizes, int n_in,
                              void* d_out, int out_size) {
    (void)in_sizes; (void)n_in; (void)out_size;
    const float* x      = (const float*)d_in[0];
    const float* stem_w = (const float*)d_in[1];
    const float* stem_b = (const float*)d_in[2];
    const float* fno_wr = (const float*)d_in[3];
    const float* fno_wi = (const float*)d_in[4];
    const float* bn1_g  = (const float*)d_in[5];
    const float* bn1_b  = (const float*)d_in[6];
    const float* lin1_w = (const float*)d_in[7];
    const float* lin1_b = (const float*)d_in[8];
    const float* bn2_g  = (const float*)d_in[9];
    const float* bn2_b  = (const float*)d_in[10];
    const float* lin2_w = (const float*)d_in[11];
    const float* lin2_b = (const float*)d_in[12];
    const float* head_w = (const float*)d_in[13];
    const float* head_b = (const float*)d_in[14];
    float* out = (float*)d_out;

    cudaFuncSetAttribute(k_passA, cudaFuncAttributeMaxDynamicSharedMemorySize, DYNA_B);
    cudaFuncSetAttribute(k_passB, cudaFuncAttributeMaxDynamicSharedMemorySize, DYNB_B);

    k_precompute_A<<<16, 256>>>(fno_wr, fno_wi);
    k_stem<<<GRID_MAIN, TPB>>>(x, stem_w, stem_b);
    for(int l = 0; l < LAYERS; l++){
        k_fin<<<1, 1024>>>(bn1_g, bn1_b, l, 0);      // h stats -> bn1 affine
        k_passA<<<GRID_MAIN, TPB, DYNA_B>>>(lin1_w, lin1_b, l);
        k_fin<<<1, 1024>>>(bn2_g, bn2_b, l, 1);      // r stats -> bn2 affine
        k_passB<<<GRID_MAIN, TPB, DYNB_B>>>(lin1_w, lin1_b, lin2_w, lin2_b, l);
    }
    k_head<<<GRID_MAIN, TPB>>>(head_w, head_b, out);
}

// round 13
// speedup vs baseline: 1.1821x; 1.0548x over previous
#include <cuda_runtime.h>
#include <stdint.h>

#define BATCH   2097152
#define DIMC    32
#define INDIM   10
#define LAYERS  4
#define MB      17
#define EPSV    1e-5f

#define GRID_MAIN 2048
#define TPB       256
#define RPT       4                       // stem/head: 1 row/thread, 4 iters
#define STRIDE    (GRID_MAIN*TPB)

#define TILE_ROWS 256
#define NT        4                       // 2048 CTAs * 256 rows * 4 tiles = BATCH
#define PL        264                     // plane stride (floats)
#define PLANE     (DIMC*PL)               // 8448 floats

#define DYNA_FL   (PLANE + 512*4)         // passA: 1 plane + 512 uint4 WF
#define DYNB_FL   (PLANE + 1536*4)        // passB: 1 plane + 1536 uint4 WF
#define DYNA_B    (DYNA_FL*4)
#define DYNB_B    (DYNB_FL*4)

typedef unsigned long long u64;

// ---------------- scratch ----------------
__device__ __align__(16) float g_h[(size_t)DIMC * BATCH];   // planar [c][row]
__device__ __align__(16) float g_A[LAYERS * DIMC * DIMC];   // fused Fourier A+I
__device__ float g_partials[GRID_MAIN * 64];
__device__ float g_scale[64];                               // slot0: bn1, slot1: bn2
__device__ float g_shift[64];

// ---------------- helpers ----------------
__device__ __forceinline__ u64 pk2(float a, float b){
    u64 r; asm("mov.b64 %0,{%1,%2};" : "=l"(r) : "f"(a), "f"(b)); return r;
}
__device__ __forceinline__ void up2(u64 v, float &a, float &b){
    asm("mov.b64 {%0,%1},%2;" : "=f"(a), "=f"(b) : "l"(v));
}
__device__ __forceinline__ u64 fma2(u64 a, u64 b, u64 c){
    u64 d; asm("fma.rn.f32x2 %0,%1,%2,%3;" : "=l"(d) : "l"(a), "l"(b), "l"(c)); return d;
}
__device__ __forceinline__ float siluf(float x){
    return x * __fdividef(1.0f, 1.0f + __expf(-x));
}
__device__ __forceinline__ unsigned tf32u(float x){
    unsigned u; asm("cvt.rna.tf32.f32 %0, %1;" : "=r"(u) : "f"(x)); return u;
}

#define MMA8(d, a, b0, b1) \
    asm("mma.sync.aligned.m16n8k8.row.col.f32.tf32.tf32.f32 " \
        "{%0,%1,%2,%3},{%4,%5,%6,%7},{%8,%9},{%0,%1,%2,%3};" \
        : "+f"((d)[0]), "+f"((d)[1]), "+f"((d)[2]), "+f"((d)[3]) \
        : "r"((a)[0]), "r"((a)[1]), "r"((a)[2]), "r"((a)[3]), "r"(b0), "r"(b1))

// ------- Fourier operator precompute: A' = A + I (verbatim) -------
__global__ void k_precompute_A(const float* __restrict__ wr, const float* __restrict__ wi){
    __shared__ double ct[32], st[32];
    int t = threadIdx.x;
    if(t < 32){
        double ang = 6.283185307179586476925286766559 * (double)t / 32.0;
        ct[t] = cos(ang); st[t] = sin(ang);
    }
    __syncthreads();
    int g = blockIdx.x * blockDim.x + t;
    if(g >= LAYERS*DIMC*DIMC) return;
    int l = g >> 10, j = (g >> 5) & 31, d = g & 31;
    const float* WR = wr + l*MB*MB;
    const float* WI = wi + l*MB*MB;
    double v = 0.0;
    for(int k = 0; k < MB; k++){
        double re = 0.0, im = 0.0;
        for(int m = 0; m < MB; m++){
            double c = ct[(m*j)&31], s = st[(m*j)&31];
            double a = (double)WR[m*MB + k], b = (double)WI[m*MB + k];
            re += c*a + s*b;
            im += c*b - s*a;
        }
        double al, be;
        if(k == 0)      { al = 1.0; be = 0.0; }
        else if(k == 16){ al = (d & 1) ? -1.0 : 1.0; be = 0.0; }
        else            { al = 2.0*ct[(k*d)&31]; be = 2.0*st[(k*d)&31]; }
        v += al*re - be*im;
    }
    v *= (1.0/32.0);
    if(j == d) v += 1.0;
    g_A[(l*DIMC + j)*DIMC + d] = (float)v;
}

// ---------------- stem (verbatim) ----------------
__global__ __launch_bounds__(TPB) void k_stem(const float* __restrict__ x,
                                              const float* __restrict__ sw,
                                              const float* __restrict__ sb){
    __shared__ __align__(16) u64 wsh[INDIM*16];
    __shared__ u64 bsh[16];
    __shared__ float tile[8960];
    if(threadIdx.x < INDIM*16){
        int r = threadIdx.x >> 4, q = threadIdx.x & 15;
        wsh[threadIdx.x] = pk2(sw[r*DIMC + 2*q], sw[r*DIMC + 2*q + 1]);
    }
    if(threadIdx.x < 16) bsh[threadIdx.x] = pk2(sb[2*threadIdx.x], sb[2*threadIdx.x+1]);
    int ch = threadIdx.x & 31, mrow = threadIdx.x >> 5;
    float ssum = 0.f, ssq = 0.f;
    __syncthreads();
#pragma unroll 1
    for(int it = 0; it < RPT; ++it){
        int rowbase = blockIdx.x*TPB + it*STRIDE;
        int row = rowbase + threadIdx.x;
        __syncthreads();
        for(int k = threadIdx.x; k < TPB*INDIM; k += TPB)
            tile[k] = x[(size_t)rowbase*INDIM + k];
        __syncthreads();
        float xv[INDIM];
#pragma unroll
        for(int i = 0; i < INDIM; i++) xv[i] = tile[threadIdx.x*INDIM + i];
        __syncthreads();
        u64 acc[16];
#pragma unroll
        for(int q = 0; q < 16; q++) acc[q] = bsh[q];
#pragma unroll
        for(int i = 0; i < INDIM; i++){
            u64 xp = pk2(xv[i], xv[i]);
            const ulonglong2* w2 = (const ulonglong2*)(wsh + i*16);
#pragma unroll
            for(int q = 0; q < 8; q++){
                ulonglong2 ww = w2[q];
                acc[2*q]   = fma2(xp, ww.x, acc[2*q]);
                acc[2*q+1] = fma2(xp, ww.y, acc[2*q+1]);
            }
        }
        float* trow = tile + threadIdx.x*35;
#pragma unroll
        for(int q = 0; q < 16; q++){
            float a, b; up2(acc[q], a, b);
            g_h[(size_t)(2*q)*BATCH + row]   = a;
            g_h[(size_t)(2*q+1)*BATCH + row] = b;
            trow[2*q] = a; trow[2*q+1] = b;
        }
        __syncthreads();
#pragma unroll
        for(int j = 0; j < 32; j++){
            float v = tile[(mrow*32 + j)*35 + ch];
            ssum += v; ssq += v*v;
        }
    }
    __syncthreads();
    tile[mrow*64 + ch]      = ssum;
    tile[mrow*64 + 32 + ch] = ssq;
    __syncthreads();
    if(threadIdx.x < 64){
        float v = 0.f;
#pragma unroll
        for(int m = 0; m < 8; m++) v += tile[m*64 + threadIdx.x];
        g_partials[blockIdx.x*64 + threadIdx.x] = v;
    }
}

// ---------------- finalize (verbatim) ----------------
__global__ void k_fin(const float* __restrict__ gamma, const float* __restrict__ beta,
                      int layer, int slot){
    __shared__ float red[1024];
    __shared__ float tot[64];
    int t = threadIdx.x;
    int col = t & 63, part = t >> 6;
    const float* p = g_partials + (size_t)part*128*64 + col;
    float v = 0.f;
#pragma unroll 8
    for(int i = 0; i < 128; i++) v += p[(size_t)i*64];
    red[part*64 + col] = v;
    __syncthreads();
    if(t < 64){
        float s = 0.f;
#pragma unroll
        for(int q = 0; q < 16; q++) s += red[q*64 + t];
        tot[t] = s;
    }
    __syncthreads();
    if(t < DIMC){
        float mean = tot[t]      * (1.0f/(float)BATCH);
        float ex2  = tot[32 + t] * (1.0f/(float)BATCH);
        float var  = fmaxf(ex2 - mean*mean, 0.0f);
        float sc   = gamma[layer*DIMC + t] * rsqrtf(var + EPSV);
        g_scale[slot*32 + t] = sc;
        g_shift[slot*32 + t] = beta[layer*DIMC + t] - mean*sc;
    }
}

// ---- MMA-pass pieces ----

__device__ __forceinline__ void prep_wf(uint4* WF, const float* __restrict__ W){
    for(int e = threadIdx.x; e < 512; e += TPB){
        int lane = e & 31, ns = (e >> 5) & 3, ks = e >> 7;
        int tig = lane & 3, gg = lane >> 2;
        int k0 = ks*8 + tig, n = ns*8 + gg;
        float v0 = W[k0*32 + n], v1 = W[(k0+4)*32 + n];
        unsigned h0 = tf32u(v0);
        unsigned l0 = tf32u(v0 - __uint_as_float(h0));
        unsigned h1 = tf32u(v1);
        unsigned l1 = tf32u(v1 - __uint_as_float(h1));
        WF[(ks*4 + ns)*32 + lane] = make_uint4(h0, h1, l0, l1);
    }
}

// staging: gmem -> plane with fused bn+silu
__device__ __forceinline__ void coop_load_act(float* S, const float* __restrict__ src,
                                              int rowbase, const float* sc, const float* sh){
#pragma unroll
    for(int i = 0; i < 8; i++){
        int f = threadIdx.x + i*256;
        int c = f >> 6, r4 = f & 63;
        float4 v = *(const float4*)(src + (size_t)c*BATCH + rowbase + 4*r4);
        float a = sc[c], b = sh[c];
        v.x = siluf(fmaf(v.x, a, b)); v.y = siluf(fmaf(v.y, a, b));
        v.z = siluf(fmaf(v.z, a, b)); v.w = siluf(fmaf(v.w, a, b));
        *(float4*)(S + c*PL + 4*r4) = v;
    }
}

// 3-split MMA chain from smem plane
__device__ __forceinline__ void chain(float acc[2][4][4], const float* P, const uint4* WF,
                                      int wbase, int tig, int gg){
#pragma unroll
    for(int ks = 0; ks < 4; ks++){
        unsigned ah[2][4], al[2][4];
#pragma unroll
        for(int s = 0; s < 2; s++){
            int rb = wbase + 16*s + gg;
            int c0 = (ks*8 + tig)*PL, c1 = c0 + 4*PL;
            float r0 = P[c0 + rb],     r1 = P[c0 + rb + 8];
            float r2 = P[c1 + rb],     r3 = P[c1 + rb + 8];
            ah[s][0] = tf32u(r0); al[s][0] = tf32u(r0 - __uint_as_float(ah[s][0]));
            ah[s][1] = tf32u(r1); al[s][1] = tf32u(r1 - __uint_as_float(ah[s][1]));
            ah[s][2] = tf32u(r2); al[s][2] = tf32u(r2 - __uint_as_float(ah[s][2]));
            ah[s][3] = tf32u(r3); al[s][3] = tf32u(r3 - __uint_as_float(ah[s][3]));
        }
#pragma unroll
        for(int ns = 0; ns < 4; ns++){
            uint4 w = WF[(ks*4 + ns)*32 + (threadIdx.x & 31)];
#pragma unroll
            for(int s = 0; s < 2; s++){
                MMA8(acc[s][ns], ah[s], w.x, w.y);
                MMA8(acc[s][ns], ah[s], w.z, w.w);
                MMA8(acc[s][ns], al[s], w.x, w.y);
            }
        }
    }
}

// 3-split MMA chain, A-fragments loaded straight from planar gmem (L1/L2 hits)
__device__ __forceinline__ void chain_g(float acc[2][4][4], const float* __restrict__ g,
                                        int rowbase, const uint4* WF,
                                        int wbase, int tig, int gg){
#pragma unroll
    for(int ks = 0; ks < 4; ks++){
        unsigned ah[2][4], al[2][4];
#pragma unroll
        for(int s = 0; s < 2; s++){
            size_t rb = (size_t)rowbase + wbase + 16*s + gg;
            const float* c0 = g + (size_t)(ks*8 + tig)*BATCH + rb;
            const float* c1 = g + (size_t)(ks*8 + tig + 4)*BATCH + rb;
            float r0 = __ldg(c0), r1 = __ldg(c0 + 8);
            float r2 = __ldg(c1), r3 = __ldg(c1 + 8);
            ah[s][0] = tf32u(r0); al[s][0] = tf32u(r0 - __uint_as_float(ah[s][0]));
            ah[s][1] = tf32u(r1); al[s][1] = tf32u(r1 - __uint_as_float(ah[s][1]));
            ah[s][2] = tf32u(r2); al[s][2] = tf32u(r2 - __uint_as_float(ah[s][2]));
            ah[s][3] = tf32u(r3); al[s][3] = tf32u(r3 - __uint_as_float(ah[s][3]));
        }
#pragma unroll
        for(int ns = 0; ns < 4; ns++){
            uint4 w = WF[(ks*4 + ns)*32 + (threadIdx.x & 31)];
#pragma unroll
            for(int s = 0; s < 2; s++){
                MMA8(acc[s][ns], ah[s], w.x, w.y);
                MMA8(acc[s][ns], ah[s], w.z, w.w);
                MMA8(acc[s][ns], al[s], w.x, w.y);
            }
        }
    }
}

__device__ __forceinline__ void add_bias(float acc[2][4][4], const float* bb, int tig){
#pragma unroll
    for(int ns = 0; ns < 4; ns++){
        float b0 = bb[ns*8 + 2*tig], b1 = bb[ns*8 + 2*tig + 1];
#pragma unroll
        for(int s = 0; s < 2; s++){
            acc[s][ns][0] += b0; acc[s][ns][1] += b1;
            acc[s][ns][2] += b0; acc[s][ns][3] += b1;
        }
    }
}

// register stats: butterfly over gg lanes, lanes 0..3 accumulate into sred[wid]
__device__ __forceinline__ void frag_stats(float* sred, float acc[2][4][4],
                                           int wid, int tig, int lane){
#pragma unroll
    for(int ns = 0; ns < 4; ns++){
        float s0 = acc[0][ns][0] + acc[0][ns][2] + acc[1][ns][0] + acc[1][ns][2];
        float s1 = acc[0][ns][1] + acc[0][ns][3] + acc[1][ns][1] + acc[1][ns][3];
        float q0 = acc[0][ns][0]*acc[0][ns][0] + acc[0][ns][2]*acc[0][ns][2]
                 + acc[1][ns][0]*acc[1][ns][0] + acc[1][ns][2]*acc[1][ns][2];
        float q1 = acc[0][ns][1]*acc[0][ns][1] + acc[0][ns][3]*acc[0][ns][3]
                 + acc[1][ns][1]*acc[1][ns][1] + acc[1][ns][3]*acc[1][ns][3];
#pragma unroll
        for(int m = 4; m < 32; m <<= 1){
            s0 += __shfl_xor_sync(0xffffffffu, s0, m);
            s1 += __shfl_xor_sync(0xffffffffu, s1, m);
            q0 += __shfl_xor_sync(0xffffffffu, q0, m);
            q1 += __shfl_xor_sync(0xffffffffu, q1, m);
        }
        if((lane & 28) == 0){              // gg == 0 (lanes 0..3)
            int col = ns*8 + 2*tig;
            sred[wid*64 + col]          += s0;
            sred[wid*64 + col + 1]      += s1;
            sred[wid*64 + 32 + col]     += q0;
            sred[wid*64 + 32 + col + 1] += q1;
        }
    }
}

#define MMA_STATS_TAIL() do{                                                   \
    if(threadIdx.x < 64){                                                      \
        float v = 0.f;                                                         \
        _Pragma("unroll")                                                      \
        for(int m = 0; m < 8; m++) v += sred[m*64 + threadIdx.x];              \
        g_partials[blockIdx.x*64 + threadIdx.x] = v;                           \
    }                                                                          \
}while(0)

// ------- pass A: stats( silu(bn1(h))@W1 + b1 ) — no gmem output at all -------
__global__ __launch_bounds__(TPB, 3) void k_passA(const float* __restrict__ w1,
                                                  const float* __restrict__ b1, int layer){
    extern __shared__ __align__(16) float dyn[];
    float* S  = dyn;
    uint4* WF = (uint4*)(dyn + PLANE);
    __shared__ float sc1[32], sh1[32], bb1[32];
    __shared__ float sred[512];
    prep_wf(WF, w1 + layer*1024);
    if(threadIdx.x < 32){
        sc1[threadIdx.x] = g_scale[threadIdx.x];
        sh1[threadIdx.x] = g_shift[threadIdx.x];
        bb1[threadIdx.x] = b1[layer*32 + threadIdx.x];
    }
    for(int i = threadIdx.x; i < 512; i += TPB) sred[i] = 0.f;
    int wid = threadIdx.x >> 5, lane = threadIdx.x & 31;
    int tig = lane & 3, gg = lane >> 2;
    int wbase = wid*32;
    __syncthreads();
#pragma unroll 1
    for(int t = 0; t < NT; ++t){
        int rowbase = blockIdx.x*(NT*TILE_ROWS) + t*TILE_ROWS;
        coop_load_act(S, g_h, rowbase, sc1, sh1);
        __syncthreads();
        float acc[2][4][4];
#pragma unroll
        for(int s = 0; s < 2; s++)
#pragma unroll
            for(int n = 0; n < 4; n++)
#pragma unroll
                for(int q = 0; q < 4; q++) acc[s][n][q] = 0.f;
        chain(acc, S, WF, wbase, tig, gg);
        add_bias(acc, bb1, tig);
        frag_stats(sred, acc, wid, tig, lane);
        __syncthreads();                  // S reads done before next staging
    }
    MMA_STATS_TAIL();
}

// ------- pass B: h' = silu( h@(A+I) + silu(bn2(r))@W2 + b2 ), r recomputed -------
__global__ __launch_bounds__(TPB, 3) void k_passB(const float* __restrict__ w1,
                                                  const float* __restrict__ b1,
                                                  const float* __restrict__ w2,
                                                  const float* __restrict__ b2, int layer){
    extern __shared__ __align__(16) float dyn[];
    float* S  = dyn;                       // s1 -> s2 plane
    uint4* WF = (uint4*)(dyn + PLANE);     // [0]=W1 [512]=W2 [1024]=A'
    __shared__ float sc1[32], sh1[32], sc2[32], sh2[32], bb1[32], bb2[32];
    __shared__ float sred[512];
    prep_wf(WF,        w1 + layer*1024);
    prep_wf(WF + 512,  w2 + layer*1024);
    prep_wf(WF + 1024, g_A + layer*1024);
    if(threadIdx.x < 32){
        sc1[threadIdx.x] = g_scale[threadIdx.x];
        sh1[threadIdx.x] = g_shift[threadIdx.x];
        sc2[threadIdx.x] = g_scale[32 + threadIdx.x];
        sh2[threadIdx.x] = g_shift[32 + threadIdx.x];
        bb1[threadIdx.x] = b1[layer*32 + threadIdx.x];
        bb2[threadIdx.x] = b2[layer*32 + threadIdx.x];
    }
    for(int i = threadIdx.x; i < 512; i += TPB) sred[i] = 0.f;
    int wid = threadIdx.x >> 5, lane = threadIdx.x & 31;
    int tig = lane & 3, gg = lane >> 2;
    int wbase = wid*32;
    __syncthreads();
#pragma unroll 1
    for(int t = 0; t < NT; ++t){
        int rowbase = blockIdx.x*(NT*TILE_ROWS) + t*TILE_ROWS;
        coop_load_act(S, g_h, rowbase, sc1, sh1);     // S = silu(bn1(h))
        __syncthreads();
        float acc[2][4][4];
        // chain 1: r = s1 @ W1 + b1
#pragma unroll
        for(int s = 0; s < 2; s++)
#pragma unroll
            for(int n = 0; n < 4; n++)
#pragma unroll
                for(int q = 0; q < 4; q++) acc[s][n][q] = 0.f;
        chain(acc, S, WF, wbase, tig, gg);
        add_bias(acc, bb1, tig);
        // s2 = silu(bn2(r)) -> S (own warp rows only)
#pragma unroll
        for(int s = 0; s < 2; s++){
            int rb = wbase + 16*s + gg;
#pragma unroll
            for(int ns = 0; ns < 4; ns++){
                int col = ns*8 + 2*tig;
                float a = sc2[col],    b  = sh2[col];
                float a1 = sc2[col+1], b1v = sh2[col+1];
                S[col*PL + rb]        = siluf(fmaf(acc[s][ns][0], a,  b));
                S[(col+1)*PL + rb]    = siluf(fmaf(acc[s][ns][1], a1, b1v));
                S[col*PL + rb + 8]    = siluf(fmaf(acc[s][ns][2], a,  b));
                S[(col+1)*PL + rb+8]  = siluf(fmaf(acc[s][ns][3], a1, b1v));
            }
        }
        __syncwarp();
        // chain 2: acc = s2 @ W2 + b2 ; chain 3: acc += h @ (A+I) from gmem
#pragma unroll
        for(int s = 0; s < 2; s++)
#pragma unroll
            for(int n = 0; n < 4; n++)
#pragma unroll
                for(int q = 0; q < 4; q++) acc[s][n][q] = 0.f;
        chain(acc, S, WF + 512, wbase, tig, gg);
        add_bias(acc, bb2, tig);
        chain_g(acc, g_h, rowbase, WF + 1024, wbase, tig, gg);
        // out = silu(acc): direct STG + register stats
#pragma unroll
        for(int s = 0; s < 2; s++){
            int rb = wbase + 16*s + gg;
#pragma unroll
            for(int ns = 0; ns < 4; ns++){
                int col = ns*8 + 2*tig;
                float v0 = siluf(acc[s][ns][0]), v1 = siluf(acc[s][ns][1]);
                float v2 = siluf(acc[s][ns][2]), v3 = siluf(acc[s][ns][3]);
                acc[s][ns][0] = v0; acc[s][ns][1] = v1;
                acc[s][ns][2] = v2; acc[s][ns][3] = v3;
                g_h[(size_t)col*BATCH     + rowbase + rb]     = v0;
                g_h[(size_t)(col+1)*BATCH + rowbase + rb]     = v1;
                g_h[(size_t)col*BATCH     + rowbase + rb + 8] = v2;
                g_h[(size_t)(col+1)*BATCH + rowbase + rb + 8] = v3;
            }
        }
        frag_stats(sred, acc, wid, tig, lane);
        __syncthreads();                  // S reads done before next staging
    }
    MMA_STATS_TAIL();
}

// ---------------- head (verbatim) ----------------
__global__ __launch_bounds__(TPB) void k_head(const float* __restrict__ hw,
                                              const float* __restrict__ hb,
                                              float* __restrict__ out){
    __shared__ float wsh[DIMC*INDIM];
    __shared__ float bshf[INDIM];
    __shared__ float tile[TPB*INDIM];
    for(int i = threadIdx.x; i < DIMC*INDIM; i += TPB) wsh[i] = hw[i];
    if(threadIdx.x < INDIM) bshf[threadIdx.x] = hb[threadIdx.x];
    __syncthreads();
#pragma unroll 1
    for(int it = 0; it < RPT; ++it){
        int rowbase = blockIdx.x*TPB + it*STRIDE;
        int row = rowbase + threadIdx.x;
        float acc[INDIM];
#pragma unroll
        for(int i = 0; i < INDIM; i++) acc[i] = bshf[i];
#pragma unroll 4
        for(int c = 0; c < DIMC; c++){
            float h = g_h[(size_t)c*BATCH + row];
#pragma unroll
            for(int i = 0; i < INDIM; i++) acc[i] = fmaf(h, wsh[c*INDIM + i], acc[i]);
        }
        __syncthreads();
#pragma unroll
        for(int i = 0; i < INDIM; i++) tile[threadIdx.x*INDIM + i] = acc[i];
        __syncthreads();
        for(int k = threadIdx.x; k < TPB*INDIM; k += TPB)
            out[(size_t)rowbase*INDIM + k] = tile[k];
    }
}

// ---------------- launch ----------------
extern "C" void kernel_launch(void* const* d_in, const int* in_sizes, int n_in,
                              void* d_out, int out_size) {
    (void)in_sizes; (void)n_in; (void)out_size;
    const float* x      = (const float*)d_in[0];
    const float* stem_w = (const float*)d_in[1];
    const float* stem_b = (const float*)d_in[2];
    const float* fno_wr = (const float*)d_in[3];
    const float* fno_wi = (const float*)d_in[4];
    const float* bn1_g  = (const float*)d_in[5];
    const float* bn1_b  = (const float*)d_in[6];
    const float* lin1_w = (const float*)d_in[7];
    const float* lin1_b = (const float*)d_in[8];
    const float* bn2_g  = (const float*)d_in[9];
    const float* bn2_b  = (const float*)d_in[10];
    const float* lin2_w = (const float*)d_in[11];
    const float* lin2_b = (const float*)d_in[12];
    const float* head_w = (const float*)d_in[13];
    const float* head_b = (const float*)d_in[14];
    float* out = (float*)d_out;

    cudaFuncSetAttribute(k_passA, cudaFuncAttributeMaxDynamicSharedMemorySize, DYNA_B);
    cudaFuncSetAttribute(k_passB, cudaFuncAttributeMaxDynamicSharedMemorySize, DYNB_B);

    k_precompute_A<<<16, 256>>>(fno_wr, fno_wi);
    k_stem<<<GRID_MAIN, TPB>>>(x, stem_w, stem_b);
    for(int l = 0; l < LAYERS; l++){
        k_fin<<<1, 1024>>>(bn1_g, bn1_b, l, 0);      // h stats -> bn1 affine
        k_passA<<<GRID_MAIN, TPB, DYNA_B>>>(lin1_w, lin1_b, l);
        k_fin<<<1, 1024>>>(bn2_g, bn2_b, l, 1);      // r stats -> bn2 affine
        k_passB<<<GRID_MAIN, TPB, DYNB_B>>>(lin1_w, lin1_b, lin2_w, lin2_b, l);
    }
    k_head<<<GRID_MAIN, TPB>>>(head_w, head_b, out);
}

// round 14
// speedup vs baseline: 1.4100x; 1.1927x over previous
#include <cuda_runtime.h>
#include <stdint.h>

#define BATCH   2097152
#define DIMC    32
#define INDIM   10
#define LAYERS  4
#define MB      17
#define EPSV    1e-5f

#define GRID_MAIN 2048
#define TPB       256
#define RPT       4                       // stem/head: 1 row/thread, 4 iters
#define STRIDE    (GRID_MAIN*TPB)

#define TILE_ROWS 256
#define NT        4                       // 2048 CTAs * 256 rows * 4 tiles = BATCH
#define PL        260                     // plane stride (floats): bank = 8*tig+gg, conflict-free
#define PLANE     (DIMC*PL)               // 8320 floats

#define DYNA_FL   (PLANE + 256*4)         // passA: 1 plane + 256 uint4 WF
#define DYNB_FL   (PLANE + 768*4)         // passB: 1 plane + 3*256 uint4 WF
#define DYNA_B    (DYNA_FL*4)
#define DYNB_B    (DYNB_FL*4)

typedef unsigned long long u64;

// ---------------- scratch ----------------
__device__ __align__(16) float g_h[(size_t)DIMC * BATCH];   // planar [c][row]
__device__ __align__(16) float g_A[LAYERS * DIMC * DIMC];   // fused Fourier A+I
__device__ float g_partials[GRID_MAIN * 64];
__device__ float g_scale[64];                               // slot0: bn1, slot1: bn2
__device__ float g_shift[64];

// ---------------- helpers ----------------
__device__ __forceinline__ u64 pk2(float a, float b){
    u64 r; asm("mov.b64 %0,{%1,%2};" : "=l"(r) : "f"(a), "f"(b)); return r;
}
__device__ __forceinline__ void up2(u64 v, float &a, float &b){
    asm("mov.b64 {%0,%1},%2;" : "=f"(a), "=f"(b) : "l"(v));
}
__device__ __forceinline__ u64 fma2(u64 a, u64 b, u64 c){
    u64 d; asm("fma.rn.f32x2 %0,%1,%2,%3;" : "=l"(d) : "l"(a), "l"(b), "l"(c)); return d;
}
__device__ __forceinline__ float siluf(float x){
    return x * __fdividef(1.0f, 1.0f + __expf(-x));
}
// packed bf16x2: d = {hi: vhi, lo: vlo}
__device__ __forceinline__ unsigned bf2(float vhi, float vlo){
    unsigned d; asm("cvt.rn.bf16x2.f32 %0,%1,%2;" : "=r"(d) : "f"(vhi), "f"(vlo)); return d;
}
// split pair (v0 -> lo half, v1 -> hi half) into bf16 head + bf16 residual
__device__ __forceinline__ void bfsplit(float v0, float v1, unsigned &hi, unsigned &lo){
    hi = bf2(v1, v0);
    float f0 = __uint_as_float(hi << 16);
    float f1 = __uint_as_float(hi & 0xffff0000u);
    lo = bf2(v1 - f1, v0 - f0);
}

// m16n8k16 bf16 MMA: d[4] += A(a[4]) * B(b0,b1)
#define MMA16(d, a, b0, b1) \
    asm("mma.sync.aligned.m16n8k16.row.col.f32.bf16.bf16.f32 " \
        "{%0,%1,%2,%3},{%4,%5,%6,%7},{%8,%9},{%0,%1,%2,%3};" \
        : "+f"((d)[0]), "+f"((d)[1]), "+f"((d)[2]), "+f"((d)[3]) \
        : "r"((a)[0]), "r"((a)[1]), "r"((a)[2]), "r"((a)[3]), "r"(b0), "r"(b1))

// ------- Fourier operator precompute: A' = A + I (verbatim) -------
__global__ void k_precompute_A(const float* __restrict__ wr, const float* __restrict__ wi){
    __shared__ double ct[32], st[32];
    int t = threadIdx.x;
    if(t < 32){
        double ang = 6.283185307179586476925286766559 * (double)t / 32.0;
        ct[t] = cos(ang); st[t] = sin(ang);
    }
    __syncthreads();
    int g = blockIdx.x * blockDim.x + t;
    if(g >= LAYERS*DIMC*DIMC) return;
    int l = g >> 10, j = (g >> 5) & 31, d = g & 31;
    const float* WR = wr + l*MB*MB;
    const float* WI = wi + l*MB*MB;
    double v = 0.0;
    for(int k = 0; k < MB; k++){
        double re = 0.0, im = 0.0;
        for(int m = 0; m < MB; m++){
            double c = ct[(m*j)&31], s = st[(m*j)&31];
            double a = (double)WR[m*MB + k], b = (double)WI[m*MB + k];
            re += c*a + s*b;
            im += c*b - s*a;
        }
        double al, be;
        if(k == 0)      { al = 1.0; be = 0.0; }
        else if(k == 16){ al = (d & 1) ? -1.0 : 1.0; be = 0.0; }
        else            { al = 2.0*ct[(k*d)&31]; be = 2.0*st[(k*d)&31]; }
        v += al*re - be*im;
    }
    v *= (1.0/32.0);
    if(j == d) v += 1.0;
    g_A[(l*DIMC + j)*DIMC + d] = (float)v;
}

// ---------------- stem (verbatim) ----------------
__global__ __launch_bounds__(TPB) void k_stem(const float* __restrict__ x,
                                              const float* __restrict__ sw,
                                              const float* __restrict__ sb){
    __shared__ __align__(16) u64 wsh[INDIM*16];
    __shared__ u64 bsh[16];
    __shared__ float tile[8960];
    if(threadIdx.x < INDIM*16){
        int r = threadIdx.x >> 4, q = threadIdx.x & 15;
        wsh[threadIdx.x] = pk2(sw[r*DIMC + 2*q], sw[r*DIMC + 2*q + 1]);
    }
    if(threadIdx.x < 16) bsh[threadIdx.x] = pk2(sb[2*threadIdx.x], sb[2*threadIdx.x+1]);
    int ch = threadIdx.x & 31, mrow = threadIdx.x >> 5;
    float ssum = 0.f, ssq = 0.f;
    __syncthreads();
#pragma unroll 1
    for(int it = 0; it < RPT; ++it){
        int rowbase = blockIdx.x*TPB + it*STRIDE;
        int row = rowbase + threadIdx.x;
        __syncthreads();
        for(int k = threadIdx.x; k < TPB*INDIM; k += TPB)
            tile[k] = x[(size_t)rowbase*INDIM + k];
        __syncthreads();
        float xv[INDIM];
#pragma unroll
        for(int i = 0; i < INDIM; i++) xv[i] = tile[threadIdx.x*INDIM + i];
        __syncthreads();
        u64 acc[16];
#pragma unroll
        for(int q = 0; q < 16; q++) acc[q] = bsh[q];
#pragma unroll
        for(int i = 0; i < INDIM; i++){
            u64 xp = pk2(xv[i], xv[i]);
            const ulonglong2* w2 = (const ulonglong2*)(wsh + i*16);
#pragma unroll
            for(int q = 0; q < 8; q++){
                ulonglong2 ww = w2[q];
                acc[2*q]   = fma2(xp, ww.x, acc[2*q]);
                acc[2*q+1] = fma2(xp, ww.y, acc[2*q+1]);
            }
        }
        float* trow = tile + threadIdx.x*35;
#pragma unroll
        for(int q = 0; q < 16; q++){
            float a, b; up2(acc[q], a, b);
            g_h[(size_t)(2*q)*BATCH + row]   = a;
            g_h[(size_t)(2*q+1)*BATCH + row] = b;
            trow[2*q] = a; trow[2*q+1] = b;
        }
        __syncthreads();
#pragma unroll
        for(int j = 0; j < 32; j++){
            float v = tile[(mrow*32 + j)*35 + ch];
            ssum += v; ssq += v*v;
        }
    }
    __syncthreads();
    tile[mrow*64 + ch]      = ssum;
    tile[mrow*64 + 32 + ch] = ssq;
    __syncthreads();
    if(threadIdx.x < 64){
        float v = 0.f;
#pragma unroll
        for(int m = 0; m < 8; m++) v += tile[m*64 + threadIdx.x];
        g_partials[blockIdx.x*64 + threadIdx.x] = v;
    }
}

// ---------------- finalize (verbatim) ----------------
__global__ void k_fin(const float* __restrict__ gamma, const float* __restrict__ beta,
                      int layer, int slot){
    __shared__ float red[1024];
    __shared__ float tot[64];
    int t = threadIdx.x;
    int col = t & 63, part = t >> 6;
    const float* p = g_partials + (size_t)part*128*64 + col;
    float v = 0.f;
#pragma unroll 8
    for(int i = 0; i < 128; i++) v += p[(size_t)i*64];
    red[part*64 + col] = v;
    __syncthreads();
    if(t < 64){
        float s = 0.f;
#pragma unroll
        for(int q = 0; q < 16; q++) s += red[q*64 + t];
        tot[t] = s;
    }
    __syncthreads();
    if(t < DIMC){
        float mean = tot[t]      * (1.0f/(float)BATCH);
        float ex2  = tot[32 + t] * (1.0f/(float)BATCH);
        float var  = fmaxf(ex2 - mean*mean, 0.0f);
        float sc   = gamma[layer*DIMC + t] * rsqrtf(var + EPSV);
        g_scale[slot*32 + t] = sc;
        g_shift[slot*32 + t] = beta[layer*DIMC + t] - mean*sc;
    }
}

// ---- MMA-pass pieces (bf16 2-part split) ----

// 256 uint4 per matrix: entry [(ks*4+ns)*32 + lane] = {hi_b0, hi_b1, lo_b0, lo_b1}
// b0 = {B[k0][n], B[k0+1][n]}, b1 = {B[k0+8][n], B[k0+9][n]}, k0 = 16ks + 2tig, n = 8ns + gg
__device__ __forceinline__ void prep_wf(uint4* WF, const float* __restrict__ W){
    for(int e = threadIdx.x; e < 256; e += TPB){
        int lane = e & 31, ns = (e >> 5) & 3, ks = e >> 7;
        int tig = lane & 3, gg = lane >> 2;
        int k0 = ks*16 + 2*tig, n = ns*8 + gg;
        float b0 = W[k0*32 + n],     b1 = W[(k0+1)*32 + n];
        float b2 = W[(k0+8)*32 + n], b3 = W[(k0+9)*32 + n];
        unsigned h01, l01, h23, l23;
        bfsplit(b0, b1, h01, l01);
        bfsplit(b2, b3, h23, l23);
        WF[(ks*4 + ns)*32 + lane] = make_uint4(h01, h23, l01, l23);
    }
}

// staging: gmem -> plane with fused bn+silu
__device__ __forceinline__ void coop_load_act(float* S, const float* __restrict__ src,
                                              int rowbase, const float* sc, const float* sh){
#pragma unroll
    for(int i = 0; i < 8; i++){
        int f = threadIdx.x + i*256;
        int c = f >> 6, r4 = f & 63;
        float4 v = *(const float4*)(src + (size_t)c*BATCH + rowbase + 4*r4);
        float a = sc[c], b = sh[c];
        v.x = siluf(fmaf(v.x, a, b)); v.y = siluf(fmaf(v.y, a, b));
        v.z = siluf(fmaf(v.z, a, b)); v.w = siluf(fmaf(v.w, a, b));
        *(float4*)(S + c*PL + 4*r4) = v;
    }
}

// split 8 A-values (rows rb/rb+8, k = k0,k0+1,k0+8,k0+9) into hi/lo fragments
#define A_SPLIT(GET, K0, RB)                                                    \
    do{                                                                         \
        float v00 = GET((K0),   (RB)),   v01 = GET((K0)+1, (RB));               \
        float u00 = GET((K0),   (RB)+8), u01 = GET((K0)+1, (RB)+8);             \
        float v08 = GET((K0)+8, (RB)),   v09 = GET((K0)+9, (RB));               \
        float u08 = GET((K0)+8, (RB)+8), u09 = GET((K0)+9, (RB)+8);             \
        bfsplit(v00, v01, ah[s][0], al[s][0]);                                  \
        bfsplit(u00, u01, ah[s][1], al[s][1]);                                  \
        bfsplit(v08, v09, ah[s][2], al[s][2]);                                  \
        bfsplit(u08, u09, ah[s][3], al[s][3]);                                  \
    }while(0)

// 3-term bf16 MMA chain from smem plane
__device__ __forceinline__ void chain(float acc[2][4][4], const float* P, const uint4* WF,
                                      int wbase, int tig, int gg, int lane){
#pragma unroll
    for(int ks = 0; ks < 2; ks++){
        unsigned ah[2][4], al[2][4];
        int k0 = ks*16 + 2*tig;
#pragma unroll
        for(int s = 0; s < 2; s++){
            int rb = wbase + 16*s + gg;
#define GET_S(K, R) P[(K)*PL + (R)]
            A_SPLIT(GET_S, k0, rb);
#undef GET_S
        }
#pragma unroll
        for(int ns = 0; ns < 4; ns++){
            uint4 w = WF[(ks*4 + ns)*32 + lane];
#pragma unroll
            for(int s = 0; s < 2; s++){
                MMA16(acc[s][ns], ah[s], w.x, w.y);   // hi*hi
                MMA16(acc[s][ns], ah[s], w.z, w.w);   // hi*lo
                MMA16(acc[s][ns], al[s], w.x, w.y);   // lo*hi
            }
        }
    }
}

// 3-term bf16 MMA chain, A loaded straight from planar gmem (L1/L2 hits)
__device__ __forceinline__ void chain_g(float acc[2][4][4], const float* __restrict__ g,
                                        int rowbase, const uint4* WF,
                                        int wbase, int tig, int gg, int lane){
#pragma unroll
    for(int ks = 0; ks < 2; ks++){
        unsigned ah[2][4], al[2][4];
        int k0 = ks*16 + 2*tig;
#pragma unroll
        for(int s = 0; s < 2; s++){
            size_t rb0 = (size_t)rowbase + wbase + 16*s + gg;
#define GET_G(K, R) __ldg(g + (size_t)(K)*BATCH + (rb0 - (wbase + 16*s + gg)) + (R))
            // R is rb-relative: pass absolute via helper below instead
#undef GET_G
            const float* base = g + rb0;
            float v00 = __ldg(base + (size_t)(k0)*BATCH),     v01 = __ldg(base + (size_t)(k0+1)*BATCH);
            float u00 = __ldg(base + (size_t)(k0)*BATCH + 8), u01 = __ldg(base + (size_t)(k0+1)*BATCH + 8);
            float v08 = __ldg(base + (size_t)(k0+8)*BATCH),     v09 = __ldg(base + (size_t)(k0+9)*BATCH);
            float u08 = __ldg(base + (size_t)(k0+8)*BATCH + 8), u09 = __ldg(base + (size_t)(k0+9)*BATCH + 8);
            bfsplit(v00, v01, ah[s][0], al[s][0]);
            bfsplit(u00, u01, ah[s][1], al[s][1]);
            bfsplit(v08, v09, ah[s][2], al[s][2]);
            bfsplit(u08, u09, ah[s][3], al[s][3]);
        }
#pragma unroll
        for(int ns = 0; ns < 4; ns++){
            uint4 w = WF[(ks*4 + ns)*32 + lane];
#pragma unroll
            for(int s = 0; s < 2; s++){
                MMA16(acc[s][ns], ah[s], w.x, w.y);
                MMA16(acc[s][ns], ah[s], w.z, w.w);
                MMA16(acc[s][ns], al[s], w.x, w.y);
            }
        }
    }
}

__device__ __forceinline__ void add_bias(float acc[2][4][4], const float* bb, int tig){
#pragma unroll
    for(int ns = 0; ns < 4; ns++){
        float b0 = bb[ns*8 + 2*tig], b1 = bb[ns*8 + 2*tig + 1];
#pragma unroll
        for(int s = 0; s < 2; s++){
            acc[s][ns][0] += b0; acc[s][ns][1] += b1;
            acc[s][ns][2] += b0; acc[s][ns][3] += b1;
        }
    }
}

// register stats: butterfly over gg lanes, lanes 0..3 accumulate into sred[wid]
__device__ __forceinline__ void frag_stats(float* sred, float acc[2][4][4],
                                           int wid, int tig, int lane){
#pragma unroll
    for(int ns = 0; ns < 4; ns++){
        float s0 = acc[0][ns][0] + acc[0][ns][2] + acc[1][ns][0] + acc[1][ns][2];
        float s1 = acc[0][ns][1] + acc[0][ns][3] + acc[1][ns][1] + acc[1][ns][3];
        float q0 = acc[0][ns][0]*acc[0][ns][0] + acc[0][ns][2]*acc[0][ns][2]
                 + acc[1][ns][0]*acc[1][ns][0] + acc[1][ns][2]*acc[1][ns][2];
        float q1 = acc[0][ns][1]*acc[0][ns][1] + acc[0][ns][3]*acc[0][ns][3]
                 + acc[1][ns][1]*acc[1][ns][1] + acc[1][ns][3]*acc[1][ns][3];
#pragma unroll
        for(int m = 4; m < 32; m <<= 1){
            s0 += __shfl_xor_sync(0xffffffffu, s0, m);
            s1 += __shfl_xor_sync(0xffffffffu, s1, m);
            q0 += __shfl_xor_sync(0xffffffffu, q0, m);
            q1 += __shfl_xor_sync(0xffffffffu, q1, m);
        }
        if((lane & 28) == 0){              // gg == 0 (lanes 0..3)
            int col = ns*8 + 2*tig;
            sred[wid*64 + col]          += s0;
            sred[wid*64 + col + 1]      += s1;
            sred[wid*64 + 32 + col]     += q0;
            sred[wid*64 + 32 + col + 1] += q1;
        }
    }
}

#define MMA_STATS_TAIL() do{                                                   \
    if(threadIdx.x < 64){                                                      \
        float v = 0.f;                                                         \
        _Pragma("unroll")                                                      \
        for(int m = 0; m < 8; m++) v += sred[m*64 + threadIdx.x];              \
        g_partials[blockIdx.x*64 + threadIdx.x] = v;                           \
    }                                                                          \
}while(0)

// ------- pass A: stats( silu(bn1(h))@W1 + b1 ) — no gmem output -------
__global__ __launch_bounds__(TPB, 3) void k_passA(const float* __restrict__ w1,
                                                  const float* __restrict__ b1, int layer){
    extern __shared__ __align__(16) float dyn[];
    float* S  = dyn;
    uint4* WF = (uint4*)(dyn + PLANE);
    __shared__ float sc1[32], sh1[32], bb1[32];
    __shared__ float sred[512];
    prep_wf(WF, w1 + layer*1024);
    if(threadIdx.x < 32){
        sc1[threadIdx.x] = g_scale[threadIdx.x];
        sh1[threadIdx.x] = g_shift[threadIdx.x];
        bb1[threadIdx.x] = b1[layer*32 + threadIdx.x];
    }
    for(int i = threadIdx.x; i < 512; i += TPB) sred[i] = 0.f;
    int wid = threadIdx.x >> 5, lane = threadIdx.x & 31;
    int tig = lane & 3, gg = lane >> 2;
    int wbase = wid*32;
    __syncthreads();
#pragma unroll 1
    for(int t = 0; t < NT; ++t){
        int rowbase = blockIdx.x*(NT*TILE_ROWS) + t*TILE_ROWS;
        coop_load_act(S, g_h, rowbase, sc1, sh1);
        __syncthreads();
        float acc[2][4][4];
#pragma unroll
        for(int s = 0; s < 2; s++)
#pragma unroll
            for(int n = 0; n < 4; n++)
#pragma unroll
                for(int q = 0; q < 4; q++) acc[s][n][q] = 0.f;
        chain(acc, S, WF, wbase, tig, gg, lane);
        add_bias(acc, bb1, tig);
        frag_stats(sred, acc, wid, tig, lane);
        __syncthreads();                  // S reads done before next staging
    }
    MMA_STATS_TAIL();
}

// ------- pass B: h' = silu( h@(A+I) + silu(bn2(r))@W2 + b2 ), r recomputed -------
__global__ __launch_bounds__(TPB, 3) void k_passB(const float* __restrict__ w1,
                                                  const float* __restrict__ b1,
                                                  const float* __restrict__ w2,
                                                  const float* __restrict__ b2, int layer){
    extern __shared__ __align__(16) float dyn[];
    float* S  = dyn;                       // s1 -> s2 plane
    uint4* WF = (uint4*)(dyn + PLANE);     // [0]=W1 [256]=W2 [512]=A'
    __shared__ float sc1[32], sh1[32], sc2[32], sh2[32], bb1[32], bb2[32];
    __shared__ float sred[512];
    prep_wf(WF,        w1 + layer*1024);
    prep_wf(WF + 256,  w2 + layer*1024);
    prep_wf(WF + 512,  g_A + layer*1024);
    if(threadIdx.x < 32){
        sc1[threadIdx.x] = g_scale[threadIdx.x];
        sh1[threadIdx.x] = g_shift[threadIdx.x];
        sc2[threadIdx.x] = g_scale[32 + threadIdx.x];
        sh2[threadIdx.x] = g_shift[32 + threadIdx.x];
        bb1[threadIdx.x] = b1[layer*32 + threadIdx.x];
        bb2[threadIdx.x] = b2[layer*32 + threadIdx.x];
    }
    for(int i = threadIdx.x; i < 512; i += TPB) sred[i] = 0.f;
    int wid = threadIdx.x >> 5, lane = threadIdx.x & 31;
    int tig = lane & 3, gg = lane >> 2;
    int wbase = wid*32;
    __syncthreads();
#pragma unroll 1
    for(int t = 0; t < NT; ++t){
        int rowbase = blockIdx.x*(NT*TILE_ROWS) + t*TILE_ROWS;
        coop_load_act(S, g_h, rowbase, sc1, sh1);     // S = silu(bn1(h))
        __syncthreads();
        float acc[2][4][4];
        // chain 1: r = s1 @ W1 + b1
#pragma unroll
        for(int s = 0; s < 2; s++)
#pragma unroll
            for(int n = 0; n < 4; n++)
#pragma unroll
                for(int q = 0; q < 4; q++) acc[s][n][q] = 0.f;
        chain(acc, S, WF, wbase, tig, gg, lane);
        add_bias(acc, bb1, tig);
        // s2 = silu(bn2(r)) -> S (own warp rows only)
#pragma unroll
        for(int s = 0; s < 2; s++){
            int rb = wbase + 16*s + gg;
#pragma unroll
            for(int ns = 0; ns < 4; ns++){
                int col = ns*8 + 2*tig;
                float a = sc2[col],    b  = sh2[col];
                float a1 = sc2[col+1], b1v = sh2[col+1];
                S[col*PL + rb]        = siluf(fmaf(acc[s][ns][0], a,  b));
                S[(col+1)*PL + rb]    = siluf(fmaf(acc[s][ns][1], a1, b1v));
                S[col*PL + rb + 8]    = siluf(fmaf(acc[s][ns][2], a,  b));
                S[(col+1)*PL + rb+8]  = siluf(fmaf(acc[s][ns][3], a1, b1v));
            }
        }
        __syncwarp();
        // chain 2: acc = s2 @ W2 + b2 ; chain 3: acc += h @ (A+I) from gmem
#pragma unroll
        for(int s = 0; s < 2; s++)
#pragma unroll
            for(int n = 0; n < 4; n++)
#pragma unroll
                for(int q = 0; q < 4; q++) acc[s][n][q] = 0.f;
        chain(acc, S, WF + 256, wbase, tig, gg, lane);
        add_bias(acc, bb2, tig);
        chain_g(acc, g_h, rowbase, WF + 512, wbase, tig, gg, lane);
        // out = silu(acc): direct STG + register stats
#pragma unroll
        for(int s = 0; s < 2; s++){
            int rb = wbase + 16*s + gg;
#pragma unroll
            for(int ns = 0; ns < 4; ns++){
                int col = ns*8 + 2*tig;
                float v0 = siluf(acc[s][ns][0]), v1 = siluf(acc[s][ns][1]);
                float v2 = siluf(acc[s][ns][2]), v3 = siluf(acc[s][ns][3]);
                acc[s][ns][0] = v0; acc[s][ns][1] = v1;
                acc[s][ns][2] = v2; acc[s][ns][3] = v3;
                g_h[(size_t)col*BATCH     + rowbase + rb]     = v0;
                g_h[(size_t)(col+1)*BATCH + rowbase + rb]     = v1;
                g_h[(size_t)col*BATCH     + rowbase + rb + 8] = v2;
                g_h[(size_t)(col+1)*BATCH + rowbase + rb + 8] = v3;
            }
        }
        frag_stats(sred, acc, wid, tig, lane);
        __syncthreads();                  // S reads done before next staging
    }
    MMA_STATS_TAIL();
}

// ---------------- head (verbatim) ----------------
__global__ __launch_bounds__(TPB) void k_head(const float* __restrict__ hw,
                                              const float* __restrict__ hb,
                                              float* __restrict__ out){
    __shared__ float wsh[DIMC*INDIM];
    __shared__ float bshf[INDIM];
    __shared__ float tile[TPB*INDIM];
    for(int i = threadIdx.x; i < DIMC*INDIM; i += TPB) wsh[i] = hw[i];
    if(threadIdx.x < INDIM) bshf[threadIdx.x] = hb[threadIdx.x];
    __syncthreads();
#pragma unroll 1
    for(int it = 0; it < RPT; ++it){
        int rowbase = blockIdx.x*TPB + it*STRIDE;
        int row = rowbase + threadIdx.x;
        float acc[INDIM];
#pragma unroll
        for(int i = 0; i < INDIM; i++) acc[i] = bshf[i];
#pragma unroll 4
        for(int c = 0; c < DIMC; c++){
            float h = g_h[(size_t)c*BATCH + row];
#pragma unroll
            for(int i = 0; i < INDIM; i++) acc[i] = fmaf(h, wsh[c*INDIM + i], acc[i]);
        }
        __syncthreads();
#pragma unroll
        for(int i = 0; i < INDIM; i++) tile[threadIdx.x*INDIM + i] = acc[i];
        __syncthreads();
        for(int k = threadIdx.x; k < TPB*INDIM; k += TPB)
            out[(size_t)rowbase*INDIM + k] = tile[k];
    }
}

// ---------------- launch ----------------
extern "C" void kernel_launch(void* const* d_in, const int* in_sizes, int n_in,
                              void* d_out, int out_size) {
    (void)in_sizes; (void)n_in; (void)out_size;
    const float* x      = (const float*)d_in[0];
    const float* stem_w = (const float*)d_in[1];
    const float* stem_b = (const float*)d_in[2];
    const float* fno_wr = (const float*)d_in[3];
    const float* fno_wi = (const float*)d_in[4];
    const float* bn1_g  = (const float*)d_in[5];
    const float* bn1_b  = (const float*)d_in[6];
    const float* lin1_w = (const float*)d_in[7];
    const float* lin1_b = (const float*)d_in[8];
    const float* bn2_g  = (const float*)d_in[9];
    const float* bn2_b  = (const float*)d_in[10];
    const float* lin2_w = (const float*)d_in[11];
    const float* lin2_b = (const float*)d_in[12];
    const float* head_w = (const float*)d_in[13];
    const float* head_b = (const float*)d_in[14];
    float* out = (float*)d_out;

    cudaFuncSetAttribute(k_passA, cudaFuncAttributeMaxDynamicSharedMemorySize, DYNA_B);
    cudaFuncSetAttribute(k_passB, cudaFuncAttributeMaxDynamicSharedMemorySize, DYNB_B);

    k_precompute_A<<<16, 256>>>(fno_wr, fno_wi);
    k_stem<<<GRID_MAIN, TPB>>>(x, stem_w, stem_b);
    for(int l = 0; l < LAYERS; l++){
        k_fin<<<1, 1024>>>(bn1_g, bn1_b, l, 0);      // h stats -> bn1 affine
        k_passA<<<GRID_MAIN, TPB, DYNA_B>>>(lin1_w, lin1_b, l);
        k_fin<<<1, 1024>>>(bn2_g, bn2_b, l, 1);      // r stats -> bn2 affine
        k_passB<<<GRID_MAIN, TPB, DYNB_B>>>(lin1_w, lin1_b, lin2_w, lin2_b, l);
    }
    k_head<<<GRID_MAIN, TPB>>>(head_w, head_b, out);
}

// round 15
// speedup vs baseline: 1.4418x; 1.0226x over previous
#include <cuda_runtime.h>
#include <stdint.h>

#define BATCH   2097152
#define DIMC    32
#define INDIM   10
#define LAYERS  4
#define MB      17
#define EPSV    1e-5f

#define GRID_MAIN 2048
#define TPB       256
#define RPT       4                       // stem/head: 1 row/thread, 4 iters
#define STRIDE    (GRID_MAIN*TPB)

#define TILE_ROWS 256
#define NT        4                       // 2048 CTAs * 256 rows * 4 tiles = BATCH
#define SWP       36                      // per-warp scratch stride (bank-conflict-free)
#define SWSZ      (DIMC*SWP)              // 1152 floats per warp

#define DYNA_B    (256*16)                        // passA: 256 uint4 WF
#define DYNB_B    (768*16 + 8*SWSZ*4)             // passB: 3*256 uint4 WF + 8 warp scratches

typedef unsigned long long u64;

// ---------------- scratch ----------------
__device__ __align__(16) float g_h[(size_t)DIMC * BATCH];   // planar [c][row]
__device__ __align__(16) float g_A[LAYERS * DIMC * DIMC];   // fused Fourier A+I
__device__ float g_partials[GRID_MAIN * 64];
__device__ float g_scale[64];                               // slot0: bn1, slot1: bn2
__device__ float g_shift[64];

// ---------------- helpers ----------------
__device__ __forceinline__ u64 pk2(float a, float b){
    u64 r; asm("mov.b64 %0,{%1,%2};" : "=l"(r) : "f"(a), "f"(b)); return r;
}
__device__ __forceinline__ void up2(u64 v, float &a, float &b){
    asm("mov.b64 {%0,%1},%2;" : "=f"(a), "=f"(b) : "l"(v));
}
__device__ __forceinline__ u64 fma2(u64 a, u64 b, u64 c){
    u64 d; asm("fma.rn.f32x2 %0,%1,%2,%3;" : "=l"(d) : "l"(a), "l"(b), "l"(c)); return d;
}
__device__ __forceinline__ float siluf(float x){
    return x * __fdividef(1.0f, 1.0f + __expf(-x));
}
__device__ __forceinline__ unsigned bf2(float vhi, float vlo){
    unsigned d; asm("cvt.rn.bf16x2.f32 %0,%1,%2;" : "=r"(d) : "f"(vhi), "f"(vlo)); return d;
}
// split pair (v0 -> lo half, v1 -> hi half) into bf16 head + bf16 residual
__device__ __forceinline__ void bfsplit(float v0, float v1, unsigned &hi, unsigned &lo){
    hi = bf2(v1, v0);
    float f0 = __uint_as_float(hi << 16);
    float f1 = __uint_as_float(hi & 0xffff0000u);
    lo = bf2(v1 - f1, v0 - f0);
}

#define MMA16(d, a, b0, b1) \
    asm("mma.sync.aligned.m16n8k16.row.col.f32.bf16.bf16.f32 " \
        "{%0,%1,%2,%3},{%4,%5,%6,%7},{%8,%9},{%0,%1,%2,%3};" \
        : "+f"((d)[0]), "+f"((d)[1]), "+f"((d)[2]), "+f"((d)[3]) \
        : "r"((a)[0]), "r"((a)[1]), "r"((a)[2]), "r"((a)[3]), "r"(b0), "r"(b1))

// ------- Fourier operator precompute: A' = A + I (verbatim) -------
__global__ void k_precompute_A(const float* __restrict__ wr, const float* __restrict__ wi){
    __shared__ double ct[32], st[32];
    int t = threadIdx.x;
    if(t < 32){
        double ang = 6.283185307179586476925286766559 * (double)t / 32.0;
        ct[t] = cos(ang); st[t] = sin(ang);
    }
    __syncthreads();
    int g = blockIdx.x * blockDim.x + t;
    if(g >= LAYERS*DIMC*DIMC) return;
    int l = g >> 10, j = (g >> 5) & 31, d = g & 31;
    const float* WR = wr + l*MB*MB;
    const float* WI = wi + l*MB*MB;
    double v = 0.0;
    for(int k = 0; k < MB; k++){
        double re = 0.0, im = 0.0;
        for(int m = 0; m < MB; m++){
            double c = ct[(m*j)&31], s = st[(m*j)&31];
            double a = (double)WR[m*MB + k], b = (double)WI[m*MB + k];
            re += c*a + s*b;
            im += c*b - s*a;
        }
        double al, be;
        if(k == 0)      { al = 1.0; be = 0.0; }
        else if(k == 16){ al = (d & 1) ? -1.0 : 1.0; be = 0.0; }
        else            { al = 2.0*ct[(k*d)&31]; be = 2.0*st[(k*d)&31]; }
        v += al*re - be*im;
    }
    v *= (1.0/32.0);
    if(j == d) v += 1.0;
    g_A[(l*DIMC + j)*DIMC + d] = (float)v;
}

// ---------------- stem (verbatim) ----------------
__global__ __launch_bounds__(TPB) void k_stem(const float* __restrict__ x,
                                              const float* __restrict__ sw,
                                              const float* __restrict__ sb){
    __shared__ __align__(16) u64 wsh[INDIM*16];
    __shared__ u64 bsh[16];
    __shared__ float tile[8960];
    if(threadIdx.x < INDIM*16){
        int r = threadIdx.x >> 4, q = threadIdx.x & 15;
        wsh[threadIdx.x] = pk2(sw[r*DIMC + 2*q], sw[r*DIMC + 2*q + 1]);
    }
    if(threadIdx.x < 16) bsh[threadIdx.x] = pk2(sb[2*threadIdx.x], sb[2*threadIdx.x+1]);
    int ch = threadIdx.x & 31, mrow = threadIdx.x >> 5;
    float ssum = 0.f, ssq = 0.f;
    __syncthreads();
#pragma unroll 1
    for(int it = 0; it < RPT; ++it){
        int rowbase = blockIdx.x*TPB + it*STRIDE;
        int row = rowbase + threadIdx.x;
        __syncthreads();
        for(int k = threadIdx.x; k < TPB*INDIM; k += TPB)
            tile[k] = x[(size_t)rowbase*INDIM + k];
        __syncthreads();
        float xv[INDIM];
#pragma unroll
        for(int i = 0; i < INDIM; i++) xv[i] = tile[threadIdx.x*INDIM + i];
        __syncthreads();
        u64 acc[16];
#pragma unroll
        for(int q = 0; q < 16; q++) acc[q] = bsh[q];
#pragma unroll
        for(int i = 0; i < INDIM; i++){
            u64 xp = pk2(xv[i], xv[i]);
            const ulonglong2* w2 = (const ulonglong2*)(wsh + i*16);
#pragma unroll
            for(int q = 0; q < 8; q++){
                ulonglong2 ww = w2[q];
                acc[2*q]   = fma2(xp, ww.x, acc[2*q]);
                acc[2*q+1] = fma2(xp, ww.y, acc[2*q+1]);
            }
        }
        float* trow = tile + threadIdx.x*35;
#pragma unroll
        for(int q = 0; q < 16; q++){
            float a, b; up2(acc[q], a, b);
            g_h[(size_t)(2*q)*BATCH + row]   = a;
            g_h[(size_t)(2*q+1)*BATCH + row] = b;
            trow[2*q] = a; trow[2*q+1] = b;
        }
        __syncthreads();
#pragma unroll
        for(int j = 0; j < 32; j++){
            float v = tile[(mrow*32 + j)*35 + ch];
            ssum += v; ssq += v*v;
        }
    }
    __syncthreads();
    tile[mrow*64 + ch]      = ssum;
    tile[mrow*64 + 32 + ch] = ssq;
    __syncthreads();
    if(threadIdx.x < 64){
        float v = 0.f;
#pragma unroll
        for(int m = 0; m < 8; m++) v += tile[m*64 + threadIdx.x];
        g_partials[blockIdx.x*64 + threadIdx.x] = v;
    }
}

// ---------------- finalize (verbatim) ----------------
__global__ void k_fin(const float* __restrict__ gamma, const float* __restrict__ beta,
                      int layer, int slot){
    __shared__ float red[1024];
    __shared__ float tot[64];
    int t = threadIdx.x;
    int col = t & 63, part = t >> 6;
    const float* p = g_partials + (size_t)part*128*64 + col;
    float v = 0.f;
#pragma unroll 8
    for(int i = 0; i < 128; i++) v += p[(size_t)i*64];
    red[part*64 + col] = v;
    __syncthreads();
    if(t < 64){
        float s = 0.f;
#pragma unroll
        for(int q = 0; q < 16; q++) s += red[q*64 + t];
        tot[t] = s;
    }
    __syncthreads();
    if(t < DIMC){
        float mean = tot[t]      * (1.0f/(float)BATCH);
        float ex2  = tot[32 + t] * (1.0f/(float)BATCH);
        float var  = fmaxf(ex2 - mean*mean, 0.0f);
        float sc   = gamma[layer*DIMC + t] * rsqrtf(var + EPSV);
        g_scale[slot*32 + t] = sc;
        g_shift[slot*32 + t] = beta[layer*DIMC + t] - mean*sc;
    }
}

// ---- MMA-pass pieces (bf16 2-part split) ----

__device__ __forceinline__ void prep_wf(uint4* WF, const float* __restrict__ W){
    for(int e = threadIdx.x; e < 256; e += TPB){
        int lane = e & 31, ns = (e >> 5) & 3, ks = e >> 7;
        int tig = lane & 3, gg = lane >> 2;
        int k0 = ks*16 + 2*tig, n = ns*8 + gg;
        float b0 = W[k0*32 + n],     b1 = W[(k0+1)*32 + n];
        float b2 = W[(k0+8)*32 + n], b3 = W[(k0+9)*32 + n];
        unsigned h01, l01, h23, l23;
        bfsplit(b0, b1, h01, l01);
        bfsplit(b2, b3, h23, l23);
        WF[(ks*4 + ns)*32 + lane] = make_uint4(h01, h23, l01, l23);
    }
}

#define DO_MMAS()                                                               \
    _Pragma("unroll")                                                           \
    for(int ns = 0; ns < 4; ns++){                                              \
        uint4 w = WF[(ks*4 + ns)*32 + lane];                                    \
        _Pragma("unroll")                                                       \
        for(int s = 0; s < 2; s++){                                             \
            MMA16(acc[s][ns], ah[s], w.x, w.y);                                 \
            MMA16(acc[s][ns], ah[s], w.z, w.w);                                 \
            MMA16(acc[s][ns], al[s], w.x, w.y);                                 \
        }                                                                       \
    }

// chain from gmem with fused bn+silu on loaded values
__device__ __forceinline__ void chain_gact(float acc[2][4][4], const float* __restrict__ g,
                                           int rowbase, const uint4* WF,
                                           int wbase, int tig, int gg, int lane,
                                           const float* sc, const float* sh){
#pragma unroll
    for(int ks = 0; ks < 2; ks++){
        unsigned ah[2][4], al[2][4];
        int k0 = ks*16 + 2*tig;
        float a0 = sc[k0],   s0 = sh[k0];
        float a1 = sc[k0+1], s1v = sh[k0+1];
        float a8 = sc[k0+8], s8 = sh[k0+8];
        float a9 = sc[k0+9], s9 = sh[k0+9];
#pragma unroll
        for(int s = 0; s < 2; s++){
            const float* base = g + (size_t)rowbase + wbase + 16*s + gg;
            float v00 = siluf(fmaf(__ldg(base + (size_t)(k0  )*BATCH),     a0, s0));
            float v01 = siluf(fmaf(__ldg(base + (size_t)(k0+1)*BATCH),     a1, s1v));
            float u00 = siluf(fmaf(__ldg(base + (size_t)(k0  )*BATCH + 8), a0, s0));
            float u01 = siluf(fmaf(__ldg(base + (size_t)(k0+1)*BATCH + 8), a1, s1v));
            float v08 = siluf(fmaf(__ldg(base + (size_t)(k0+8)*BATCH),     a8, s8));
            float v09 = siluf(fmaf(__ldg(base + (size_t)(k0+9)*BATCH),     a9, s9));
            float u08 = siluf(fmaf(__ldg(base + (size_t)(k0+8)*BATCH + 8), a8, s8));
            float u09 = siluf(fmaf(__ldg(base + (size_t)(k0+9)*BATCH + 8), a9, s9));
            bfsplit(v00, v01, ah[s][0], al[s][0]);
            bfsplit(u00, u01, ah[s][1], al[s][1]);
            bfsplit(v08, v09, ah[s][2], al[s][2]);
            bfsplit(u08, u09, ah[s][3], al[s][3]);
        }
        DO_MMAS();
    }
}

// chain from gmem, raw values
__device__ __forceinline__ void chain_g(float acc[2][4][4], const float* __restrict__ g,
                                        int rowbase, const uint4* WF,
                                        int wbase, int tig, int gg, int lane){
#pragma unroll
    for(int ks = 0; ks < 2; ks++){
        unsigned ah[2][4], al[2][4];
        int k0 = ks*16 + 2*tig;
#pragma unroll
        for(int s = 0; s < 2; s++){
            const float* base = g + (size_t)rowbase + wbase + 16*s + gg;
            float v00 = __ldg(base + (size_t)(k0  )*BATCH);
            float v01 = __ldg(base + (size_t)(k0+1)*BATCH);
            float u00 = __ldg(base + (size_t)(k0  )*BATCH + 8);
            float u01 = __ldg(base + (size_t)(k0+1)*BATCH + 8);
            float v08 = __ldg(base + (size_t)(k0+8)*BATCH);
            float v09 = __ldg(base + (size_t)(k0+9)*BATCH);
            float u08 = __ldg(base + (size_t)(k0+8)*BATCH + 8);
            float u09 = __ldg(base + (size_t)(k0+9)*BATCH + 8);
            bfsplit(v00, v01, ah[s][0], al[s][0]);
            bfsplit(u00, u01, ah[s][1], al[s][1]);
            bfsplit(v08, v09, ah[s][2], al[s][2]);
            bfsplit(u08, u09, ah[s][3], al[s][3]);
        }
        DO_MMAS();
    }
}

// chain from warp-private smem scratch (32 local rows, stride SWP)
__device__ __forceinline__ void chain_sw(float acc[2][4][4], const float* SW,
                                         const uint4* WF, int tig, int gg, int lane){
#pragma unroll
    for(int ks = 0; ks < 2; ks++){
        unsigned ah[2][4], al[2][4];
        int k0 = ks*16 + 2*tig;
#pragma unroll
        for(int s = 0; s < 2; s++){
            int rb = 16*s + gg;
            float v00 = SW[(k0  )*SWP + rb],     v01 = SW[(k0+1)*SWP + rb];
            float u00 = SW[(k0  )*SWP + rb + 8], u01 = SW[(k0+1)*SWP + rb + 8];
            float v08 = SW[(k0+8)*SWP + rb],     v09 = SW[(k0+9)*SWP + rb];
            float u08 = SW[(k0+8)*SWP + rb + 8], u09 = SW[(k0+9)*SWP + rb + 8];
            bfsplit(v00, v01, ah[s][0], al[s][0]);
            bfsplit(u00, u01, ah[s][1], al[s][1]);
            bfsplit(v08, v09, ah[s][2], al[s][2]);
            bfsplit(u08, u09, ah[s][3], al[s][3]);
        }
        DO_MMAS();
    }
}

__device__ __forceinline__ void add_bias(float acc[2][4][4], const float* bb, int tig){
#pragma unroll
    for(int ns = 0; ns < 4; ns++){
        float b0 = bb[ns*8 + 2*tig], b1 = bb[ns*8 + 2*tig + 1];
#pragma unroll
        for(int s = 0; s < 2; s++){
            acc[s][ns][0] += b0; acc[s][ns][1] += b1;
            acc[s][ns][2] += b0; acc[s][ns][3] += b1;
        }
    }
}

// register stats: butterfly over gg lanes, lanes 0..3 accumulate into sred[wid]
__device__ __forceinline__ void frag_stats(float* sred, float acc[2][4][4],
                                           int wid, int tig, int lane){
#pragma unroll
    for(int ns = 0; ns < 4; ns++){
        float s0 = acc[0][ns][0] + acc[0][ns][2] + acc[1][ns][0] + acc[1][ns][2];
        float s1 = acc[0][ns][1] + acc[0][ns][3] + acc[1][ns][1] + acc[1][ns][3];
        float q0 = acc[0][ns][0]*acc[0][ns][0] + acc[0][ns][2]*acc[0][ns][2]
                 + acc[1][ns][0]*acc[1][ns][0] + acc[1][ns][2]*acc[1][ns][2];
        float q1 = acc[0][ns][1]*acc[0][ns][1] + acc[0][ns][3]*acc[0][ns][3]
                 + acc[1][ns][1]*acc[1][ns][1] + acc[1][ns][3]*acc[1][ns][3];
#pragma unroll
        for(int m = 4; m < 32; m <<= 1){
            s0 += __shfl_xor_sync(0xffffffffu, s0, m);
            s1 += __shfl_xor_sync(0xffffffffu, s1, m);
            q0 += __shfl_xor_sync(0xffffffffu, q0, m);
            q1 += __shfl_xor_sync(0xffffffffu, q1, m);
        }
        if((lane & 28) == 0){
            int col = ns*8 + 2*tig;
            sred[wid*64 + col]          += s0;
            sred[wid*64 + col + 1]      += s1;
            sred[wid*64 + 32 + col]     += q0;
            sred[wid*64 + 32 + col + 1] += q1;
        }
    }
}

#define MMA_STATS_TAIL() do{                                                   \
    __syncthreads();                                                           \
    if(threadIdx.x < 64){                                                      \
        float v = 0.f;                                                         \
        _Pragma("unroll")                                                      \
        for(int m = 0; m < 8; m++) v += sred[m*64 + threadIdx.x];              \
        g_partials[blockIdx.x*64 + threadIdx.x] = v;                           \
    }                                                                          \
}while(0)

// ------- pass A: stats( silu(bn1(h))@W1 + b1 ) — plane-free, sync-free loop -------
__global__ __launch_bounds__(TPB, 3) void k_passA(const float* __restrict__ w1,
                                                  const float* __restrict__ b1, int layer){
    extern __shared__ __align__(16) float dyn[];
    uint4* WF = (uint4*)dyn;
    __shared__ float sc1[32], sh1[32], bb1[32];
    __shared__ float sred[512];
    prep_wf(WF, w1 + layer*1024);
    if(threadIdx.x < 32){
        sc1[threadIdx.x] = g_scale[threadIdx.x];
        sh1[threadIdx.x] = g_shift[threadIdx.x];
        bb1[threadIdx.x] = b1[layer*32 + threadIdx.x];
    }
    for(int i = threadIdx.x; i < 512; i += TPB) sred[i] = 0.f;
    int wid = threadIdx.x >> 5, lane = threadIdx.x & 31;
    int tig = lane & 3, gg = lane >> 2;
    int wbase = wid*32;
    __syncthreads();
#pragma unroll 1
    for(int t = 0; t < NT; ++t){
        int rowbase = blockIdx.x*(NT*TILE_ROWS) + t*TILE_ROWS;
        float acc[2][4][4];
#pragma unroll
        for(int s = 0; s < 2; s++)
#pragma unroll
            for(int n = 0; n < 4; n++)
#pragma unroll
                for(int q = 0; q < 4; q++) acc[s][n][q] = 0.f;
        chain_gact(acc, g_h, rowbase, WF, wbase, tig, gg, lane, sc1, sh1);
        add_bias(acc, bb1, tig);
        frag_stats(sred, acc, wid, tig, lane);
    }
    MMA_STATS_TAIL();
}

// ------- pass B: h' = silu( h@(A+I) + silu(bn2(r))@W2 + b2 ), warp-private scratch -------
__global__ __launch_bounds__(TPB, 3) void k_passB(const float* __restrict__ w1,
                                                  const float* __restrict__ b1,
                                                  const float* __restrict__ w2,
                                                  const float* __restrict__ b2, int layer){
    extern __shared__ __align__(16) float dyn[];
    uint4* WF   = (uint4*)dyn;                    // [0]=W1 [256]=W2 [512]=A'
    float* SWbase = dyn + 768*4;                  // 8 warp scratches, SWSZ floats each
    __shared__ float sc1[32], sh1[32], sc2[32], sh2[32], bb1[32], bb2[32];
    __shared__ float sred[512];
    prep_wf(WF,        w1 + layer*1024);
    prep_wf(WF + 256,  w2 + layer*1024);
    prep_wf(WF + 512,  g_A + layer*1024);
    if(threadIdx.x < 32){
        sc1[threadIdx.x] = g_scale[threadIdx.x];
        sh1[threadIdx.x] = g_shift[threadIdx.x];
        sc2[threadIdx.x] = g_scale[32 + threadIdx.x];
        sh2[threadIdx.x] = g_shift[32 + threadIdx.x];
        bb1[threadIdx.x] = b1[layer*32 + threadIdx.x];
        bb2[threadIdx.x] = b2[layer*32 + threadIdx.x];
    }
    for(int i = threadIdx.x; i < 512; i += TPB) sred[i] = 0.f;
    int wid = threadIdx.x >> 5, lane = threadIdx.x & 31;
    int tig = lane & 3, gg = lane >> 2;
    int wbase = wid*32;
    float* SW = SWbase + wid*SWSZ;
    __syncthreads();
#pragma unroll 1
    for(int t = 0; t < NT; ++t){
        int rowbase = blockIdx.x*(NT*TILE_ROWS) + t*TILE_ROWS;
        float acc[2][4][4];
        // chain 1: r = silu(bn1(h)) @ W1 + b1  (gmem, fused act)
#pragma unroll
        for(int s = 0; s < 2; s++)
#pragma unroll
            for(int n = 0; n < 4; n++)
#pragma unroll
                for(int q = 0; q < 4; q++) acc[s][n][q] = 0.f;
        chain_gact(acc, g_h, rowbase, WF, wbase, tig, gg, lane, sc1, sh1);
        add_bias(acc, bb1, tig);
        // s2 = silu(bn2(r)) -> warp scratch (fragment layout, conflict-free)
#pragma unroll
        for(int s = 0; s < 2; s++){
            int rb = 16*s + gg;
#pragma unroll
            for(int ns = 0; ns < 4; ns++){
                int col = ns*8 + 2*tig;
                float a = sc2[col],    b  = sh2[col];
                float a1 = sc2[col+1], b1v = sh2[col+1];
                SW[col*SWP + rb]         = siluf(fmaf(acc[s][ns][0], a,  b));
                SW[(col+1)*SWP + rb]     = siluf(fmaf(acc[s][ns][1], a1, b1v));
                SW[col*SWP + rb + 8]     = siluf(fmaf(acc[s][ns][2], a,  b));
                SW[(col+1)*SWP + rb + 8] = siluf(fmaf(acc[s][ns][3], a1, b1v));
            }
        }
        __syncwarp();
        // chain 2: acc = s2 @ W2 + b2 ; chain 3: acc += h @ (A+I) (gmem re-read)
#pragma unroll
        for(int s = 0; s < 2; s++)
#pragma unroll
            for(int n = 0; n < 4; n++)
#pragma unroll
                for(int q = 0; q < 4; q++) acc[s][n][q] = 0.f;
        chain_sw(acc, SW, WF + 256, tig, gg, lane);
        add_bias(acc, bb2, tig);
        chain_g(acc, g_h, rowbase, WF + 512, wbase, tig, gg, lane);
        // out = silu(acc): direct STG + register stats
#pragma unroll
        for(int s = 0; s < 2; s++){
            int rb = wbase + 16*s + gg;
#pragma unroll
            for(int ns = 0; ns < 4; ns++){
                int col = ns*8 + 2*tig;
                float v0 = siluf(acc[s][ns][0]), v1 = siluf(acc[s][ns][1]);
                float v2 = siluf(acc[s][ns][2]), v3 = siluf(acc[s][ns][3]);
                acc[s][ns][0] = v0; acc[s][ns][1] = v1;
                acc[s][ns][2] = v2; acc[s][ns][3] = v3;
                g_h[(size_t)col*BATCH     + rowbase + rb]     = v0;
                g_h[(size_t)(col+1)*BATCH + rowbase + rb]     = v1;
                g_h[(size_t)col*BATCH     + rowbase + rb + 8] = v2;
                g_h[(size_t)(col+1)*BATCH + rowbase + rb + 8] = v3;
            }
        }
        frag_stats(sred, acc, wid, tig, lane);
        __syncwarp();                     // SW reads done before next tile overwrite
    }
    MMA_STATS_TAIL();
}

// ---------------- head (verbatim) ----------------
__global__ __launch_bounds__(TPB) void k_head(const float* __restrict__ hw,
                                              const float* __restrict__ hb,
                                              float* __restrict__ out){
    __shared__ float wsh[DIMC*INDIM];
    __shared__ float bshf[INDIM];
    __shared__ float tile[TPB*INDIM];
    for(int i = threadIdx.x; i < DIMC*INDIM; i += TPB) wsh[i] = hw[i];
    if(threadIdx.x < INDIM) bshf[threadIdx.x] = hb[threadIdx.x];
    __syncthreads();
#pragma unroll 1
    for(int it = 0; it < RPT; ++it){
        int rowbase = blockIdx.x*TPB + it*STRIDE;
        int row = rowbase + threadIdx.x;
        float acc[INDIM];
#pragma unroll
        for(int i = 0; i < INDIM; i++) acc[i] = bshf[i];
#pragma unroll 4
        for(int c = 0; c < DIMC; c++){
            float h = g_h[(size_t)c*BATCH + row];
#pragma unroll
            for(int i = 0; i < INDIM; i++) acc[i] = fmaf(h, wsh[c*INDIM + i], acc[i]);
        }
        __syncthreads();
#pragma unroll
        for(int i = 0; i < INDIM; i++) tile[threadIdx.x*INDIM + i] = acc[i];
        __syncthreads();
        for(int k = threadIdx.x; k < TPB*INDIM; k += TPB)
            out[(size_t)rowbase*INDIM + k] = tile[k];
    }
}

// ---------------- launch ----------------
extern "C" void kernel_launch(void* const* d_in, const int* in_sizes, int n_in,
                              void* d_out, int out_size) {
    (void)in_sizes; (void)n_in; (void)out_size;
    const float* x      = (const float*)d_in[0];
    const float* stem_w = (const float*)d_in[1];
    const float* stem_b = (const float*)d_in[2];
    const float* fno_wr = (const float*)d_in[3];
    const float* fno_wi = (const float*)d_in[4];
    const float* bn1_g  = (const float*)d_in[5];
    const float* bn1_b  = (const float*)d_in[6];
    const float* lin1_w = (const float*)d_in[7];
    const float* lin1_b = (const float*)d_in[8];
    const float* bn2_g  = (const float*)d_in[9];
    const float* bn2_b  = (const float*)d_in[10];
    const float* lin2_w = (const float*)d_in[11];
    const float* lin2_b = (const float*)d_in[12];
    const float* head_w = (const float*)d_in[13];
    const float* head_b = (const float*)d_in[14];
    float* out = (float*)d_out;

    cudaFuncSetAttribute(k_passA, cudaFuncAttributeMaxDynamicSharedMemorySize, DYNA_B);
    cudaFuncSetAttribute(k_passB, cudaFuncAttributeMaxDynamicSharedMemorySize, DYNB_B);

    k_precompute_A<<<16, 256>>>(fno_wr, fno_wi);
    k_stem<<<GRID_MAIN, TPB>>>(x, stem_w, stem_b);
    for(int l = 0; l < LAYERS; l++){
        k_fin<<<1, 1024>>>(bn1_g, bn1_b, l, 0);      // h stats -> bn1 affine
        k_passA<<<GRID_MAIN, TPB, DYNA_B>>>(lin1_w, lin1_b, l);
        k_fin<<<1, 1024>>>(bn2_g, bn2_b, l, 1);      // r stats -> bn2 affine
        k_passB<<<GRID_MAIN, TPB, DYNB_B>>>(lin1_w, lin1_b, lin2_w, lin2_b, l);
    }
    k_head<<<GRID_MAIN, TPB>>>(head_w, head_b, out);
}

// round 16
// speedup vs baseline: 1.5325x; 1.0629x over previous
#include <cuda_runtime.h>
#include <stdint.h>

#define BATCH   2097152
#define DIMC    32
#define INDIM   10
#define LAYERS  4
#define MB      17
#define EPSV    1e-5f

#define GRID_MAIN 2048
#define TPB       256
#define RPT       4                       // stem/head: 1 row/thread, 4 iters
#define STRIDE    (GRID_MAIN*TPB)

#define TILE_ROWS 256
#define NT        4                       // 2048 CTAs * 256 rows * 4 tiles = BATCH
#define SWP       36                      // per-warp scratch stride (bank-conflict-free)
#define SWSZ      (DIMC*SWP)              // 1152 floats per warp

#define DYNA_B    (256*16)                        // passA: 256 uint4 WF
#define DYNB_B    (768*16 + 8*SWSZ*4)             // passB: 3*256 uint4 WF + 8 warp scratches

typedef unsigned long long u64;

// ---------------- scratch ----------------
__device__ __align__(16) float g_h[(size_t)DIMC * BATCH];   // planar [c][row]
__device__ __align__(16) float g_A[LAYERS * DIMC * DIMC];   // fused Fourier A+I
__device__ float g_partials[GRID_MAIN * 64];
__device__ float g_scale[64];                               // slot0: bn1, slot1: bn2
__device__ float g_shift[64];

// ---------------- helpers ----------------
__device__ __forceinline__ u64 pk2(float a, float b){
    u64 r; asm("mov.b64 %0,{%1,%2};" : "=l"(r) : "f"(a), "f"(b)); return r;
}
__device__ __forceinline__ void up2(u64 v, float &a, float &b){
    asm("mov.b64 {%0,%1},%2;" : "=f"(a), "=f"(b) : "l"(v));
}
__device__ __forceinline__ u64 fma2(u64 a, u64 b, u64 c){
    u64 d; asm("fma.rn.f32x2 %0,%1,%2,%3;" : "=l"(d) : "l"(a), "l"(b), "l"(c)); return d;
}
__device__ __forceinline__ float siluf(float x){
    return x * __fdividef(1.0f, 1.0f + __expf(-x));
}
__device__ __forceinline__ unsigned bf2(float vhi, float vlo){
    unsigned d; asm("cvt.rn.bf16x2.f32 %0,%1,%2;" : "=r"(d) : "f"(vhi), "f"(vlo)); return d;
}
// split pair (v0 -> lo half, v1 -> hi half) into bf16 head + bf16 residual
__device__ __forceinline__ void bfsplit(float v0, float v1, unsigned &hi, unsigned &lo){
    hi = bf2(v1, v0);
    float f0 = __uint_as_float(hi << 16);
    float f1 = __uint_as_float(hi & 0xffff0000u);
    lo = bf2(v1 - f1, v0 - f0);
}

#define MMA16(d, a, b0, b1) \
    asm("mma.sync.aligned.m16n8k16.row.col.f32.bf16.bf16.f32 " \
        "{%0,%1,%2,%3},{%4,%5,%6,%7},{%8,%9},{%0,%1,%2,%3};" \
        : "+f"((d)[0]), "+f"((d)[1]), "+f"((d)[2]), "+f"((d)[3]) \
        : "r"((a)[0]), "r"((a)[1]), "r"((a)[2]), "r"((a)[3]), "r"(b0), "r"(b1))

// ------- Fourier operator precompute: A' = A + I (verbatim) -------
__global__ void k_precompute_A(const float* __restrict__ wr, const float* __restrict__ wi){
    __shared__ double ct[32], st[32];
    int t = threadIdx.x;
    if(t < 32){
        double ang = 6.283185307179586476925286766559 * (double)t / 32.0;
        ct[t] = cos(ang); st[t] = sin(ang);
    }
    __syncthreads();
    int g = blockIdx.x * blockDim.x + t;
    if(g >= LAYERS*DIMC*DIMC) return;
    int l = g >> 10, j = (g >> 5) & 31, d = g & 31;
    const float* WR = wr + l*MB*MB;
    const float* WI = wi + l*MB*MB;
    double v = 0.0;
    for(int k = 0; k < MB; k++){
        double re = 0.0, im = 0.0;
        for(int m = 0; m < MB; m++){
            double c = ct[(m*j)&31], s = st[(m*j)&31];
            double a = (double)WR[m*MB + k], b = (double)WI[m*MB + k];
            re += c*a + s*b;
            im += c*b - s*a;
        }
        double al, be;
        if(k == 0)      { al = 1.0; be = 0.0; }
        else if(k == 16){ al = (d & 1) ? -1.0 : 1.0; be = 0.0; }
        else            { al = 2.0*ct[(k*d)&31]; be = 2.0*st[(k*d)&31]; }
        v += al*re - be*im;
    }
    v *= (1.0/32.0);
    if(j == d) v += 1.0;
    g_A[(l*DIMC + j)*DIMC + d] = (float)v;
}

// ---------------- stem (verbatim) ----------------
__global__ __launch_bounds__(TPB) void k_stem(const float* __restrict__ x,
                                              const float* __restrict__ sw,
                                              const float* __restrict__ sb){
    __shared__ __align__(16) u64 wsh[INDIM*16];
    __shared__ u64 bsh[16];
    __shared__ float tile[8960];
    if(threadIdx.x < INDIM*16){
        int r = threadIdx.x >> 4, q = threadIdx.x & 15;
        wsh[threadIdx.x] = pk2(sw[r*DIMC + 2*q], sw[r*DIMC + 2*q + 1]);
    }
    if(threadIdx.x < 16) bsh[threadIdx.x] = pk2(sb[2*threadIdx.x], sb[2*threadIdx.x+1]);
    int ch = threadIdx.x & 31, mrow = threadIdx.x >> 5;
    float ssum = 0.f, ssq = 0.f;
    __syncthreads();
#pragma unroll 1
    for(int it = 0; it < RPT; ++it){
        int rowbase = blockIdx.x*TPB + it*STRIDE;
        int row = rowbase + threadIdx.x;
        __syncthreads();
        for(int k = threadIdx.x; k < TPB*INDIM; k += TPB)
            tile[k] = x[(size_t)rowbase*INDIM + k];
        __syncthreads();
        float xv[INDIM];
#pragma unroll
        for(int i = 0; i < INDIM; i++) xv[i] = tile[threadIdx.x*INDIM + i];
        __syncthreads();
        u64 acc[16];
#pragma unroll
        for(int q = 0; q < 16; q++) acc[q] = bsh[q];
#pragma unroll
        for(int i = 0; i < INDIM; i++){
            u64 xp = pk2(xv[i], xv[i]);
            const ulonglong2* w2 = (const ulonglong2*)(wsh + i*16);
#pragma unroll
            for(int q = 0; q < 8; q++){
                ulonglong2 ww = w2[q];
                acc[2*q]   = fma2(xp, ww.x, acc[2*q]);
                acc[2*q+1] = fma2(xp, ww.y, acc[2*q+1]);
            }
        }
        float* trow = tile + threadIdx.x*35;
#pragma unroll
        for(int q = 0; q < 16; q++){
            float a, b; up2(acc[q], a, b);
            g_h[(size_t)(2*q)*BATCH + row]   = a;
            g_h[(size_t)(2*q+1)*BATCH + row] = b;
            trow[2*q] = a; trow[2*q+1] = b;
        }
        __syncthreads();
#pragma unroll
        for(int j = 0; j < 32; j++){
            float v = tile[(mrow*32 + j)*35 + ch];
            ssum += v; ssq += v*v;
        }
    }
    __syncthreads();
    tile[mrow*64 + ch]      = ssum;
    tile[mrow*64 + 32 + ch] = ssq;
    __syncthreads();
    if(threadIdx.x < 64){
        float v = 0.f;
#pragma unroll
        for(int m = 0; m < 8; m++) v += tile[m*64 + threadIdx.x];
        g_partials[blockIdx.x*64 + threadIdx.x] = v;
    }
}

// ---------------- finalize (verbatim) ----------------
__global__ void k_fin(const float* __restrict__ gamma, const float* __restrict__ beta,
                      int layer, int slot){
    __shared__ float red[1024];
    __shared__ float tot[64];
    int t = threadIdx.x;
    int col = t & 63, part = t >> 6;
    const float* p = g_partials + (size_t)part*128*64 + col;
    float v = 0.f;
#pragma unroll 8
    for(int i = 0; i < 128; i++) v += p[(size_t)i*64];
    red[part*64 + col] = v;
    __syncthreads();
    if(t < 64){
        float s = 0.f;
#pragma unroll
        for(int q = 0; q < 16; q++) s += red[q*64 + t];
        tot[t] = s;
    }
    __syncthreads();
    if(t < DIMC){
        float mean = tot[t]      * (1.0f/(float)BATCH);
        float ex2  = tot[32 + t] * (1.0f/(float)BATCH);
        float var  = fmaxf(ex2 - mean*mean, 0.0f);
        float sc   = gamma[layer*DIMC + t] * rsqrtf(var + EPSV);
        g_scale[slot*32 + t] = sc;
        g_shift[slot*32 + t] = beta[layer*DIMC + t] - mean*sc;
    }
}

// ---- MMA-pass pieces (bf16 2-part split) ----

__device__ __forceinline__ void prep_wf(uint4* WF, const float* __restrict__ W){
    for(int e = threadIdx.x; e < 256; e += TPB){
        int lane = e & 31, ns = (e >> 5) & 3, ks = e >> 7;
        int tig = lane & 3, gg = lane >> 2;
        int k0 = ks*16 + 2*tig, n = ns*8 + gg;
        float b0 = W[k0*32 + n],     b1 = W[(k0+1)*32 + n];
        float b2 = W[(k0+8)*32 + n], b3 = W[(k0+9)*32 + n];
        unsigned h01, l01, h23, l23;
        bfsplit(b0, b1, h01, l01);
        bfsplit(b2, b3, h23, l23);
        WF[(ks*4 + ns)*32 + lane] = make_uint4(h01, h23, l01, l23);
    }
}

#define DO_MMAS_1(ACC, AH, AL)                                                  \
    _Pragma("unroll")                                                           \
    for(int ns = 0; ns < 4; ns++){                                              \
        uint4 w = WF[(ks*4 + ns)*32 + lane];                                    \
        _Pragma("unroll")                                                       \
        for(int s = 0; s < 2; s++){                                             \
            MMA16((ACC)[s][ns], (AH)[s], w.x, w.y);                             \
            MMA16((ACC)[s][ns], (AH)[s], w.z, w.w);                             \
            MMA16((ACC)[s][ns], (AL)[s], w.x, w.y);                             \
        }                                                                       \
    }

// chain from gmem with fused bn+silu
__device__ __forceinline__ void chain_gact(float acc[2][4][4], const float* __restrict__ g,
                                           int rowbase, const uint4* WF,
                                           int wbase, int tig, int gg, int lane,
                                           const float* sc, const float* sh){
#pragma unroll
    for(int ks = 0; ks < 2; ks++){
        unsigned ah[2][4], al[2][4];
        int k0 = ks*16 + 2*tig;
        float a0 = sc[k0],   s0 = sh[k0];
        float a1 = sc[k0+1], s1v = sh[k0+1];
        float a8 = sc[k0+8], s8 = sh[k0+8];
        float a9 = sc[k0+9], s9 = sh[k0+9];
#pragma unroll
        for(int s = 0; s < 2; s++){
            const float* base = g + (size_t)rowbase + wbase + 16*s + gg;
            float v00 = siluf(fmaf(__ldg(base + (size_t)(k0  )*BATCH),     a0, s0));
            float v01 = siluf(fmaf(__ldg(base + (size_t)(k0+1)*BATCH),     a1, s1v));
            float u00 = siluf(fmaf(__ldg(base + (size_t)(k0  )*BATCH + 8), a0, s0));
            float u01 = siluf(fmaf(__ldg(base + (size_t)(k0+1)*BATCH + 8), a1, s1v));
            float v08 = siluf(fmaf(__ldg(base + (size_t)(k0+8)*BATCH),     a8, s8));
            float v09 = siluf(fmaf(__ldg(base + (size_t)(k0+9)*BATCH),     a9, s9));
            float u08 = siluf(fmaf(__ldg(base + (size_t)(k0+8)*BATCH + 8), a8, s8));
            float u09 = siluf(fmaf(__ldg(base + (size_t)(k0+9)*BATCH + 8), a9, s9));
            bfsplit(v00, v01, ah[s][0], al[s][0]);
            bfsplit(u00, u01, ah[s][1], al[s][1]);
            bfsplit(v08, v09, ah[s][2], al[s][2]);
            bfsplit(u08, u09, ah[s][3], al[s][3]);
        }
        DO_MMAS_1(acc, ah, al);
    }
}

// fused passB chains: one raw-h load feeds accB += h@A' (WFA) and accA += silu(bn1 h)@W1 (WF1)
__device__ __forceinline__ void chain_fused(float accA[2][4][4], float accB[2][4][4],
                                            const float* __restrict__ g, int rowbase,
                                            const uint4* WF1, const uint4* WFA,
                                            int wbase, int tig, int gg, int lane,
                                            const float* sc, const float* sh){
#pragma unroll
    for(int ks = 0; ks < 2; ks++){
        unsigned ahR[2][4], alR[2][4], ahA[2][4], alA[2][4];
        int k0 = ks*16 + 2*tig;
        float a0 = sc[k0],   s0 = sh[k0];
        float a1 = sc[k0+1], s1v = sh[k0+1];
        float a8 = sc[k0+8], s8 = sh[k0+8];
        float a9 = sc[k0+9], s9 = sh[k0+9];
#pragma unroll
        for(int s = 0; s < 2; s++){
            const float* base = g + (size_t)rowbase + wbase + 16*s + gg;
            float v00 = __ldg(base + (size_t)(k0  )*BATCH);
            float v01 = __ldg(base + (size_t)(k0+1)*BATCH);
            float u00 = __ldg(base + (size_t)(k0  )*BATCH + 8);
            float u01 = __ldg(base + (size_t)(k0+1)*BATCH + 8);
            float v08 = __ldg(base + (size_t)(k0+8)*BATCH);
            float v09 = __ldg(base + (size_t)(k0+9)*BATCH);
            float u08 = __ldg(base + (size_t)(k0+8)*BATCH + 8);
            float u09 = __ldg(base + (size_t)(k0+9)*BATCH + 8);
            bfsplit(v00, v01, ahR[s][0], alR[s][0]);
            bfsplit(u00, u01, ahR[s][1], alR[s][1]);
            bfsplit(v08, v09, ahR[s][2], alR[s][2]);
            bfsplit(u08, u09, ahR[s][3], alR[s][3]);
            bfsplit(siluf(fmaf(v00, a0, s0)),  siluf(fmaf(v01, a1, s1v)), ahA[s][0], alA[s][0]);
            bfsplit(siluf(fmaf(u00, a0, s0)),  siluf(fmaf(u01, a1, s1v)), ahA[s][1], alA[s][1]);
            bfsplit(siluf(fmaf(v08, a8, s8)),  siluf(fmaf(v09, a9, s9)),  ahA[s][2], alA[s][2]);
            bfsplit(siluf(fmaf(u08, a8, s8)),  siluf(fmaf(u09, a9, s9)),  ahA[s][3], alA[s][3]);
        }
#pragma unroll
        for(int ns = 0; ns < 4; ns++){
            uint4 wA = WFA[(ks*4 + ns)*32 + lane];
            uint4 w1 = WF1[(ks*4 + ns)*32 + lane];
#pragma unroll
            for(int s = 0; s < 2; s++){
                MMA16(accB[s][ns], ahR[s], wA.x, wA.y);
                MMA16(accB[s][ns], ahR[s], wA.z, wA.w);
                MMA16(accB[s][ns], alR[s], wA.x, wA.y);
                MMA16(accA[s][ns], ahA[s], w1.x, w1.y);
                MMA16(accA[s][ns], ahA[s], w1.z, w1.w);
                MMA16(accA[s][ns], alA[s], w1.x, w1.y);
            }
        }
    }
}

// chain from warp-private smem scratch (32 local rows, stride SWP)
__device__ __forceinline__ void chain_sw(float acc[2][4][4], const float* SW,
                                         const uint4* WF, int tig, int gg, int lane){
#pragma unroll
    for(int ks = 0; ks < 2; ks++){
        unsigned ah[2][4], al[2][4];
        int k0 = ks*16 + 2*tig;
#pragma unroll
        for(int s = 0; s < 2; s++){
            int rb = 16*s + gg;
            float v00 = SW[(k0  )*SWP + rb],     v01 = SW[(k0+1)*SWP + rb];
            float u00 = SW[(k0  )*SWP + rb + 8], u01 = SW[(k0+1)*SWP + rb + 8];
            float v08 = SW[(k0+8)*SWP + rb],     v09 = SW[(k0+9)*SWP + rb];
            float u08 = SW[(k0+8)*SWP + rb + 8], u09 = SW[(k0+9)*SWP + rb + 8];
            bfsplit(v00, v01, ah[s][0], al[s][0]);
            bfsplit(u00, u01, ah[s][1], al[s][1]);
            bfsplit(v08, v09, ah[s][2], al[s][2]);
            bfsplit(u08, u09, ah[s][3], al[s][3]);
        }
        DO_MMAS_1(acc, ah, al);
    }
}

__device__ __forceinline__ void add_bias(float acc[2][4][4], const float* bb, int tig){
#pragma unroll
    for(int ns = 0; ns < 4; ns++){
        float b0 = bb[ns*8 + 2*tig], b1 = bb[ns*8 + 2*tig + 1];
#pragma unroll
        for(int s = 0; s < 2; s++){
            acc[s][ns][0] += b0; acc[s][ns][1] += b1;
            acc[s][ns][2] += b0; acc[s][ns][3] += b1;
        }
    }
}

// per-tile register stat accumulation (no shuffles, no smem)
__device__ __forceinline__ void stat_accum(float* sts, float* stq, float acc[2][4][4]){
#pragma unroll
    for(int ns = 0; ns < 4; ns++){
        float v0 = acc[0][ns][0], v1 = acc[0][ns][1], v2 = acc[0][ns][2], v3 = acc[0][ns][3];
        float w0 = acc[1][ns][0], w1 = acc[1][ns][1], w2 = acc[1][ns][2], w3 = acc[1][ns][3];
        sts[2*ns]   += v0 + v2 + w0 + w2;
        sts[2*ns+1] += v1 + v3 + w1 + w3;
        stq[2*ns]   += v0*v0 + v2*v2 + w0*w0 + w2*w2;
        stq[2*ns+1] += v1*v1 + v3*v3 + w1*w1 + w3*w3;
    }
}

// once per kernel: butterfly over gg lanes, lanes 0..3 store all 64 warp entries
__device__ __forceinline__ void stats_final(float* sred, float* sts, float* stq,
                                            int wid, int tig, int lane){
#pragma unroll
    for(int i = 0; i < 8; i++){
        float s = sts[i], q = stq[i];
#pragma unroll
        for(int m = 4; m < 32; m <<= 1){
            s += __shfl_xor_sync(0xffffffffu, s, m);
            q += __shfl_xor_sync(0xffffffffu, q, m);
        }
        if((lane & 28) == 0){
            int col = (i >> 1)*8 + 2*tig + (i & 1);
            sred[wid*64 + col]      = s;
            sred[wid*64 + 32 + col] = q;
        }
    }
    __syncthreads();
    if(threadIdx.x < 64){
        float v = 0.f;
#pragma unroll
        for(int m = 0; m < 8; m++) v += sred[m*64 + threadIdx.x];
        g_partials[blockIdx.x*64 + threadIdx.x] = v;
    }
}

// ------- pass A: stats( silu(bn1(h))@W1 + b1 ) — plane-free, register stats -------
__global__ __launch_bounds__(TPB, 3) void k_passA(const float* __restrict__ w1,
                                                  const float* __restrict__ b1, int layer){
    extern __shared__ __align__(16) float dyn[];
    uint4* WF = (uint4*)dyn;
    __shared__ float sc1[32], sh1[32], bb1[32];
    __shared__ float sred[512];
    prep_wf(WF, w1 + layer*1024);
    if(threadIdx.x < 32){
        sc1[threadIdx.x] = g_scale[threadIdx.x];
        sh1[threadIdx.x] = g_shift[threadIdx.x];
        bb1[threadIdx.x] = b1[layer*32 + threadIdx.x];
    }
    int wid = threadIdx.x >> 5, lane = threadIdx.x & 31;
    int tig = lane & 3, gg = lane >> 2;
    int wbase = wid*32;
    float sts[8], stq[8];
#pragma unroll
    for(int i = 0; i < 8; i++){ sts[i] = 0.f; stq[i] = 0.f; }
    __syncthreads();
#pragma unroll 1
    for(int t = 0; t < NT; ++t){
        int rowbase = blockIdx.x*(NT*TILE_ROWS) + t*TILE_ROWS;
        float acc[2][4][4];
#pragma unroll
        for(int s = 0; s < 2; s++)
#pragma unroll
            for(int n = 0; n < 4; n++)
#pragma unroll
                for(int q = 0; q < 4; q++) acc[s][n][q] = 0.f;
        chain_gact(acc, g_h, rowbase, WF, wbase, tig, gg, lane, sc1, sh1);
        add_bias(acc, bb1, tig);
        stat_accum(sts, stq, acc);
    }
    stats_final(sred, sts, stq, wid, tig, lane);
}

// ------- pass B: h' = silu( h@(A+I) + silu(bn2(r))@W2 + b2 ), fused h-load -------
__global__ __launch_bounds__(TPB, 2) void k_passB(const float* __restrict__ w1,
                                                  const float* __restrict__ b1,
                                                  const float* __restrict__ w2,
                                                  const float* __restrict__ b2, int layer){
    extern __shared__ __align__(16) float dyn[];
    uint4* WF   = (uint4*)dyn;                    // [0]=W1 [256]=W2 [512]=A'
    float* SWbase = dyn + 768*4;                  // 8 warp scratches, SWSZ floats each
    __shared__ float sc1[32], sh1[32], sc2[32], sh2[32], bb1[32], bb2[32];
    __shared__ float sred[512];
    prep_wf(WF,        w1 + layer*1024);
    prep_wf(WF + 256,  w2 + layer*1024);
    prep_wf(WF + 512,  g_A + layer*1024);
    if(threadIdx.x < 32){
        sc1[threadIdx.x] = g_scale[threadIdx.x];
        sh1[threadIdx.x] = g_shift[threadIdx.x];
        sc2[threadIdx.x] = g_scale[32 + threadIdx.x];
        sh2[threadIdx.x] = g_shift[32 + threadIdx.x];
        bb1[threadIdx.x] = b1[layer*32 + threadIdx.x];
        bb2[threadIdx.x] = b2[layer*32 + threadIdx.x];
    }
    int wid = threadIdx.x >> 5, lane = threadIdx.x & 31;
    int tig = lane & 3, gg = lane >> 2;
    int wbase = wid*32;
    float* SW = SWbase + wid*SWSZ;
    float sts[8], stq[8];
#pragma unroll
    for(int i = 0; i < 8; i++){ sts[i] = 0.f; stq[i] = 0.f; }
    __syncthreads();
#pragma unroll 1
    for(int t = 0; t < NT; ++t){
        int rowbase = blockIdx.x*(NT*TILE_ROWS) + t*TILE_ROWS;
        float accA[2][4][4], accB[2][4][4];
#pragma unroll
        for(int s = 0; s < 2; s++)
#pragma unroll
            for(int n = 0; n < 4; n++)
#pragma unroll
                for(int q = 0; q < 4; q++){ accA[s][n][q] = 0.f; accB[s][n][q] = 0.f; }
        // fused: accA = silu(bn1 h) @ W1 ; accB = h @ (A+I)  (single h read)
        chain_fused(accA, accB, g_h, rowbase, WF, WF + 512, wbase, tig, gg, lane, sc1, sh1);
        add_bias(accA, bb1, tig);
        // s2 = silu(bn2(r)) -> warp scratch
#pragma unroll
        for(int s = 0; s < 2; s++){
            int rb = 16*s + gg;
#pragma unroll
            for(int ns = 0; ns < 4; ns++){
                int col = ns*8 + 2*tig;
                float a = sc2[col],    b  = sh2[col];
                float a1 = sc2[col+1], b1v = sh2[col+1];
                SW[col*SWP + rb]         = siluf(fmaf(accA[s][ns][0], a,  b));
                SW[(col+1)*SWP + rb]     = siluf(fmaf(accA[s][ns][1], a1, b1v));
                SW[col*SWP + rb + 8]     = siluf(fmaf(accA[s][ns][2], a,  b));
                SW[(col+1)*SWP + rb + 8] = siluf(fmaf(accA[s][ns][3], a1, b1v));
            }
        }
        __syncwarp();
        // chain 2: accB += s2 @ W2 ; then + b2
        chain_sw(accB, SW, WF + 256, tig, gg, lane);
        add_bias(accB, bb2, tig);
        // out = silu(accB): direct STG + register stats
#pragma unroll
        for(int s = 0; s < 2; s++){
            int rb = wbase + 16*s + gg;
#pragma unroll
            for(int ns = 0; ns < 4; ns++){
                int col = ns*8 + 2*tig;
                float v0 = siluf(accB[s][ns][0]), v1 = siluf(accB[s][ns][1]);
                float v2 = siluf(accB[s][ns][2]), v3 = siluf(accB[s][ns][3]);
                accB[s][ns][0] = v0; accB[s][ns][1] = v1;
                accB[s][ns][2] = v2; accB[s][ns][3] = v3;
                g_h[(size_t)col*BATCH     + rowbase + rb]     = v0;
                g_h[(size_t)(col+1)*BATCH + rowbase + rb]     = v1;
                g_h[(size_t)col*BATCH     + rowbase + rb + 8] = v2;
                g_h[(size_t)(col+1)*BATCH + rowbase + rb + 8] = v3;
            }
        }
        stat_accum(sts, stq, accB);
        __syncwarp();                     // SW reads done before next tile overwrite
    }
    stats_final(sred, sts, stq, wid, tig, lane);
}

// ---------------- head (verbatim) ----------------
__global__ __launch_bounds__(TPB) void k_head(const float* __restrict__ hw,
                                              const float* __restrict__ hb,
                                              float* __restrict__ out){
    __shared__ float wsh[DIMC*INDIM];
    __shared__ float bshf[INDIM];
    __shared__ float tile[TPB*INDIM];
    for(int i = threadIdx.x; i < DIMC*INDIM; i += TPB) wsh[i] = hw[i];
    if(threadIdx.x < INDIM) bshf[threadIdx.x] = hb[threadIdx.x];
    __syncthreads();
#pragma unroll 1
    for(int it = 0; it < RPT; ++it){
        int rowbase = blockIdx.x*TPB + it*STRIDE;
        int row = rowbase + threadIdx.x;
        float acc[INDIM];
#pragma unroll
        for(int i = 0; i < INDIM; i++) acc[i] = bshf[i];
#pragma unroll 4
        for(int c = 0; c < DIMC; c++){
            float h = g_h[(size_t)c*BATCH + row];
#pragma unroll
            for(int i = 0; i < INDIM; i++) acc[i] = fmaf(h, wsh[c*INDIM + i], acc[i]);
        }
        __syncthreads();
#pragma unroll
        for(int i = 0; i < INDIM; i++) tile[threadIdx.x*INDIM + i] = acc[i];
        __syncthreads();
        for(int k = threadIdx.x; k < TPB*INDIM; k += TPB)
            out[(size_t)rowbase*INDIM + k] = tile[k];
    }
}

// ---------------- launch ----------------
extern "C" void kernel_launch(void* const* d_in, const int* in_sizes, int n_in,
                              void* d_out, int out_size) {
    (void)in_sizes; (void)n_in; (void)out_size;
    const float* x      = (const float*)d_in[0];
    const float* stem_w = (const float*)d_in[1];
    const float* stem_b = (const float*)d_in[2];
    const float* fno_wr = (const float*)d_in[3];
    const float* fno_wi = (const float*)d_in[4];
    const float* bn1_g  = (const float*)d_in[5];
    const float* bn1_b  = (const float*)d_in[6];
    const float* lin1_w = (const float*)d_in[7];
    const float* lin1_b = (const float*)d_in[8];
    const float* bn2_g  = (const float*)d_in[9];
    const float* bn2_b  = (const float*)d_in[10];
    const float* lin2_w = (const float*)d_in[11];
    const float* lin2_b = (const float*)d_in[12];
    const float* head_w = (const float*)d_in[13];
    const float* head_b = (const float*)d_in[14];
    float* out = (float*)d_out;

    cudaFuncSetAttribute(k_passA, cudaFuncAttributeMaxDynamicSharedMemorySize, DYNA_B);
    cudaFuncSetAttribute(k_passB, cudaFuncAttributeMaxDynamicSharedMemorySize, DYNB_B);

    k_precompute_A<<<16, 256>>>(fno_wr, fno_wi);
    k_stem<<<GRID_MAIN, TPB>>>(x, stem_w, stem_b);
    for(int l = 0; l < LAYERS; l++){
        k_fin<<<1, 1024>>>(bn1_g, bn1_b, l, 0);      // h stats -> bn1 affine
        k_passA<<<GRID_MAIN, TPB, DYNA_B>>>(lin1_w, lin1_b, l);
        k_fin<<<1, 1024>>>(bn2_g, bn2_b, l, 1);      // r stats -> bn2 affine
        k_passB<<<GRID_MAIN, TPB, DYNB_B>>>(lin1_w, lin1_b, lin2_w, lin2_b, l);
    }
    k_head<<<GRID_MAIN, TPB>>>(head_w, head_b, out);
}

// round 17
// speedup vs baseline: 1.6062x; 1.0481x over previous
#include <cuda_runtime.h>
#include <stdint.h>

#define BATCH   2097152
#define DIMC    32
#define INDIM   10
#define LAYERS  4
#define MB      17
#define EPSV    1e-5f

#define GRID_MAIN 2048
#define TPB       256
#define RPT       4                       // stem/head: 1 row/thread, 4 iters
#define STRIDE    (GRID_MAIN*TPB)

#define TILE_ROWS 256
#define NT        4                       // passA: 4 tiles of 256 rows (32 rows/warp)
#define NTB       8                       // passB: 8 tiles of 128 rows (16 rows/warp)
#define SWP       20                      // passB per-warp scratch stride (conflict-free)
#define SWSZ      (DIMC*SWP)              // 640 floats per warp

#define DYNA_B    (256*16)                        // passA: 256 uint4 WF
#define DYNB_B    (768*16 + 8*SWSZ*4)             // passB: 3*256 uint4 WF + 8 warp scratches

typedef unsigned long long u64;

// ---------------- scratch ----------------
__device__ __align__(16) float g_h[(size_t)DIMC * BATCH];   // planar [c][row]
__device__ __align__(16) float g_A[LAYERS * DIMC * DIMC];   // fused Fourier A+I
__device__ float g_partials[GRID_MAIN * 64];
__device__ float g_scale[64];                               // slot0: bn1, slot1: bn2
__device__ float g_shift[64];

// ---------------- helpers ----------------
__device__ __forceinline__ u64 pk2(float a, float b){
    u64 r; asm("mov.b64 %0,{%1,%2};" : "=l"(r) : "f"(a), "f"(b)); return r;
}
__device__ __forceinline__ void up2(u64 v, float &a, float &b){
    asm("mov.b64 {%0,%1},%2;" : "=f"(a), "=f"(b) : "l"(v));
}
__device__ __forceinline__ u64 fma2(u64 a, u64 b, u64 c){
    u64 d; asm("fma.rn.f32x2 %0,%1,%2,%3;" : "=l"(d) : "l"(a), "l"(b), "l"(c)); return d;
}
__device__ __forceinline__ float siluf(float x){
    return x * __fdividef(1.0f, 1.0f + __expf(-x));
}
__device__ __forceinline__ unsigned bf2(float vhi, float vlo){
    unsigned d; asm("cvt.rn.bf16x2.f32 %0,%1,%2;" : "=r"(d) : "f"(vhi), "f"(vlo)); return d;
}
// split pair (v0 -> lo half, v1 -> hi half) into bf16 head + bf16 residual
__device__ __forceinline__ void bfsplit(float v0, float v1, unsigned &hi, unsigned &lo){
    hi = bf2(v1, v0);
    float f0 = __uint_as_float(hi << 16);
    float f1 = __uint_as_float(hi & 0xffff0000u);
    lo = bf2(v1 - f1, v0 - f0);
}

#define MMA16(d, a, b0, b1) \
    asm("mma.sync.aligned.m16n8k16.row.col.f32.bf16.bf16.f32 " \
        "{%0,%1,%2,%3},{%4,%5,%6,%7},{%8,%9},{%0,%1,%2,%3};" \
        : "+f"((d)[0]), "+f"((d)[1]), "+f"((d)[2]), "+f"((d)[3]) \
        : "r"((a)[0]), "r"((a)[1]), "r"((a)[2]), "r"((a)[3]), "r"(b0), "r"(b1))

// ------- Fourier operator precompute: A' = A + I (verbatim) -------
__global__ void k_precompute_A(const float* __restrict__ wr, const float* __restrict__ wi){
    __shared__ double ct[32], st[32];
    int t = threadIdx.x;
    if(t < 32){
        double ang = 6.283185307179586476925286766559 * (double)t / 32.0;
        ct[t] = cos(ang); st[t] = sin(ang);
    }
    __syncthreads();
    int g = blockIdx.x * blockDim.x + t;
    if(g >= LAYERS*DIMC*DIMC) return;
    int l = g >> 10, j = (g >> 5) & 31, d = g & 31;
    const float* WR = wr + l*MB*MB;
    const float* WI = wi + l*MB*MB;
    double v = 0.0;
    for(int k = 0; k < MB; k++){
        double re = 0.0, im = 0.0;
        for(int m = 0; m < MB; m++){
            double c = ct[(m*j)&31], s = st[(m*j)&31];
            double a = (double)WR[m*MB + k], b = (double)WI[m*MB + k];
            re += c*a + s*b;
            im += c*b - s*a;
        }
        double al, be;
        if(k == 0)      { al = 1.0; be = 0.0; }
        else if(k == 16){ al = (d & 1) ? -1.0 : 1.0; be = 0.0; }
        else            { al = 2.0*ct[(k*d)&31]; be = 2.0*st[(k*d)&31]; }
        v += al*re - be*im;
    }
    v *= (1.0/32.0);
    if(j == d) v += 1.0;
    g_A[(l*DIMC + j)*DIMC + d] = (float)v;
}

// ---------------- stem (verbatim) ----------------
__global__ __launch_bounds__(TPB) void k_stem(const float* __restrict__ x,
                                              const float* __restrict__ sw,
                                              const float* __restrict__ sb){
    __shared__ __align__(16) u64 wsh[INDIM*16];
    __shared__ u64 bsh[16];
    __shared__ float tile[8960];
    if(threadIdx.x < INDIM*16){
        int r = threadIdx.x >> 4, q = threadIdx.x & 15;
        wsh[threadIdx.x] = pk2(sw[r*DIMC + 2*q], sw[r*DIMC + 2*q + 1]);
    }
    if(threadIdx.x < 16) bsh[threadIdx.x] = pk2(sb[2*threadIdx.x], sb[2*threadIdx.x+1]);
    int ch = threadIdx.x & 31, mrow = threadIdx.x >> 5;
    float ssum = 0.f, ssq = 0.f;
    __syncthreads();
#pragma unroll 1
    for(int it = 0; it < RPT; ++it){
        int rowbase = blockIdx.x*TPB + it*STRIDE;
        int row = rowbase + threadIdx.x;
        __syncthreads();
        for(int k = threadIdx.x; k < TPB*INDIM; k += TPB)
            tile[k] = x[(size_t)rowbase*INDIM + k];
        __syncthreads();
        float xv[INDIM];
#pragma unroll
        for(int i = 0; i < INDIM; i++) xv[i] = tile[threadIdx.x*INDIM + i];
        __syncthreads();
        u64 acc[16];
#pragma unroll
        for(int q = 0; q < 16; q++) acc[q] = bsh[q];
#pragma unroll
        for(int i = 0; i < INDIM; i++){
            u64 xp = pk2(xv[i], xv[i]);
            const ulonglong2* w2 = (const ulonglong2*)(wsh + i*16);
#pragma unroll
            for(int q = 0; q < 8; q++){
                ulonglong2 ww = w2[q];
                acc[2*q]   = fma2(xp, ww.x, acc[2*q]);
                acc[2*q+1] = fma2(xp, ww.y, acc[2*q+1]);
            }
        }
        float* trow = tile + threadIdx.x*35;
#pragma unroll
        for(int q = 0; q < 16; q++){
            float a, b; up2(acc[q], a, b);
            g_h[(size_t)(2*q)*BATCH + row]   = a;
            g_h[(size_t)(2*q+1)*BATCH + row] = b;
            trow[2*q] = a; trow[2*q+1] = b;
        }
        __syncthreads();
#pragma unroll
        for(int j = 0; j < 32; j++){
            float v = tile[(mrow*32 + j)*35 + ch];
            ssum += v; ssq += v*v;
        }
    }
    __syncthreads();
    tile[mrow*64 + ch]      = ssum;
    tile[mrow*64 + 32 + ch] = ssq;
    __syncthreads();
    if(threadIdx.x < 64){
        float v = 0.f;
#pragma unroll
        for(int m = 0; m < 8; m++) v += tile[m*64 + threadIdx.x];
        g_partials[blockIdx.x*64 + threadIdx.x] = v;
    }
}

// ---------------- finalize (verbatim) ----------------
__global__ void k_fin(const float* __restrict__ gamma, const float* __restrict__ beta,
                      int layer, int slot){
    __shared__ float red[1024];
    __shared__ float tot[64];
    int t = threadIdx.x;
    int col = t & 63, part = t >> 6;
    const float* p = g_partials + (size_t)part*128*64 + col;
    float v = 0.f;
#pragma unroll 8
    for(int i = 0; i < 128; i++) v += p[(size_t)i*64];
    red[part*64 + col] = v;
    __syncthreads();
    if(t < 64){
        float s = 0.f;
#pragma unroll
        for(int q = 0; q < 16; q++) s += red[q*64 + t];
        tot[t] = s;
    }
    __syncthreads();
    if(t < DIMC){
        float mean = tot[t]      * (1.0f/(float)BATCH);
        float ex2  = tot[32 + t] * (1.0f/(float)BATCH);
        float var  = fmaxf(ex2 - mean*mean, 0.0f);
        float sc   = gamma[layer*DIMC + t] * rsqrtf(var + EPSV);
        g_scale[slot*32 + t] = sc;
        g_shift[slot*32 + t] = beta[layer*DIMC + t] - mean*sc;
    }
}

// ---- MMA-pass pieces (bf16 2-part split) ----

__device__ __forceinline__ void prep_wf(uint4* WF, const float* __restrict__ W){
    for(int e = threadIdx.x; e < 256; e += TPB){
        int lane = e & 31, ns = (e >> 5) & 3, ks = e >> 7;
        int tig = lane & 3, gg = lane >> 2;
        int k0 = ks*16 + 2*tig, n = ns*8 + gg;
        float b0 = W[k0*32 + n],     b1 = W[(k0+1)*32 + n];
        float b2 = W[(k0+8)*32 + n], b3 = W[(k0+9)*32 + n];
        unsigned h01, l01, h23, l23;
        bfsplit(b0, b1, h01, l01);
        bfsplit(b2, b3, h23, l23);
        WF[(ks*4 + ns)*32 + lane] = make_uint4(h01, h23, l01, l23);
    }
}

#define DO_MMAS_1(ACC, AH, AL)                                                  \
    _Pragma("unroll")                                                           \
    for(int ns = 0; ns < 4; ns++){                                              \
        uint4 w = WF[(ks*4 + ns)*32 + lane];                                    \
        _Pragma("unroll")                                                       \
        for(int s = 0; s < 2; s++){                                             \
            MMA16((ACC)[s][ns], (AH)[s], w.x, w.y);                             \
            MMA16((ACC)[s][ns], (AH)[s], w.z, w.w);                             \
            MMA16((ACC)[s][ns], (AL)[s], w.x, w.y);                             \
        }                                                                       \
    }

// passA chain from gmem with fused bn+silu (32 rows/warp, verbatim round-16)
__device__ __forceinline__ void chain_gact(float acc[2][4][4], const float* __restrict__ g,
                                           int rowbase, const uint4* WF,
                                           int wbase, int tig, int gg, int lane,
                                           const float* sc, const float* sh){
#pragma unroll
    for(int ks = 0; ks < 2; ks++){
        unsigned ah[2][4], al[2][4];
        int k0 = ks*16 + 2*tig;
        float a0 = sc[k0],   s0 = sh[k0];
        float a1 = sc[k0+1], s1v = sh[k0+1];
        float a8 = sc[k0+8], s8 = sh[k0+8];
        float a9 = sc[k0+9], s9 = sh[k0+9];
#pragma unroll
        for(int s = 0; s < 2; s++){
            const float* base = g + (size_t)rowbase + wbase + 16*s + gg;
            float v00 = siluf(fmaf(__ldg(base + (size_t)(k0  )*BATCH),     a0, s0));
            float v01 = siluf(fmaf(__ldg(base + (size_t)(k0+1)*BATCH),     a1, s1v));
            float u00 = siluf(fmaf(__ldg(base + (size_t)(k0  )*BATCH + 8), a0, s0));
            float u01 = siluf(fmaf(__ldg(base + (size_t)(k0+1)*BATCH + 8), a1, s1v));
            float v08 = siluf(fmaf(__ldg(base + (size_t)(k0+8)*BATCH),     a8, s8));
            float v09 = siluf(fmaf(__ldg(base + (size_t)(k0+9)*BATCH),     a9, s9));
            float u08 = siluf(fmaf(__ldg(base + (size_t)(k0+8)*BATCH + 8), a8, s8));
            float u09 = siluf(fmaf(__ldg(base + (size_t)(k0+9)*BATCH + 8), a9, s9));
            bfsplit(v00, v01, ah[s][0], al[s][0]);
            bfsplit(u00, u01, ah[s][1], al[s][1]);
            bfsplit(v08, v09, ah[s][2], al[s][2]);
            bfsplit(u08, u09, ah[s][3], al[s][3]);
        }
        DO_MMAS_1(acc, ah, al);
    }
}

// passB fused chain, 16 rows/warp: accB += h@A' ; accA += silu(bn1 h)@W1 (single h read)
__device__ __forceinline__ void chain_fused16(float accA[4][4], float accB[4][4],
                                              const float* __restrict__ g, int rowabs,
                                              const uint4* WF1, const uint4* WFA,
                                              int tig, int gg, int lane,
                                              const float* sc, const float* sh){
#pragma unroll
    for(int ks = 0; ks < 2; ks++){
        unsigned ahR[4], alR[4], ahA[4], alA[4];
        int k0 = ks*16 + 2*tig;
        float a0 = sc[k0],   s0 = sh[k0];
        float a1 = sc[k0+1], s1v = sh[k0+1];
        float a8 = sc[k0+8], s8 = sh[k0+8];
        float a9 = sc[k0+9], s9 = sh[k0+9];
        const float* base = g + (size_t)rowabs + gg;
        float v00 = __ldg(base + (size_t)(k0  )*BATCH);
        float v01 = __ldg(base + (size_t)(k0+1)*BATCH);
        float u00 = __ldg(base + (size_t)(k0  )*BATCH + 8);
        float u01 = __ldg(base + (size_t)(k0+1)*BATCH + 8);
        float v08 = __ldg(base + (size_t)(k0+8)*BATCH);
        float v09 = __ldg(base + (size_t)(k0+9)*BATCH);
        float u08 = __ldg(base + (size_t)(k0+8)*BATCH + 8);
        float u09 = __ldg(base + (size_t)(k0+9)*BATCH + 8);
        bfsplit(v00, v01, ahR[0], alR[0]);
        bfsplit(u00, u01, ahR[1], alR[1]);
        bfsplit(v08, v09, ahR[2], alR[2]);
        bfsplit(u08, u09, ahR[3], alR[3]);
        bfsplit(siluf(fmaf(v00, a0, s0)),  siluf(fmaf(v01, a1, s1v)), ahA[0], alA[0]);
        bfsplit(siluf(fmaf(u00, a0, s0)),  siluf(fmaf(u01, a1, s1v)), ahA[1], alA[1]);
        bfsplit(siluf(fmaf(v08, a8, s8)),  siluf(fmaf(v09, a9, s9)),  ahA[2], alA[2]);
        bfsplit(siluf(fmaf(u08, a8, s8)),  siluf(fmaf(u09, a9, s9)),  ahA[3], alA[3]);
#pragma unroll
        for(int ns = 0; ns < 4; ns++){
            uint4 wA = WFA[(ks*4 + ns)*32 + lane];
            uint4 w1 = WF1[(ks*4 + ns)*32 + lane];
            MMA16(accB[ns], ahR, wA.x, wA.y);
            MMA16(accB[ns], ahR, wA.z, wA.w);
            MMA16(accB[ns], alR, wA.x, wA.y);
            MMA16(accA[ns], ahA, w1.x, w1.y);
            MMA16(accA[ns], ahA, w1.z, w1.w);
            MMA16(accA[ns], alA, w1.x, w1.y);
        }
    }
}

// passB chain from warp-private scratch, 16 rows/warp
__device__ __forceinline__ void chain_sw16(float acc[4][4], const float* SW,
                                           const uint4* WF, int tig, int gg, int lane){
#pragma unroll
    for(int ks = 0; ks < 2; ks++){
        unsigned ah[4], al[4];
        int k0 = ks*16 + 2*tig;
        float v00 = SW[(k0  )*SWP + gg],     v01 = SW[(k0+1)*SWP + gg];
        float u00 = SW[(k0  )*SWP + gg + 8], u01 = SW[(k0+1)*SWP + gg + 8];
        float v08 = SW[(k0+8)*SWP + gg],     v09 = SW[(k0+9)*SWP + gg];
        float u08 = SW[(k0+8)*SWP + gg + 8], u09 = SW[(k0+9)*SWP + gg + 8];
        bfsplit(v00, v01, ah[0], al[0]);
        bfsplit(u00, u01, ah[1], al[1]);
        bfsplit(v08, v09, ah[2], al[2]);
        bfsplit(u08, u09, ah[3], al[3]);
#pragma unroll
        for(int ns = 0; ns < 4; ns++){
            uint4 w = WF[(ks*4 + ns)*32 + lane];
            MMA16(acc[ns], ah, w.x, w.y);
            MMA16(acc[ns], ah, w.z, w.w);
            MMA16(acc[ns], al, w.x, w.y);
        }
    }
}

__device__ __forceinline__ void add_bias(float acc[2][4][4], const float* bb, int tig){
#pragma unroll
    for(int ns = 0; ns < 4; ns++){
        float b0 = bb[ns*8 + 2*tig], b1 = bb[ns*8 + 2*tig + 1];
#pragma unroll
        for(int s = 0; s < 2; s++){
            acc[s][ns][0] += b0; acc[s][ns][1] += b1;
            acc[s][ns][2] += b0; acc[s][ns][3] += b1;
        }
    }
}
__device__ __forceinline__ void add_bias16(float acc[4][4], const float* bb, int tig){
#pragma unroll
    for(int ns = 0; ns < 4; ns++){
        float b0 = bb[ns*8 + 2*tig], b1 = bb[ns*8 + 2*tig + 1];
        acc[ns][0] += b0; acc[ns][1] += b1;
        acc[ns][2] += b0; acc[ns][3] += b1;
    }
}

// per-tile register stat accumulation
__device__ __forceinline__ void stat_accum(float* sts, float* stq, float acc[2][4][4]){
#pragma unroll
    for(int ns = 0; ns < 4; ns++){
        float v0 = acc[0][ns][0], v1 = acc[0][ns][1], v2 = acc[0][ns][2], v3 = acc[0][ns][3];
        float w0 = acc[1][ns][0], w1 = acc[1][ns][1], w2 = acc[1][ns][2], w3 = acc[1][ns][3];
        sts[2*ns]   += v0 + v2 + w0 + w2;
        sts[2*ns+1] += v1 + v3 + w1 + w3;
        stq[2*ns]   += v0*v0 + v2*v2 + w0*w0 + w2*w2;
        stq[2*ns+1] += v1*v1 + v3*v3 + w1*w1 + w3*w3;
    }
}
__device__ __forceinline__ void stat_accum16(float* sts, float* stq, float acc[4][4]){
#pragma unroll
    for(int ns = 0; ns < 4; ns++){
        float v0 = acc[ns][0], v1 = acc[ns][1], v2 = acc[ns][2], v3 = acc[ns][3];
        sts[2*ns]   += v0 + v2;
        sts[2*ns+1] += v1 + v3;
        stq[2*ns]   += v0*v0 + v2*v2;
        stq[2*ns+1] += v1*v1 + v3*v3;
    }
}

// once per kernel: butterfly over gg lanes, lanes 0..3 store all 64 warp entries
__device__ __forceinline__ void stats_final(float* sred, float* sts, float* stq,
                                            int wid, int tig, int lane){
#pragma unroll
    for(int i = 0; i < 8; i++){
        float s = sts[i], q = stq[i];
#pragma unroll
        for(int m = 4; m < 32; m <<= 1){
            s += __shfl_xor_sync(0xffffffffu, s, m);
            q += __shfl_xor_sync(0xffffffffu, q, m);
        }
        if((lane & 28) == 0){
            int col = (i >> 1)*8 + 2*tig + (i & 1);
            sred[wid*64 + col]      = s;
            sred[wid*64 + 32 + col] = q;
        }
    }
    __syncthreads();
    if(threadIdx.x < 64){
        float v = 0.f;
#pragma unroll
        for(int m = 0; m < 8; m++) v += sred[m*64 + threadIdx.x];
        g_partials[blockIdx.x*64 + threadIdx.x] = v;
    }
}

// ------- pass A: stats( silu(bn1(h))@W1 + b1 ) — verbatim round 16 -------
__global__ __launch_bounds__(TPB, 3) void k_passA(const float* __restrict__ w1,
                                                  const float* __restrict__ b1, int layer){
    extern __shared__ __align__(16) float dyn[];
    uint4* WF = (uint4*)dyn;
    __shared__ float sc1[32], sh1[32], bb1[32];
    __shared__ float sred[512];
    prep_wf(WF, w1 + layer*1024);
    if(threadIdx.x < 32){
        sc1[threadIdx.x] = g_scale[threadIdx.x];
        sh1[threadIdx.x] = g_shift[threadIdx.x];
        bb1[threadIdx.x] = b1[layer*32 + threadIdx.x];
    }
    int wid = threadIdx.x >> 5, lane = threadIdx.x & 31;
    int tig = lane & 3, gg = lane >> 2;
    int wbase = wid*32;
    float sts[8], stq[8];
#pragma unroll
    for(int i = 0; i < 8; i++){ sts[i] = 0.f; stq[i] = 0.f; }
    __syncthreads();
#pragma unroll 1
    for(int t = 0; t < NT; ++t){
        int rowbase = blockIdx.x*(NT*TILE_ROWS) + t*TILE_ROWS;
        float acc[2][4][4];
#pragma unroll
        for(int s = 0; s < 2; s++)
#pragma unroll
            for(int n = 0; n < 4; n++)
#pragma unroll
                for(int q = 0; q < 4; q++) acc[s][n][q] = 0.f;
        chain_gact(acc, g_h, rowbase, WF, wbase, tig, gg, lane, sc1, sh1);
        add_bias(acc, bb1, tig);
        stat_accum(sts, stq, acc);
    }
    stats_final(sred, sts, stq, wid, tig, lane);
}

// ------- pass B: 16 rows/warp, occ 3 -------
__global__ __launch_bounds__(TPB, 3) void k_passB(const float* __restrict__ w1,
                                                  const float* __restrict__ b1,
                                                  const float* __restrict__ w2,
                                                  const float* __restrict__ b2, int layer){
    extern __shared__ __align__(16) float dyn[];
    uint4* WF   = (uint4*)dyn;                    // [0]=W1 [256]=W2 [512]=A'
    float* SWbase = dyn + 768*4;                  // 8 warp scratches, SWSZ floats each
    __shared__ float sc1[32], sh1[32], sc2[32], sh2[32], bb1[32], bb2[32];
    __shared__ float sred[512];
    prep_wf(WF,        w1 + layer*1024);
    prep_wf(WF + 256,  w2 + layer*1024);
    prep_wf(WF + 512,  g_A + layer*1024);
    if(threadIdx.x < 32){
        sc1[threadIdx.x] = g_scale[threadIdx.x];
        sh1[threadIdx.x] = g_shift[threadIdx.x];
        sc2[threadIdx.x] = g_scale[32 + threadIdx.x];
        sh2[threadIdx.x] = g_shift[32 + threadIdx.x];
        bb1[threadIdx.x] = b1[layer*32 + threadIdx.x];
        bb2[threadIdx.x] = b2[layer*32 + threadIdx.x];
    }
    int wid = threadIdx.x >> 5, lane = threadIdx.x & 31;
    int tig = lane & 3, gg = lane >> 2;
    float* SW = SWbase + wid*SWSZ;
    float sts[8], stq[8];
#pragma unroll
    for(int i = 0; i < 8; i++){ sts[i] = 0.f; stq[i] = 0.f; }
    __syncthreads();
#pragma unroll 1
    for(int t = 0; t < NTB; ++t){
        int rowabs = blockIdx.x*1024 + t*128 + wid*16;   // this warp's 16-row strip
        float accA[4][4], accB[4][4];
#pragma unroll
        for(int n = 0; n < 4; n++)
#pragma unroll
            for(int q = 0; q < 4; q++){ accA[n][q] = 0.f; accB[n][q] = 0.f; }
        // fused: accA = silu(bn1 h) @ W1 ; accB = h @ (A+I)
        chain_fused16(accA, accB, g_h, rowabs, WF, WF + 512, tig, gg, lane, sc1, sh1);
        add_bias16(accA, bb1, tig);
        // s2 = silu(bn2(r)) -> warp scratch
#pragma unroll
        for(int ns = 0; ns < 4; ns++){
            int col = ns*8 + 2*tig;
            float a = sc2[col],    b  = sh2[col];
            float a1 = sc2[col+1], b1v = sh2[col+1];
            SW[col*SWP + gg]         = siluf(fmaf(accA[ns][0], a,  b));
            SW[(col+1)*SWP + gg]     = siluf(fmaf(accA[ns][1], a1, b1v));
            SW[col*SWP + gg + 8]     = siluf(fmaf(accA[ns][2], a,  b));
            SW[(col+1)*SWP + gg + 8] = siluf(fmaf(accA[ns][3], a1, b1v));
        }
        __syncwarp();
        // chain 2: accB += s2 @ W2 ; + b2
        chain_sw16(accB, SW, WF + 256, tig, gg, lane);
        add_bias16(accB, bb2, tig);
        // out = silu(accB): direct STG + register stats
#pragma unroll
        for(int ns = 0; ns < 4; ns++){
            int col = ns*8 + 2*tig;
            float v0 = siluf(accB[ns][0]), v1 = siluf(accB[ns][1]);
            float v2 = siluf(accB[ns][2]), v3 = siluf(accB[ns][3]);
            accB[ns][0] = v0; accB[ns][1] = v1;
            accB[ns][2] = v2; accB[ns][3] = v3;
            g_h[(size_t)col*BATCH     + rowabs + gg]     = v0;
            g_h[(size_t)(col+1)*BATCH + rowabs + gg]     = v1;
            g_h[(size_t)col*BATCH     + rowabs + gg + 8] = v2;
            g_h[(size_t)(col+1)*BATCH + rowabs + gg + 8] = v3;
        }
        stat_accum16(sts, stq, accB);
        __syncwarp();                     // SW reads done before next tile overwrite
    }
    stats_final(sred, sts, stq, wid, tig, lane);
}

// ---------------- head (verbatim) ----------------
__global__ __launch_bounds__(TPB) void k_head(const float* __restrict__ hw,
                                              const float* __restrict__ hb,
                                              float* __restrict__ out){
    __shared__ float wsh[DIMC*INDIM];
    __shared__ float bshf[INDIM];
    __shared__ float tile[TPB*INDIM];
    for(int i = threadIdx.x; i < DIMC*INDIM; i += TPB) wsh[i] = hw[i];
    if(threadIdx.x < INDIM) bshf[threadIdx.x] = hb[threadIdx.x];
    __syncthreads();
#pragma unroll 1
    for(int it = 0; it < RPT; ++it){
        int rowbase = blockIdx.x*TPB + it*STRIDE;
        int row = rowbase + threadIdx.x;
        float acc[INDIM];
#pragma unroll
        for(int i = 0; i < INDIM; i++) acc[i] = bshf[i];
#pragma unroll 4
        for(int c = 0; c < DIMC; c++){
            float h = g_h[(size_t)c*BATCH + row];
#pragma unroll
            for(int i = 0; i < INDIM; i++) acc[i] = fmaf(h, wsh[c*INDIM + i], acc[i]);
        }
        __syncthreads();
#pragma unroll
        for(int i = 0; i < INDIM; i++) tile[threadIdx.x*INDIM + i] = acc[i];
        __syncthreads();
        for(int k = threadIdx.x; k < TPB*INDIM; k += TPB)
            out[(size_t)rowbase*INDIM + k] = tile[k];
    }
}

// ---------------- launch ----------------
extern "C" void kernel_launch(void* const* d_in, const int* in_sizes, int n_in,
                              void* d_out, int out_size) {
    (void)in_sizes; (void)n_in; (void)out_size;
    const float* x      = (const float*)d_in[0];
    const float* stem_w = (const float*)d_in[1];
    const float* stem_b = (const float*)d_in[2];
    const float* fno_wr = (const float*)d_in[3];
    const float* fno_wi = (const float*)d_in[4];
    const float* bn1_g  = (const float*)d_in[5];
    const float* bn1_b  = (const float*)d_in[6];
    const float* lin1_w = (const float*)d_in[7];
    const float* lin1_b = (const float*)d_in[8];
    const float* bn2_g  = (const float*)d_in[9];
    const float* bn2_b  = (const float*)d_in[10];
    const float* lin2_w = (const float*)d_in[11];
    const float* lin2_b = (const float*)d_in[12];
    const float* head_w = (const float*)d_in[13];
    const float* head_b = (const float*)d_in[14];
    float* out = (float*)d_out;

    cudaFuncSetAttribute(k_passA, cudaFuncAttributeMaxDynamicSharedMemorySize, DYNA_B);
    cudaFuncSetAttribute(k_passB, cudaFuncAttributeMaxDynamicSharedMemorySize, DYNB_B);

    k_precompute_A<<<16, 256>>>(fno_wr, fno_wi);
    k_stem<<<GRID_MAIN, TPB>>>(x, stem_w, stem_b);
    for(int l = 0; l < LAYERS; l++){
        k_fin<<<1, 1024>>>(bn1_g, bn1_b, l, 0);      // h stats -> bn1 affine
        k_passA<<<GRID_MAIN, TPB, DYNA_B>>>(lin1_w, lin1_b, l);
        k_fin<<<1, 1024>>>(bn2_g, bn2_b, l, 1);      // r stats -> bn2 affine
        k_passB<<<GRID_MAIN, TPB, DYNB_B>>>(lin1_w, lin1_b, lin2_w, lin2_b, l);
    }
    k_head<<<GRID_MAIN, TPB>>>(head_w, head_b, out);
}